// round 3
// baseline (speedup 1.0000x reference)
#include <cuda_runtime.h>
#include <math.h>

#define BB   32
#define LL   4096
#define PP   16
#define NPAT 256
#define SS   257
#define DD   512
#define HH   8
#define DHD  64
#define NLAY 8
#define FFD  2048
#define NCLS 4
#define TT   (BB*SS)      /* 8224 */
#define TPAD 8320         /* 65*128 */
#define KCONV 8192
#define MCONV 8192

// ---------------- scratch (device globals; no allocations) ----------------
__device__ float g_x[TPAD*DD];
__device__ float g_q[TPAD*DD];
__device__ float g_k[TPAD*DD];
__device__ float g_v[TPAD*DD];
__device__ float g_attn[TPAD*DD];
__device__ float g_y[TPAD*DD];
__device__ float g_h[(size_t)TPAD*FFD];
__device__ float g_kv[BB*HH*DHD*DHD];
__device__ float g_ksum[BB*HH*DHD];
__device__ float g_Wc[(size_t)KCONV*DD];
__device__ float g_len[BB];

// ---------------- generic SGEMM: C[M,N] = A[M,K]@B[K,N] + bias (+gelu) ----
// BM=128, BN=128, BK=16, 256 threads, 8x8 microtile.
// M % 128 == 0, K % 16 == 0, N % 128 == 0 (enforced by padding).
template<int EPI>
__global__ void __launch_bounds__(256) gemm_k(
    const float* __restrict__ A, const float* __restrict__ Bm,
    const float* __restrict__ bias, float* __restrict__ C,
    int M, int N, int K)
{
    __shared__ float As[16][132];
    __shared__ float Bs[16][128];
    int tid = threadIdx.x;
    int m0 = blockIdx.y * 128;
    int n0 = blockIdx.x * 128;
    int tx = tid & 15, ty = tid >> 4;
    float acc[8][8];
#pragma unroll
    for (int i = 0; i < 8; i++)
#pragma unroll
        for (int j = 0; j < 8; j++) acc[i][j] = 0.f;

    for (int k0 = 0; k0 < K; k0 += 16) {
        // load A tile 128x16 (transposed into As[k][m])
#pragma unroll
        for (int ld = 0; ld < 2; ld++) {
            int idx = tid + ld * 256;
            int row = idx >> 2, c4 = idx & 3;
            float4 v = *(const float4*)(A + (size_t)(m0 + row) * K + k0 + c4 * 4);
            As[c4*4+0][row] = v.x; As[c4*4+1][row] = v.y;
            As[c4*4+2][row] = v.z; As[c4*4+3][row] = v.w;
        }
        // load B tile 16x128
#pragma unroll
        for (int ld = 0; ld < 2; ld++) {
            int idx = tid + ld * 256;
            int row = idx >> 5, c4 = idx & 31;
            float4 v = *(const float4*)(Bm + (size_t)(k0 + row) * N + n0 + c4 * 4);
            *(float4*)&Bs[row][c4*4] = v;
        }
        __syncthreads();
#pragma unroll
        for (int kk = 0; kk < 16; kk++) {
            float a[8], b[8];
            *(float4*)&a[0] = *(const float4*)&As[kk][ty*8];
            *(float4*)&a[4] = *(const float4*)&As[kk][ty*8 + 4];
            *(float4*)&b[0] = *(const float4*)&Bs[kk][tx*8];
            *(float4*)&b[4] = *(const float4*)&Bs[kk][tx*8 + 4];
#pragma unroll
            for (int i = 0; i < 8; i++)
#pragma unroll
                for (int j = 0; j < 8; j++) acc[i][j] += a[i] * b[j];
        }
        __syncthreads();
    }
#pragma unroll
    for (int i = 0; i < 8; i++) {
        int m = m0 + ty*8 + i;
#pragma unroll
        for (int j = 0; j < 8; j++) {
            int n = n0 + tx*8 + j;
            float val = acc[i][j] + bias[n];
            if (EPI == 1) val = 0.5f * val * (1.0f + erff(val * 0.70710678118654752f));
            C[(size_t)m * N + n] = val;
        }
    }
}

// ---------------- conv-embedding GEMM with row gather ----------------
// out row r = (b, nn): x[b, nn+1, o] = sum_{p,i} emb[tok[b,nn*16+p], i] * Wc[p*512+i][o]
//                      + conv_b[o] + pos[nn+1][o]
__global__ void __launch_bounds__(256) conv_gemm_k(
    const int* __restrict__ tok, const float* __restrict__ emb,
    const float* __restrict__ conv_b, const float* __restrict__ pos)
{
    __shared__ float As[16][132];
    __shared__ float Bs[16][64];
    __shared__ int toks[128];
    int tid = threadIdx.x;
    int m0 = blockIdx.y * 128;
    int n0 = blockIdx.x * 64;
    int tx = tid & 15, ty = tid >> 4;
    float acc[8][4];
#pragma unroll
    for (int i = 0; i < 8; i++)
#pragma unroll
        for (int j = 0; j < 4; j++) acc[i][j] = 0.f;

    for (int k0 = 0; k0 < KCONV; k0 += 16) {
        int p  = k0 >> 9;
        int i0 = k0 & 511;
        if (i0 == 0) {
            __syncthreads();
            if (tid < 128) {
                int r = m0 + tid;
                int b = r >> 8, nn = r & 255;
                toks[tid] = tok[b * LL + nn * PP + p];
            }
            __syncthreads();
        }
#pragma unroll
        for (int ld = 0; ld < 2; ld++) {
            int idx = tid + ld * 256;
            int row = idx >> 2, c4 = idx & 3;
            int t = toks[row];
            float4 v = *(const float4*)(emb + (size_t)t * DD + i0 + c4 * 4);
            As[c4*4+0][row] = v.x; As[c4*4+1][row] = v.y;
            As[c4*4+2][row] = v.z; As[c4*4+3][row] = v.w;
        }
        {
            int row = tid >> 4, c4 = tid & 15;
            float4 v = *(const float4*)(g_Wc + (size_t)(k0 + row) * DD + n0 + c4 * 4);
            *(float4*)&Bs[row][c4*4] = v;
        }
        __syncthreads();
#pragma unroll
        for (int kk = 0; kk < 16; kk++) {
            float a[8], b[4];
#pragma unroll
            for (int i = 0; i < 8; i++) a[i] = As[kk][ty*8 + i];
#pragma unroll
            for (int j = 0; j < 4; j++) b[j] = Bs[kk][tx*4 + j];
#pragma unroll
            for (int i = 0; i < 8; i++)
#pragma unroll
                for (int j = 0; j < 4; j++) acc[i][j] += a[i] * b[j];
        }
        __syncthreads();
    }
#pragma unroll
    for (int i = 0; i < 8; i++) {
        int r = m0 + ty*8 + i;
        int b = r >> 8, nn = r & 255;
        int s = nn + 1;
        size_t orow = ((size_t)(b * SS + s)) * DD;
#pragma unroll
        for (int j = 0; j < 4; j++) {
            int o = n0 + tx*4 + j;
            g_x[orow + o] = acc[i][j] + conv_b[o] + pos[(size_t)s * DD + o];
        }
    }
}

// ---------------- small kernels ----------------
__global__ void transpose_convw_k(const float* __restrict__ cw) {
    int idx = blockIdx.x * blockDim.x + threadIdx.x;
    if (idx >= KCONV * DD) return;
    int o = idx & 511;
    int k = idx >> 9;
    int i = k & 511;
    int p = k >> 9;
    g_Wc[idx] = cw[(size_t)o * 8192 + i * 16 + p];
}

__global__ void lengths_k(const float* __restrict__ mask) {
    __shared__ float sh[256];
    int b = blockIdx.x;
    float s = 0.f;
    for (int i = threadIdx.x; i < LL; i += 256) s += mask[(size_t)b * LL + i];
    sh[threadIdx.x] = s;
    __syncthreads();
    for (int st = 128; st > 0; st >>= 1) {
        if (threadIdx.x < st) sh[threadIdx.x] += sh[threadIdx.x + st];
        __syncthreads();
    }
    if (threadIdx.x == 0) g_len[b] = ceilf((sh[0] + 1.0f) / (float)PP);
}

__global__ void init_cls_k(const float* __restrict__ cls, const float* __restrict__ pos) {
    int idx = blockIdx.x * blockDim.x + threadIdx.x;
    if (idx >= BB * DD) return;
    int b = idx >> 9, d = idx & 511;
    g_x[(size_t)b * SS * DD + d] = cls[d] + pos[d];
}

__global__ void zero_pad_k() {
    int i = blockIdx.x * blockDim.x + threadIdx.x;
    int n = (TPAD - TT) * DD;
    if (i < n) {
        g_x[(size_t)TT * DD + i] = 0.f;
        g_attn[(size_t)TT * DD + i] = 0.f;
    }
}

// rope + elu feature map, in place on g_q / g_k (k also masked)
__global__ void __launch_bounds__(512) rope_feat_k() {
    int t = blockIdx.x;            // 0..TT-1
    int c = threadIdx.x;           // 0..511
    __shared__ float qrow[DD], krow[DD];
    size_t base = (size_t)t * DD;
    qrow[c] = g_q[base + c];
    krow[c] = g_k[base + c];
    __syncthreads();
    int s = t % SS, b = t / SS;
    int cc = c & 63, j = cc & 31;
    float invf = powf(10000.f, -(float)(2 * j) / 64.f);
    float ang = (float)s * invf;
    float cs = cosf(ang), sn = sinf(ang);
    int partner = (cc < 32) ? c + 32 : c - 32;
    float sgn = (cc < 32) ? -1.f : 1.f;
    float qr = qrow[c] * cs + sgn * qrow[partner] * sn;
    float kr = krow[c] * cs + sgn * krow[partner] * sn;
    float qf = qr > 0.f ? qr + 1.f : expf(qr);   // elu+1
    float kf = kr > 0.f ? kr + 1.f : expf(kr);
    float msk = ((float)s < g_len[b]) ? 1.f : 0.f;
    g_q[base + c] = qf;
    g_k[base + c] = kf * msk;
}

// per (b,h): kv[d][m] = sum_s kf[b,s,h,d]*v[b,s,h,m];  ksum[d] = sum_s kf
__global__ void __launch_bounds__(256) kv_k() {
    int bh = blockIdx.x;
    int b = bh >> 3, h = bh & 7;
    __shared__ float kf_sh[DHD], v_sh[DHD];
    int tid = threadIdx.x;
    int m = tid & 63, dg = tid >> 6;
    float acc[16];
#pragma unroll
    for (int jj = 0; jj < 16; jj++) acc[jj] = 0.f;
    float ksum_acc = 0.f;
    for (int s = 0; s < SS; s++) {
        size_t base = ((size_t)(b * SS + s)) * DD + h * DHD;
        if (tid < DHD) kf_sh[tid] = g_k[base + tid];
        else if (tid < 2 * DHD) v_sh[tid - DHD] = g_v[base + tid - DHD];
        __syncthreads();
        float vv = v_sh[m];
#pragma unroll
        for (int jj = 0; jj < 16; jj++) acc[jj] += kf_sh[dg * 16 + jj] * vv;
        if (tid < DHD) ksum_acc += kf_sh[tid];
        __syncthreads();
    }
#pragma unroll
    for (int jj = 0; jj < 16; jj++) {
        int d = dg * 16 + jj;
        g_kv[((size_t)bh * DHD + d) * DHD + m] = acc[jj];
    }
    if (tid < DHD) g_ksum[bh * DHD + tid] = ksum_acc;
}

// per (b,h): attn[b,s,h,m] = z * sum_d qf[d]*kv[d][m], z = 1/(qf·ksum + 1e-6)
__global__ void __launch_bounds__(256) attn_k() {
    int bh = blockIdx.x;
    int b = bh >> 3, h = bh & 7;
    __shared__ float kvs[DHD * DHD];
    __shared__ float ks[DHD];
    __shared__ float qsh[DHD];
    __shared__ float part[4][DHD];
    __shared__ float red[64];
    __shared__ float zsh;
    int tid = threadIdx.x;
    for (int i = tid; i < DHD * DHD; i += 256) kvs[i] = g_kv[(size_t)bh * DHD * DHD + i];
    if (tid < DHD) ks[tid] = g_ksum[bh * DHD + tid];
    __syncthreads();
    int m = tid & 63, dg = tid >> 6;
    for (int s = 0; s < SS; s++) {
        size_t base = ((size_t)(b * SS + s)) * DD + h * DHD;
        if (tid < DHD) qsh[tid] = g_q[base + tid];
        __syncthreads();
        if (tid < 64) red[tid] = qsh[tid] * ks[tid];
        __syncthreads();
        if (tid < 32) {
            float r = red[tid] + red[tid + 32];
            for (int o = 16; o; o >>= 1) r += __shfl_down_sync(0xffffffffu, r, o);
            if (tid == 0) zsh = 1.f / (r + 1e-6f);
        }
        float a = 0.f;
#pragma unroll
        for (int jj = 0; jj < 16; jj++) {
            int d = dg * 16 + jj;
            a += qsh[d] * kvs[d * DHD + m];
        }
        part[dg][m] = a;
        __syncthreads();
        if (tid < 64)
            g_attn[base + tid] = (part[0][tid] + part[1][tid] + part[2][tid] + part[3][tid]) * zsh;
        __syncthreads();
    }
}

// X = LN(X (+ Y)) rowwise, 512 cols
template<int ADD>
__global__ void __launch_bounds__(256) ln_k(
    const float* __restrict__ Y, const float* __restrict__ sc,
    const float* __restrict__ bi, float* __restrict__ X)
{
    int t = blockIdx.x, tid = threadIdx.x;
    size_t base = (size_t)t * DD;
    float v0 = X[base + tid];
    float v1 = X[base + tid + 256];
    if (ADD) { v0 += Y[base + tid]; v1 += Y[base + tid + 256]; }
    float s = v0 + v1, ss = v0 * v0 + v1 * v1;
    __shared__ float rs[8], rss[8];
    for (int o = 16; o; o >>= 1) {
        s  += __shfl_down_sync(0xffffffffu, s, o);
        ss += __shfl_down_sync(0xffffffffu, ss, o);
    }
    int w = tid >> 5;
    if ((tid & 31) == 0) { rs[w] = s; rss[w] = ss; }
    __syncthreads();
    if (tid == 0) {
        float S1 = 0.f, S2 = 0.f;
        for (int i = 0; i < 8; i++) { S1 += rs[i]; S2 += rss[i]; }
        rs[0] = S1 / (float)DD;
        rss[0] = S2 / (float)DD;
    }
    __syncthreads();
    float mean = rs[0];
    float var = rss[0] - mean * mean;
    float inv = rsqrtf(var + 1e-5f);
    X[base + tid]       = (v0 - mean) * inv * sc[tid] + bi[tid];
    X[base + tid + 256] = (v1 - mean) * inv * sc[tid + 256] + bi[tid + 256];
}

// final LN on token 0 + classifier head
__global__ void __launch_bounds__(256) final_k(
    const float* __restrict__ lnf_s, const float* __restrict__ lnf_b,
    const float* __restrict__ ow, const float* __restrict__ ob,
    float* __restrict__ out)
{
    int b = blockIdx.x, tid = threadIdx.x;
    size_t base = (size_t)b * SS * DD;
    float v0 = g_x[base + tid];
    float v1 = g_x[base + tid + 256];
    float s = v0 + v1, ss = v0 * v0 + v1 * v1;
    __shared__ float rs[8], rss[8];
    __shared__ float row[DD];
    for (int o = 16; o; o >>= 1) {
        s  += __shfl_down_sync(0xffffffffu, s, o);
        ss += __shfl_down_sync(0xffffffffu, ss, o);
    }
    int w = tid >> 5;
    if ((tid & 31) == 0) { rs[w] = s; rss[w] = ss; }
    __syncthreads();
    if (tid == 0) {
        float S1 = 0.f, S2 = 0.f;
        for (int i = 0; i < 8; i++) { S1 += rs[i]; S2 += rss[i]; }
        rs[0] = S1 / (float)DD;
        rss[0] = S2 / (float)DD;
    }
    __syncthreads();
    float mean = rs[0];
    float inv = rsqrtf(rss[0] - mean * mean + 1e-5f);
    row[tid]       = (v0 - mean) * inv * lnf_s[tid] + lnf_b[tid];
    row[tid + 256] = (v1 - mean) * inv * lnf_s[tid + 256] + lnf_b[tid + 256];
    __syncthreads();
    for (int c = 0; c < NCLS; c++) {
        float p = row[tid] * ow[tid * NCLS + c] + row[tid + 256] * ow[(tid + 256) * NCLS + c];
        for (int o = 16; o; o >>= 1) p += __shfl_down_sync(0xffffffffu, p, o);
        if ((tid & 31) == 0) rs[tid >> 5] = p;
        __syncthreads();
        if (tid == 0) {
            float t2 = 0.f;
            for (int i = 0; i < 8; i++) t2 += rs[i];
            out[b * NCLS + c] = t2 + ob[c];
        }
        __syncthreads();
    }
}

// ---------------- host driver ----------------
extern "C" void kernel_launch(void* const* d_in, const int* in_sizes, int n_in,
                              void* d_out, int out_size)
{
    const int*   inputs     = (const int*)  d_in[0];
    const float* input_mask = (const float*)d_in[1];
    const float* emb        = (const float*)d_in[2];
    const float* conv_w     = (const float*)d_in[3];
    const float* conv_b     = (const float*)d_in[4];
    const float* pos        = (const float*)d_in[5];
    const float* cls        = (const float*)d_in[6];
    const float* Wq         = (const float*)d_in[7];
    const float* bq         = (const float*)d_in[8];
    const float* Wk         = (const float*)d_in[9];
    const float* bk         = (const float*)d_in[10];
    const float* Wv         = (const float*)d_in[11];
    const float* bv         = (const float*)d_in[12];
    const float* Wo         = (const float*)d_in[13];
    const float* bo         = (const float*)d_in[14];
    const float* ln1_s      = (const float*)d_in[15];
    const float* ln1_b      = (const float*)d_in[16];
    const float* ln2_s      = (const float*)d_in[17];
    const float* ln2_b      = (const float*)d_in[18];
    const float* W1         = (const float*)d_in[19];
    const float* b1         = (const float*)d_in[20];
    const float* W2         = (const float*)d_in[21];
    const float* b2         = (const float*)d_in[22];
    const float* lnf_s      = (const float*)d_in[23];
    const float* lnf_b      = (const float*)d_in[24];
    const float* out_w      = (const float*)d_in[25];
    const float* out_b      = (const float*)d_in[26];
    float* out = (float*)d_out;

    float *px, *pq, *pk, *pv, *pattn, *py, *ph;
    cudaGetSymbolAddress((void**)&px,    g_x);
    cudaGetSymbolAddress((void**)&pq,    g_q);
    cudaGetSymbolAddress((void**)&pk,    g_k);
    cudaGetSymbolAddress((void**)&pv,    g_v);
    cudaGetSymbolAddress((void**)&pattn, g_attn);
    cudaGetSymbolAddress((void**)&py,    g_y);
    cudaGetSymbolAddress((void**)&ph,    g_h);

    // prologue
    transpose_convw_k<<<(KCONV * DD + 255) / 256, 256>>>(conv_w);
    lengths_k<<<BB, 256>>>(input_mask);
    zero_pad_k<<<((TPAD - TT) * DD + 255) / 256, 256>>>();
    init_cls_k<<<(BB * DD + 255) / 256, 256>>>(cls, pos);
    conv_gemm_k<<<dim3(DD / 64, MCONV / 128), 256>>>(inputs, emb, conv_b, pos);

    dim3 gD(DD / 128, TPAD / 128);   // N=512 GEMMs over all tokens
    dim3 gF(FFD / 128, TPAD / 128);  // N=2048

    for (int i = 0; i < NLAY; i++) {
        size_t wOff = (size_t)i * DD * DD;
        gemm_k<0><<<gD, 256>>>(px, Wq + wOff, bq + (size_t)i * DD, pq, TPAD, DD, DD);
        gemm_k<0><<<gD, 256>>>(px, Wk + wOff, bk + (size_t)i * DD, pk, TPAD, DD, DD);
        gemm_k<0><<<gD, 256>>>(px, Wv + wOff, bv + (size_t)i * DD, pv, TPAD, DD, DD);
        rope_feat_k<<<TT, 512>>>();
        kv_k<<<BB * HH, 256>>>();
        attn_k<<<BB * HH, 256>>>();
        gemm_k<0><<<gD, 256>>>(pattn, Wo + wOff, bo + (size_t)i * DD, py, TPAD, DD, DD);
        ln_k<1><<<TPAD, 256>>>(py, ln1_s + (size_t)i * DD, ln1_b + (size_t)i * DD, px);
        gemm_k<1><<<gF, 256>>>(px, W1 + (size_t)i * DD * FFD, b1 + (size_t)i * FFD, ph, TPAD, FFD, DD);
        gemm_k<0><<<gD, 256>>>(ph, W2 + (size_t)i * FFD * DD, b2 + (size_t)i * DD, py, TPAD, DD, FFD);
        ln_k<1><<<TPAD, 256>>>(py, ln2_s + (size_t)i * DD, ln2_b + (size_t)i * DD, px);
    }

    final_k<<<BB, 256>>>(lnf_s, lnf_b, out_w, out_b, out);
}

// round 4
// speedup vs baseline: 1.2270x; 1.2270x over previous
#include <cuda_runtime.h>
#include <mma.h>
#include <math.h>

using namespace nvcuda;

#define BB   32
#define LL   4096
#define PP   16
#define SS   257
#define DD   512
#define HH   8
#define DHD  64
#define NLAY 8
#define FFD  2048
#define NCLS 4
#define TT   (BB*SS)      /* 8224 */
#define TPAD 8320         /* 65*128 */
#define KCONV 8192
#define MCONV 8192

// ---------------- scratch (device globals; no allocations) ----------------
__device__ float g_x[TPAD*DD];
__device__ float g_q[TPAD*DD];
__device__ float g_k[TPAD*DD];
__device__ float g_v[TPAD*DD];
__device__ float g_attn[TPAD*DD];
__device__ float g_y[TPAD*DD];
__device__ float g_h[(size_t)TPAD*FFD];
__device__ float g_kv[BB*HH*DHD*DHD];
__device__ float g_ksum[BB*HH*DHD];
__device__ float g_Wc[(size_t)KCONV*DD];
__device__ float g_len[BB];

// ================= tf32 tensor-core GEMM =================
// C[M,N] = A[M,K] @ B[K,N] + bias (+ optional exact GELU)
// BM=128, BN=128, BK=32, 256 threads (8 warps, 2x4), warp tile 64x32,
// wmma m16n16k8 tf32, fp32 accumulate.
// M%128==0, N%128==0, K%32==0 (guaranteed by padding).

#define GLD 36   /* As row stride (floats) */
#define BLD 132  /* Bs row stride (floats) */

template<int EPI>
__global__ void __launch_bounds__(256) gemm_tc_k(
    const float* __restrict__ A, const float* __restrict__ Bm,
    const float* __restrict__ bias, float* __restrict__ C,
    int M, int N, int K)
{
    __shared__ float As[128][GLD];
    __shared__ float Bs[32][BLD];
    __shared__ float stage[8][16][20];

    int tid  = threadIdx.x;
    int wid  = tid >> 5, lane = tid & 31;
    int wm   = wid >> 2;          // 0..1
    int wn   = wid & 3;           // 0..3
    int m0   = blockIdx.y * 128;
    int n0   = blockIdx.x * 128;

    wmma::fragment<wmma::accumulator, 16, 16, 8, float> acc[4][2];
#pragma unroll
    for (int i = 0; i < 4; i++)
#pragma unroll
        for (int j = 0; j < 2; j++) wmma::fill_fragment(acc[i][j], 0.f);

    for (int k0 = 0; k0 < K; k0 += 32) {
        // A tile 128x32
#pragma unroll
        for (int t = 0; t < 4; t++) {
            int idx = tid + t * 256;
            int row = idx >> 3, c4 = idx & 7;
            float4 v = *(const float4*)(A + (size_t)(m0 + row) * K + k0 + c4 * 4);
            *(float4*)&As[row][c4 * 4] = v;
        }
        // B tile 32x128
#pragma unroll
        for (int t = 0; t < 4; t++) {
            int idx = tid + t * 256;
            int row = idx >> 5, c4 = idx & 31;
            float4 v = *(const float4*)(Bm + (size_t)(k0 + row) * N + n0 + c4 * 4);
            *(float4*)&Bs[row][c4 * 4] = v;
        }
        __syncthreads();
#pragma unroll
        for (int k8 = 0; k8 < 4; k8++) {
            wmma::fragment<wmma::matrix_a, 16, 16, 8, wmma::precision::tf32, wmma::row_major> af[4];
            wmma::fragment<wmma::matrix_b, 16, 16, 8, wmma::precision::tf32, wmma::row_major> bf[2];
#pragma unroll
            for (int i = 0; i < 4; i++) {
                wmma::load_matrix_sync(af[i], &As[wm * 64 + i * 16][k8 * 8], GLD);
#pragma unroll
                for (int e = 0; e < af[i].num_elements; e++)
                    af[i].x[e] = wmma::__float_to_tf32(af[i].x[e]);
            }
#pragma unroll
            for (int j = 0; j < 2; j++) {
                wmma::load_matrix_sync(bf[j], &Bs[k8 * 8][wn * 32 + j * 16], BLD);
#pragma unroll
                for (int e = 0; e < bf[j].num_elements; e++)
                    bf[j].x[e] = wmma::__float_to_tf32(bf[j].x[e]);
            }
#pragma unroll
            for (int i = 0; i < 4; i++)
#pragma unroll
                for (int j = 0; j < 2; j++)
                    wmma::mma_sync(acc[i][j], af[i], bf[j], acc[i][j]);
        }
        __syncthreads();
    }

    // epilogue: stage per-warp, apply bias (+gelu), write C
#pragma unroll
    for (int i = 0; i < 4; i++)
#pragma unroll
        for (int j = 0; j < 2; j++) {
            wmma::store_matrix_sync(&stage[wid][0][0], acc[i][j], 20, wmma::mem_row_major);
            __syncwarp();
#pragma unroll
            for (int e = 0; e < 8; e++) {
                int idx = lane * 8 + e;
                int r = idx >> 4, c = idx & 15;
                int m = m0 + wm * 64 + i * 16 + r;
                int n = n0 + wn * 32 + j * 16 + c;
                float val = stage[wid][r][c] + bias[n];
                if (EPI == 1) val = 0.5f * val * (1.0f + erff(val * 0.70710678118654752f));
                C[(size_t)m * N + n] = val;
            }
            __syncwarp();
        }
}

// ---------------- conv-embedding GEMM (gather A rows) on tensor cores ----
__global__ void __launch_bounds__(256) conv_gemm_tc_k(
    const int* __restrict__ tok, const float* __restrict__ emb,
    const float* __restrict__ conv_b, const float* __restrict__ pos)
{
    __shared__ float As[128][GLD];
    __shared__ float Bs[32][BLD];
    __shared__ float stage[8][16][20];
    __shared__ int toks[128];

    int tid  = threadIdx.x;
    int wid  = tid >> 5, lane = tid & 31;
    int wm   = wid >> 2, wn = wid & 3;
    int m0   = blockIdx.y * 128;
    int n0   = blockIdx.x * 128;

    wmma::fragment<wmma::accumulator, 16, 16, 8, float> acc[4][2];
#pragma unroll
    for (int i = 0; i < 4; i++)
#pragma unroll
        for (int j = 0; j < 2; j++) wmma::fill_fragment(acc[i][j], 0.f);

    for (int k0 = 0; k0 < KCONV; k0 += 32) {
        int p  = k0 >> 9;
        int i0 = k0 & 511;
        if (i0 == 0) {
            __syncthreads();
            if (tid < 128) {
                int r = m0 + tid;
                int b = r >> 8, nn = r & 255;
                toks[tid] = tok[b * LL + nn * PP + p];
            }
            __syncthreads();
        }
#pragma unroll
        for (int t = 0; t < 4; t++) {
            int idx = tid + t * 256;
            int row = idx >> 3, c4 = idx & 7;
            int tk = toks[row];
            float4 v = *(const float4*)(emb + (size_t)tk * DD + i0 + c4 * 4);
            *(float4*)&As[row][c4 * 4] = v;
        }
#pragma unroll
        for (int t = 0; t < 4; t++) {
            int idx = tid + t * 256;
            int row = idx >> 5, c4 = idx & 31;
            float4 v = *(const float4*)(g_Wc + (size_t)(k0 + row) * DD + n0 + c4 * 4);
            *(float4*)&Bs[row][c4 * 4] = v;
        }
        __syncthreads();
#pragma unroll
        for (int k8 = 0; k8 < 4; k8++) {
            wmma::fragment<wmma::matrix_a, 16, 16, 8, wmma::precision::tf32, wmma::row_major> af[4];
            wmma::fragment<wmma::matrix_b, 16, 16, 8, wmma::precision::tf32, wmma::row_major> bf[2];
#pragma unroll
            for (int i = 0; i < 4; i++) {
                wmma::load_matrix_sync(af[i], &As[wm * 64 + i * 16][k8 * 8], GLD);
#pragma unroll
                for (int e = 0; e < af[i].num_elements; e++)
                    af[i].x[e] = wmma::__float_to_tf32(af[i].x[e]);
            }
#pragma unroll
            for (int j = 0; j < 2; j++) {
                wmma::load_matrix_sync(bf[j], &Bs[k8 * 8][wn * 32 + j * 16], BLD);
#pragma unroll
                for (int e = 0; e < bf[j].num_elements; e++)
                    bf[j].x[e] = wmma::__float_to_tf32(bf[j].x[e]);
            }
#pragma unroll
            for (int i = 0; i < 4; i++)
#pragma unroll
                for (int j = 0; j < 2; j++)
                    wmma::mma_sync(acc[i][j], af[i], bf[j], acc[i][j]);
        }
        __syncthreads();
    }

#pragma unroll
    for (int i = 0; i < 4; i++)
#pragma unroll
        for (int j = 0; j < 2; j++) {
            wmma::store_matrix_sync(&stage[wid][0][0], acc[i][j], 20, wmma::mem_row_major);
            __syncwarp();
#pragma unroll
            for (int e = 0; e < 8; e++) {
                int idx = lane * 8 + e;
                int r = idx >> 4, c = idx & 15;
                int mrow = m0 + wm * 64 + i * 16 + r;
                int b = mrow >> 8, nn = mrow & 255;
                int s = nn + 1;
                int n = n0 + wn * 32 + j * 16 + c;
                float val = stage[wid][r][c] + conv_b[n] + pos[(size_t)s * DD + n];
                g_x[((size_t)(b * SS + s)) * DD + n] = val;
            }
            __syncwarp();
        }
}

// ---------------- small kernels ----------------
__global__ void transpose_convw_k(const float* __restrict__ cw) {
    int idx = blockIdx.x * blockDim.x + threadIdx.x;
    if (idx >= KCONV * DD) return;
    int o = idx & 511;
    int k = idx >> 9;
    int i = k & 511;
    int p = k >> 9;
    g_Wc[idx] = cw[(size_t)o * 8192 + i * 16 + p];
}

__global__ void lengths_k(const float* __restrict__ mask) {
    __shared__ float sh[256];
    int b = blockIdx.x;
    float s = 0.f;
    for (int i = threadIdx.x; i < LL; i += 256) s += mask[(size_t)b * LL + i];
    sh[threadIdx.x] = s;
    __syncthreads();
    for (int st = 128; st > 0; st >>= 1) {
        if (threadIdx.x < st) sh[threadIdx.x] += sh[threadIdx.x + st];
        __syncthreads();
    }
    if (threadIdx.x == 0) g_len[b] = ceilf((sh[0] + 1.0f) / (float)PP);
}

__global__ void init_cls_k(const float* __restrict__ cls, const float* __restrict__ pos) {
    int idx = blockIdx.x * blockDim.x + threadIdx.x;
    if (idx >= BB * DD) return;
    int b = idx >> 9, d = idx & 511;
    g_x[(size_t)b * SS * DD + d] = cls[d] + pos[d];
}

__global__ void zero_pad_k() {
    int i = blockIdx.x * blockDim.x + threadIdx.x;
    int n = (TPAD - TT) * DD;
    if (i < n) {
        g_x[(size_t)TT * DD + i] = 0.f;
        g_attn[(size_t)TT * DD + i] = 0.f;
    }
}

// rope + elu feature map, in place on g_q / g_k (k also masked)
__global__ void __launch_bounds__(512) rope_feat_k() {
    int t = blockIdx.x;            // 0..TT-1
    int c = threadIdx.x;           // 0..511
    __shared__ float qrow[DD], krow[DD];
    size_t base = (size_t)t * DD;
    qrow[c] = g_q[base + c];
    krow[c] = g_k[base + c];
    __syncthreads();
    int s = t % SS, b = t / SS;
    int cc = c & 63, j = cc & 31;
    float invf = powf(10000.f, -(float)(2 * j) / 64.f);
    float ang = (float)s * invf;
    float cs = cosf(ang), sn = sinf(ang);
    int partner = (cc < 32) ? c + 32 : c - 32;
    float sgn = (cc < 32) ? -1.f : 1.f;
    float qr = qrow[c] * cs + sgn * qrow[partner] * sn;
    float kr = krow[c] * cs + sgn * krow[partner] * sn;
    float qf = qr > 0.f ? qr + 1.f : expf(qr);   // elu+1
    float kf = kr > 0.f ? kr + 1.f : expf(kr);
    float msk = ((float)s < g_len[b]) ? 1.f : 0.f;
    g_q[base + c] = qf;
    g_k[base + c] = kf * msk;
}

// per (b,h): kv[d][m] = sum_s kf[b,s,h,d]*v[b,s,h,m];  ksum[d] = sum_s kf
__global__ void __launch_bounds__(256) kv_k() {
    int bh = blockIdx.x;
    int b = bh >> 3, h = bh & 7;
    __shared__ float kf_sh[DHD], v_sh[DHD];
    int tid = threadIdx.x;
    int m = tid & 63, dg = tid >> 6;
    float acc[16];
#pragma unroll
    for (int jj = 0; jj < 16; jj++) acc[jj] = 0.f;
    float ksum_acc = 0.f;
    for (int s = 0; s < SS; s++) {
        size_t base = ((size_t)(b * SS + s)) * DD + h * DHD;
        if (tid < DHD) kf_sh[tid] = g_k[base + tid];
        else if (tid < 2 * DHD) v_sh[tid - DHD] = g_v[base + tid - DHD];
        __syncthreads();
        float vv = v_sh[m];
#pragma unroll
        for (int jj = 0; jj < 16; jj++) acc[jj] += kf_sh[dg * 16 + jj] * vv;
        if (tid < DHD) ksum_acc += kf_sh[tid];
        __syncthreads();
    }
#pragma unroll
    for (int jj = 0; jj < 16; jj++) {
        int d = dg * 16 + jj;
        g_kv[((size_t)bh * DHD + d) * DHD + m] = acc[jj];
    }
    if (tid < DHD) g_ksum[bh * DHD + tid] = ksum_acc;
}

// per (b,h): attn[b,s,h,m] = z * sum_d qf[d]*kv[d][m], z = 1/(qf·ksum + 1e-6)
__global__ void __launch_bounds__(256) attn_k() {
    int bh = blockIdx.x;
    int b = bh >> 3, h = bh & 7;
    __shared__ float kvs[DHD * DHD];
    __shared__ float ks[DHD];
    __shared__ float qsh[DHD];
    __shared__ float part[4][DHD];
    __shared__ float red[64];
    __shared__ float zsh;
    int tid = threadIdx.x;
    for (int i = tid; i < DHD * DHD; i += 256) kvs[i] = g_kv[(size_t)bh * DHD * DHD + i];
    if (tid < DHD) ks[tid] = g_ksum[bh * DHD + tid];
    __syncthreads();
    int m = tid & 63, dg = tid >> 6;
    for (int s = 0; s < SS; s++) {
        size_t base = ((size_t)(b * SS + s)) * DD + h * DHD;
        if (tid < DHD) qsh[tid] = g_q[base + tid];
        __syncthreads();
        if (tid < 64) red[tid] = qsh[tid] * ks[tid];
        __syncthreads();
        if (tid < 32) {
            float r = red[tid] + red[tid + 32];
            for (int o = 16; o; o >>= 1) r += __shfl_down_sync(0xffffffffu, r, o);
            if (tid == 0) zsh = 1.f / (r + 1e-6f);
        }
        float a = 0.f;
#pragma unroll
        for (int jj = 0; jj < 16; jj++) {
            int d = dg * 16 + jj;
            a += qsh[d] * kvs[d * DHD + m];
        }
        part[dg][m] = a;
        __syncthreads();
        if (tid < 64)
            g_attn[base + tid] = (part[0][tid] + part[1][tid] + part[2][tid] + part[3][tid]) * zsh;
        __syncthreads();
    }
}

// X = LN(X (+ Y)) rowwise, 512 cols
template<int ADD>
__global__ void __launch_bounds__(256) ln_k(
    const float* __restrict__ Y, const float* __restrict__ sc,
    const float* __restrict__ bi, float* __restrict__ X)
{
    int t = blockIdx.x, tid = threadIdx.x;
    size_t base = (size_t)t * DD;
    float v0 = X[base + tid];
    float v1 = X[base + tid + 256];
    if (ADD) { v0 += Y[base + tid]; v1 += Y[base + tid + 256]; }
    float s = v0 + v1, ss = v0 * v0 + v1 * v1;
    __shared__ float rs[8], rss[8];
    for (int o = 16; o; o >>= 1) {
        s  += __shfl_down_sync(0xffffffffu, s, o);
        ss += __shfl_down_sync(0xffffffffu, ss, o);
    }
    int w = tid >> 5;
    if ((tid & 31) == 0) { rs[w] = s; rss[w] = ss; }
    __syncthreads();
    if (tid == 0) {
        float S1 = 0.f, S2 = 0.f;
        for (int i = 0; i < 8; i++) { S1 += rs[i]; S2 += rss[i]; }
        rs[0] = S1 / (float)DD;
        rss[0] = S2 / (float)DD;
    }
    __syncthreads();
    float mean = rs[0];
    float var = rss[0] - mean * mean;
    float inv = rsqrtf(var + 1e-5f);
    X[base + tid]       = (v0 - mean) * inv * sc[tid] + bi[tid];
    X[base + tid + 256] = (v1 - mean) * inv * sc[tid + 256] + bi[tid + 256];
}

// final LN on token 0 + classifier head
__global__ void __launch_bounds__(256) final_k(
    const float* __restrict__ lnf_s, const float* __restrict__ lnf_b,
    const float* __restrict__ ow, const float* __restrict__ ob,
    float* __restrict__ out)
{
    int b = blockIdx.x, tid = threadIdx.x;
    size_t base = (size_t)b * SS * DD;
    float v0 = g_x[base + tid];
    float v1 = g_x[base + tid + 256];
    float s = v0 + v1, ss = v0 * v0 + v1 * v1;
    __shared__ float rs[8], rss[8];
    __shared__ float row[DD];
    for (int o = 16; o; o >>= 1) {
        s  += __shfl_down_sync(0xffffffffu, s, o);
        ss += __shfl_down_sync(0xffffffffu, ss, o);
    }
    int w = tid >> 5;
    if ((tid & 31) == 0) { rs[w] = s; rss[w] = ss; }
    __syncthreads();
    if (tid == 0) {
        float S1 = 0.f, S2 = 0.f;
        for (int i = 0; i < 8; i++) { S1 += rs[i]; S2 += rss[i]; }
        rs[0] = S1 / (float)DD;
        rss[0] = S2 / (float)DD;
    }
    __syncthreads();
    float mean = rs[0];
    float inv = rsqrtf(rss[0] - mean * mean + 1e-5f);
    row[tid]       = (v0 - mean) * inv * lnf_s[tid] + lnf_b[tid];
    row[tid + 256] = (v1 - mean) * inv * lnf_s[tid + 256] + lnf_b[tid + 256];
    __syncthreads();
    for (int c = 0; c < NCLS; c++) {
        float p = row[tid] * ow[tid * NCLS + c] + row[tid + 256] * ow[(tid + 256) * NCLS + c];
        for (int o = 16; o; o >>= 1) p += __shfl_down_sync(0xffffffffu, p, o);
        if ((tid & 31) == 0) rs[tid >> 5] = p;
        __syncthreads();
        if (tid == 0) {
            float t2 = 0.f;
            for (int i = 0; i < 8; i++) t2 += rs[i];
            out[b * NCLS + c] = t2 + ob[c];
        }
        __syncthreads();
    }
}

// ---------------- host driver ----------------
extern "C" void kernel_launch(void* const* d_in, const int* in_sizes, int n_in,
                              void* d_out, int out_size)
{
    const int*   inputs     = (const int*)  d_in[0];
    const float* input_mask = (const float*)d_in[1];
    const float* emb        = (const float*)d_in[2];
    const float* conv_w     = (const float*)d_in[3];
    const float* conv_b     = (const float*)d_in[4];
    const float* pos        = (const float*)d_in[5];
    const float* cls        = (const float*)d_in[6];
    const float* Wq         = (const float*)d_in[7];
    const float* bq         = (const float*)d_in[8];
    const float* Wk         = (const float*)d_in[9];
    const float* bk         = (const float*)d_in[10];
    const float* Wv         = (const float*)d_in[11];
    const float* bv         = (const float*)d_in[12];
    const float* Wo         = (const float*)d_in[13];
    const float* bo         = (const float*)d_in[14];
    const float* ln1_s      = (const float*)d_in[15];
    const float* ln1_b      = (const float*)d_in[16];
    const float* ln2_s      = (const float*)d_in[17];
    const float* ln2_b      = (const float*)d_in[18];
    const float* W1         = (const float*)d_in[19];
    const float* b1         = (const float*)d_in[20];
    const float* W2         = (const float*)d_in[21];
    const float* b2         = (const float*)d_in[22];
    const float* lnf_s      = (const float*)d_in[23];
    const float* lnf_b      = (const float*)d_in[24];
    const float* out_w      = (const float*)d_in[25];
    const float* out_b      = (const float*)d_in[26];
    float* out = (float*)d_out;

    float *px, *pq, *pk, *pv, *pattn, *py, *ph;
    cudaGetSymbolAddress((void**)&px,    g_x);
    cudaGetSymbolAddress((void**)&pq,    g_q);
    cudaGetSymbolAddress((void**)&pk,    g_k);
    cudaGetSymbolAddress((void**)&pv,    g_v);
    cudaGetSymbolAddress((void**)&pattn, g_attn);
    cudaGetSymbolAddress((void**)&py,    g_y);
    cudaGetSymbolAddress((void**)&ph,    g_h);

    // prologue
    transpose_convw_k<<<(KCONV * DD + 255) / 256, 256>>>(conv_w);
    lengths_k<<<BB, 256>>>(input_mask);
    zero_pad_k<<<((TPAD - TT) * DD + 255) / 256, 256>>>();
    init_cls_k<<<(BB * DD + 255) / 256, 256>>>(cls, pos);
    conv_gemm_tc_k<<<dim3(DD / 128, MCONV / 128), 256>>>(inputs, emb, conv_b, pos);

    dim3 gD(DD / 128, TPAD / 128);   // (4, 65)
    dim3 gF(FFD / 128, TPAD / 128);  // (16, 65)

    for (int i = 0; i < NLAY; i++) {
        size_t wOff = (size_t)i * DD * DD;
        gemm_tc_k<0><<<gD, 256>>>(px, Wq + wOff, bq + (size_t)i * DD, pq, TPAD, DD, DD);
        gemm_tc_k<0><<<gD, 256>>>(px, Wk + wOff, bk + (size_t)i * DD, pk, TPAD, DD, DD);
        gemm_tc_k<0><<<gD, 256>>>(px, Wv + wOff, bv + (size_t)i * DD, pv, TPAD, DD, DD);
        rope_feat_k<<<TT, 512>>>();
        kv_k<<<BB * HH, 256>>>();
        attn_k<<<BB * HH, 256>>>();
        gemm_tc_k<0><<<gD, 256>>>(pattn, Wo + wOff, bo + (size_t)i * DD, py, TPAD, DD, DD);
        ln_k<1><<<TPAD, 256>>>(py, ln1_s + (size_t)i * DD, ln1_b + (size_t)i * DD, px);
        gemm_tc_k<1><<<gF, 256>>>(px, W1 + (size_t)i * DD * FFD, b1 + (size_t)i * FFD, ph, TPAD, FFD, DD);
        gemm_tc_k<0><<<gD, 256>>>(ph, W2 + (size_t)i * FFD * DD, b2 + (size_t)i * DD, py, TPAD, DD, FFD);
        ln_k<1><<<TPAD, 256>>>(py, ln2_s + (size_t)i * DD, ln2_b + (size_t)i * DD, px);
    }

    final_k<<<BB, 256>>>(lnf_s, lnf_b, out_w, out_b, out);
}

// round 5
// speedup vs baseline: 1.4756x; 1.2027x over previous
#include <cuda_runtime.h>
#include <mma.h>
#include <math.h>

using namespace nvcuda;

#define BB   32
#define LL   4096
#define PP   16
#define SS   257
#define DD   512
#define HH   8
#define DHD  64
#define NLAY 8
#define FFD  2048
#define NCLS 4
#define TT   (BB*SS)      /* 8224 */
#define TPAD 8320         /* 65*128 */
#define KCONV 8192
#define MCONV 8192
#define NQKV 1536

// ---------------- scratch (device globals; no allocations) ----------------
__device__ float g_x[TPAD*DD];
__device__ float g_xr[TPAD*DD];          // tf32-rounded copy of x (GEMM A)
__device__ float g_qkv[(size_t)TPAD*NQKV];
__device__ float g_attn[TPAD*DD];        // rounded (GEMM A)
__device__ float g_y[TPAD*DD];
__device__ float g_h[(size_t)TPAD*FFD];  // rounded (GEMM A)
__device__ float g_kv[BB*HH*DHD*DHD];
__device__ float g_ksum[BB*HH*DHD];
__device__ float g_len[BB];
// pre-rounded weights
__device__ float g_Wc[(size_t)KCONV*DD];
__device__ float g_embt[(size_t)32000*DD];
__device__ float g_Wqkv[(size_t)NLAY*DD*NQKV];
__device__ float g_bqkv[NLAY*NQKV];
__device__ float g_Wo[(size_t)NLAY*DD*DD];
__device__ float g_W1[(size_t)NLAY*DD*FFD];
__device__ float g_W2[(size_t)NLAY*FFD*DD];

// ---------------- helpers ----------------
__device__ __forceinline__ float tf32r(float x) {
    float y; asm("cvt.rna.tf32.f32 %0, %1;" : "=f"(y) : "f"(x)); return y;
}
__device__ __forceinline__ void cp_async16(float* dst, const float* src) {
    unsigned d = (unsigned)__cvta_generic_to_shared(dst);
    asm volatile("cp.async.cg.shared.global [%0], [%1], 16;\n" :: "r"(d), "l"(src) : "memory");
}
__device__ __forceinline__ void cp_commit() {
    asm volatile("cp.async.commit_group;\n" ::: "memory");
}
__device__ __forceinline__ void cp_wait_1() {
    asm volatile("cp.async.wait_group 1;\n" ::: "memory");
}

// ================= pipelined tf32 tensor-core GEMM =================
// C[M,N] = A[M,K]@B[K,N] + bias (+gelu&round). A,B pre-rounded to tf32.
// BM=128, BN=128, BK=32, 256 thr (8 warps 2x4), warp tile 64x32, 3-stage cp.async.
#define STAGES 3
#define ASZ (128*36)
#define BSZ (32*132)
#define STGF (ASZ+BSZ)
#define SMEMB (STAGES*STGF*4)

#define GEMM_ISSUE(IT, STG_, APTR, BPTR, KDIM, NDIM) do{                          \
    float* As_ = sm + (STG_)*STGF; float* Bs_ = As_ + ASZ; int k0_ = (IT) << 5;   \
    _Pragma("unroll") for (int t_ = 0; t_ < 4; t_++) {                            \
        int idx_ = tid + t_*256; int row_ = idx_ >> 3, c4_ = idx_ & 7;            \
        cp_async16(As_ + row_*36 + c4_*4,                                         \
                   (APTR) + (size_t)(m0 + row_)*(KDIM) + k0_ + c4_*4); }          \
    _Pragma("unroll") for (int t_ = 0; t_ < 4; t_++) {                            \
        int idx_ = tid + t_*256; int row_ = idx_ >> 5, c4_ = idx_ & 31;           \
        cp_async16(Bs_ + row_*132 + c4_*4,                                        \
                   (BPTR) + (size_t)(k0_ + row_)*(NDIM) + n0 + c4_*4); }          \
} while(0)

#define GEMM_COMPUTE(STG_) do{                                                    \
    const float* As_ = sm + (STG_)*STGF; const float* Bs_ = As_ + ASZ;            \
    _Pragma("unroll") for (int k8 = 0; k8 < 4; k8++) {                            \
        wmma::fragment<wmma::matrix_a,16,16,8,wmma::precision::tf32,wmma::row_major> af[4]; \
        wmma::fragment<wmma::matrix_b,16,16,8,wmma::precision::tf32,wmma::row_major> bf[2]; \
        _Pragma("unroll") for (int i = 0; i < 4; i++)                             \
            wmma::load_matrix_sync(af[i], As_ + (wm*64 + i*16)*36 + k8*8, 36);    \
        _Pragma("unroll") for (int j = 0; j < 2; j++)                             \
            wmma::load_matrix_sync(bf[j], Bs_ + (k8*8)*132 + wn*32 + j*16, 132);  \
        _Pragma("unroll") for (int i = 0; i < 4; i++)                             \
            _Pragma("unroll") for (int j = 0; j < 2; j++)                         \
                wmma::mma_sync(acc[i][j], af[i], bf[j], acc[i][j]); }             \
} while(0)

template<int EPI>   // 0: bias   1: bias+gelu+round (for g_h)
__global__ void __launch_bounds__(256) gemm_tc2_k(
    const float* __restrict__ A, const float* __restrict__ Bm,
    const float* __restrict__ bias, float* __restrict__ C,
    int N, int K)
{
    extern __shared__ float sm[];
    int tid = threadIdx.x, wid = tid >> 5, lane = tid & 31;
    int wm = wid >> 2, wn = wid & 3;
    int m0 = blockIdx.y * 128, n0 = blockIdx.x * 128;
    int KT = K >> 5;

    wmma::fragment<wmma::accumulator,16,16,8,float> acc[4][2];
#pragma unroll
    for (int i = 0; i < 4; i++)
#pragma unroll
        for (int j = 0; j < 2; j++) wmma::fill_fragment(acc[i][j], 0.f);

    for (int s = 0; s < STAGES-1; s++) { if (s < KT) GEMM_ISSUE(s, s, A, Bm, K, N); cp_commit(); }
    for (int it = 0; it < KT; it++) {
        cp_wait_1(); __syncthreads();
        int pf = it + STAGES - 1;
        if (pf < KT) GEMM_ISSUE(pf, pf % STAGES, A, Bm, K, N);
        cp_commit();
        GEMM_COMPUTE(it % STAGES);
    }
    __syncthreads();

    float* stg = sm + wid * 16 * 20;
#pragma unroll
    for (int i = 0; i < 4; i++)
#pragma unroll
        for (int j = 0; j < 2; j++) {
            wmma::store_matrix_sync(stg, acc[i][j], 20, wmma::mem_row_major);
            __syncwarp();
#pragma unroll
            for (int e = 0; e < 8; e++) {
                int idx = lane * 8 + e;
                int r = idx >> 4, c = idx & 15;
                int m = m0 + wm*64 + i*16 + r;
                int n = n0 + wn*32 + j*16 + c;
                float val = stg[r*20 + c] + bias[n];
                if (EPI == 1) {
                    val = 0.5f * val * (1.0f + erff(val * 0.70710678118654752f));
                    val = tf32r(val);
                }
                C[(size_t)m * N + n] = val;
            }
            __syncwarp();
        }
}

// ---------------- conv-embedding GEMM (gathered A), pipelined ----------------
__global__ void __launch_bounds__(256) conv_gemm_tc2_k(
    const int* __restrict__ tok, const float* __restrict__ conv_b,
    const float* __restrict__ pos)
{
    extern __shared__ float sm[];
    __shared__ int toks[16][128];
    int tid = threadIdx.x, wid = tid >> 5, lane = tid & 31;
    int wm = wid >> 2, wn = wid & 3;
    int m0 = blockIdx.y * 128, n0 = blockIdx.x * 128;
    const int KT = KCONV >> 5;   // 256

    if (tid < 128) {
        int r = m0 + tid;
        int b = r >> 8, nn = r & 255;
        int base = b * LL + nn * PP;
#pragma unroll
        for (int p = 0; p < 16; p++) toks[p][tid] = tok[base + p];
    }
    __syncthreads();

    wmma::fragment<wmma::accumulator,16,16,8,float> acc[4][2];
#pragma unroll
    for (int i = 0; i < 4; i++)
#pragma unroll
        for (int j = 0; j < 2; j++) wmma::fill_fragment(acc[i][j], 0.f);

#define CONV_ISSUE(IT, STG_) do{                                                  \
    float* As_ = sm + (STG_)*STGF; float* Bs_ = As_ + ASZ; int k0_ = (IT) << 5;   \
    int p_ = k0_ >> 9, i0_ = k0_ & 511;                                           \
    _Pragma("unroll") for (int t_ = 0; t_ < 4; t_++) {                            \
        int idx_ = tid + t_*256; int row_ = idx_ >> 3, c4_ = idx_ & 7;            \
        int tk_ = toks[p_][row_];                                                 \
        cp_async16(As_ + row_*36 + c4_*4,                                         \
                   g_embt + (size_t)tk_*DD + i0_ + c4_*4); }                      \
    _Pragma("unroll") for (int t_ = 0; t_ < 4; t_++) {                            \
        int idx_ = tid + t_*256; int row_ = idx_ >> 5, c4_ = idx_ & 31;           \
        cp_async16(Bs_ + row_*132 + c4_*4,                                        \
                   g_Wc + (size_t)(k0_ + row_)*DD + n0 + c4_*4); }                \
} while(0)

    for (int s = 0; s < STAGES-1; s++) { CONV_ISSUE(s, s); cp_commit(); }
    for (int it = 0; it < KT; it++) {
        cp_wait_1(); __syncthreads();
        int pf = it + STAGES - 1;
        if (pf < KT) CONV_ISSUE(pf, pf % STAGES);
        cp_commit();
        GEMM_COMPUTE(it % STAGES);
    }
    __syncthreads();

    float* stg = sm + wid * 16 * 20;
#pragma unroll
    for (int i = 0; i < 4; i++)
#pragma unroll
        for (int j = 0; j < 2; j++) {
            wmma::store_matrix_sync(stg, acc[i][j], 20, wmma::mem_row_major);
            __syncwarp();
#pragma unroll
            for (int e = 0; e < 8; e++) {
                int idx = lane * 8 + e;
                int r = idx >> 4, c = idx & 15;
                int mrow = m0 + wm*64 + i*16 + r;
                int b = mrow >> 8, nn = mrow & 255;
                int s = nn + 1;
                int n = n0 + wn*32 + j*16 + c;
                float val = stg[r*20 + c] + conv_b[n] + pos[(size_t)s*DD + n];
                size_t o = ((size_t)(b*SS + s))*DD + n;
                g_x[o]  = val;
                g_xr[o] = tf32r(val);
            }
            __syncwarp();
        }
}

// ---------------- prologue pack/round kernels ----------------
__global__ void transpose_convw_k(const float* __restrict__ cw) {
    int idx = blockIdx.x * blockDim.x + threadIdx.x;
    if (idx >= KCONV * DD) return;
    int o = idx & 511;
    int k = idx >> 9;
    int i = k & 511;
    int p = k >> 9;
    g_Wc[idx] = tf32r(cw[(size_t)o * 8192 + i * 16 + p]);
}

__global__ void round_k(const float* __restrict__ src, float* __restrict__ dst, int n) {
    int i = blockIdx.x * 256 + threadIdx.x;
    if (i < n) dst[i] = tf32r(src[i]);
}

__global__ void pack_qkv_k(const float* __restrict__ Wq, const float* __restrict__ Wk,
                           const float* __restrict__ Wv, const float* __restrict__ bq,
                           const float* __restrict__ bk, const float* __restrict__ bv) {
    int idx = blockIdx.x * 256 + threadIdx.x;
    if (idx < NLAY * DD * NQKV) {
        int i = idx / (DD * NQKV);
        int rem = idx % (DD * NQKV);
        int k = rem / NQKV, n = rem % NQKV;
        int w = n >> 9, nn = n & 511;
        const float* W = (w == 0) ? Wq : (w == 1) ? Wk : Wv;
        g_Wqkv[idx] = tf32r(W[(size_t)i*DD*DD + (size_t)k*DD + nn]);
    }
    if (idx < NLAY * NQKV) {
        int i = idx / NQKV, n = idx % NQKV;
        int w = n >> 9, nn = n & 511;
        const float* Bv = (w == 0) ? bq : (w == 1) ? bk : bv;
        g_bqkv[idx] = Bv[i*DD + nn];
    }
}

// ---------------- small kernels ----------------
__global__ void lengths_k(const float* __restrict__ mask) {
    __shared__ float sh[256];
    int b = blockIdx.x;
    float s = 0.f;
    for (int i = threadIdx.x; i < LL; i += 256) s += mask[(size_t)b * LL + i];
    sh[threadIdx.x] = s;
    __syncthreads();
    for (int st = 128; st > 0; st >>= 1) {
        if (threadIdx.x < st) sh[threadIdx.x] += sh[threadIdx.x + st];
        __syncthreads();
    }
    if (threadIdx.x == 0) g_len[b] = ceilf((sh[0] + 1.0f) / (float)PP);
}

__global__ void init_cls_k(const float* __restrict__ cls, const float* __restrict__ pos) {
    int idx = blockIdx.x * blockDim.x + threadIdx.x;
    if (idx >= BB * DD) return;
    int b = idx >> 9, d = idx & 511;
    float v = cls[d] + pos[d];
    size_t o = (size_t)b * SS * DD + d;
    g_x[o] = v; g_xr[o] = tf32r(v);
}

__global__ void zero_pad_k() {
    int i = blockIdx.x * blockDim.x + threadIdx.x;
    int n = (TPAD - TT) * DD;
    if (i < n) {
        g_x[(size_t)TT * DD + i] = 0.f;
        g_xr[(size_t)TT * DD + i] = 0.f;
        g_attn[(size_t)TT * DD + i] = 0.f;
    }
}

// rope + elu feature map in place on g_qkv (q at +0, k at +512; k masked)
__global__ void __launch_bounds__(512) rope_feat_k() {
    int t = blockIdx.x;
    int c = threadIdx.x;
    __shared__ float qrow[DD], krow[DD];
    size_t base = (size_t)t * NQKV;
    qrow[c] = g_qkv[base + c];
    krow[c] = g_qkv[base + 512 + c];
    __syncthreads();
    int s = t % SS, b = t / SS;
    int cc = c & 63, j = cc & 31;
    float invf = powf(10000.f, -(float)(2 * j) / 64.f);
    float ang = (float)s * invf;
    float cs = cosf(ang), sn = sinf(ang);
    int partner = (cc < 32) ? c + 32 : c - 32;
    float sgn = (cc < 32) ? -1.f : 1.f;
    float qr = qrow[c] * cs + sgn * qrow[partner] * sn;
    float kr = krow[c] * cs + sgn * krow[partner] * sn;
    float qf = qr > 0.f ? qr + 1.f : expf(qr);
    float kf = kr > 0.f ? kr + 1.f : expf(kr);
    float msk = ((float)s < g_len[b]) ? 1.f : 0.f;
    g_qkv[base + c] = qf;
    g_qkv[base + 512 + c] = kf * msk;
}

// per (b,h): kv[d][m] = sum_s kf*v ; ksum[d] = sum_s kf  (8-step chunks)
__global__ void __launch_bounds__(256) kv2_k() {
    int bh = blockIdx.x;
    int b = bh >> 3, h = bh & 7;
    __shared__ float kf_sh[8][64], v_sh[8][64];
    int tid = threadIdx.x;
    int m = tid & 63, dg = tid >> 6;
    float acc[16];
#pragma unroll
    for (int jj = 0; jj < 16; jj++) acc[jj] = 0.f;
    float ksum = 0.f;
    for (int s0 = 0; s0 < SS; s0 += 8) {
        __syncthreads();
#pragma unroll
        for (int u = 0; u < 4; u++) {
            int idx = tid + u * 256;
            int which = idx >> 9;
            int rr = (idx >> 6) & 7;
            int cc = idx & 63;
            int s = s0 + rr;
            float val = (s < SS)
                ? g_qkv[(size_t)(b*SS + s)*NQKV + (which ? 1024 : 512) + h*64 + cc]
                : 0.f;
            if (which) v_sh[rr][cc] = val; else kf_sh[rr][cc] = val;
        }
        __syncthreads();
#pragma unroll
        for (int r = 0; r < 8; r++) {
            float vr = v_sh[r][m];
#pragma unroll
            for (int jj = 0; jj < 16; jj++) acc[jj] += kf_sh[r][dg*16 + jj] * vr;
        }
        if (tid < 64) {
#pragma unroll
            for (int r = 0; r < 8; r++) ksum += kf_sh[r][tid];
        }
    }
#pragma unroll
    for (int jj = 0; jj < 16; jj++)
        g_kv[((size_t)bh * DHD + dg*16 + jj) * DHD + m] = acc[jj];
    if (tid < 64) g_ksum[bh * DHD + tid] = ksum;
}

// per (b,h): attn = z * qf @ kv   (4-step chunks); stores rounded
__global__ void __launch_bounds__(256) attn2_k() {
    int bh = blockIdx.x;
    int b = bh >> 3, h = bh & 7;
    __shared__ float kvs[DHD * DHD];
    __shared__ float ks[DHD];
    __shared__ float q4[4][64];
    __shared__ float red[4][64];
    __shared__ float part[4][4][64];
    __shared__ float zsh[4];
    int tid = threadIdx.x, wid = tid >> 5, lane = tid & 31;
    int m = tid & 63, dg = tid >> 6;
    for (int i = tid; i < DHD * DHD; i += 256) kvs[i] = g_kv[(size_t)bh * DHD * DHD + i];
    if (tid < 64) ks[tid] = g_ksum[bh * DHD + tid];
    __syncthreads();
    for (int s0 = 0; s0 < SS; s0 += 4) {
        int r = tid >> 6, c = tid & 63;
        int sr = s0 + r;
        q4[r][c] = (sr < SS) ? g_qkv[(size_t)(b*SS + sr)*NQKV + h*64 + c] : 0.f;
        __syncthreads();
        red[r][c] = q4[r][c] * ks[c];
        __syncthreads();
        if (wid < 4) {
            float v = red[wid][lane] + red[wid][lane + 32];
            for (int o = 16; o; o >>= 1) v += __shfl_down_sync(0xffffffffu, v, o);
            if (lane == 0) zsh[wid] = 1.f / (v + 1e-6f);
        }
        float a[4] = {0.f, 0.f, 0.f, 0.f};
#pragma unroll
        for (int jj = 0; jj < 16; jj++) {
            int d = dg*16 + jj;
            float kc = kvs[d * DHD + m];
#pragma unroll
            for (int rr = 0; rr < 4; rr++) a[rr] += q4[rr][d] * kc;
        }
#pragma unroll
        for (int rr = 0; rr < 4; rr++) part[dg][rr][m] = a[rr];
        __syncthreads();
        {
            int rr = tid >> 6, mm = tid & 63;
            int s = s0 + rr;
            if (s < SS) {
                float o = (part[0][rr][mm] + part[1][rr][mm] +
                           part[2][rr][mm] + part[3][rr][mm]) * zsh[rr];
                g_attn[((size_t)(b*SS + s))*DD + h*64 + mm] = tf32r(o);
            }
        }
        __syncthreads();
    }
}

// X = LN(X + Y); writes fp32 X and rounded XR
__global__ void __launch_bounds__(256) ln_k(
    const float* __restrict__ Y, const float* __restrict__ sc,
    const float* __restrict__ bi, float* __restrict__ X, float* __restrict__ XR)
{
    int t = blockIdx.x, tid = threadIdx.x;
    size_t base = (size_t)t * DD;
    float v0 = X[base + tid] + Y[base + tid];
    float v1 = X[base + tid + 256] + Y[base + tid + 256];
    float s = v0 + v1, ss = v0 * v0 + v1 * v1;
    __shared__ float rs[8], rss[8];
    for (int o = 16; o; o >>= 1) {
        s  += __shfl_down_sync(0xffffffffu, s, o);
        ss += __shfl_down_sync(0xffffffffu, ss, o);
    }
    int w = tid >> 5;
    if ((tid & 31) == 0) { rs[w] = s; rss[w] = ss; }
    __syncthreads();
    if (tid == 0) {
        float S1 = 0.f, S2 = 0.f;
        for (int i = 0; i < 8; i++) { S1 += rs[i]; S2 += rss[i]; }
        rs[0] = S1 / (float)DD;
        rss[0] = S2 / (float)DD;
    }
    __syncthreads();
    float mean = rs[0];
    float inv = rsqrtf(rss[0] - mean * mean + 1e-5f);
    float o0 = (v0 - mean) * inv * sc[tid] + bi[tid];
    float o1 = (v1 - mean) * inv * sc[tid + 256] + bi[tid + 256];
    X[base + tid] = o0;        XR[base + tid] = tf32r(o0);
    X[base + tid + 256] = o1;  XR[base + tid + 256] = tf32r(o1);
}

// final LN on token 0 + classifier head
__global__ void __launch_bounds__(256) final_k(
    const float* __restrict__ lnf_s, const float* __restrict__ lnf_b,
    const float* __restrict__ ow, const float* __restrict__ ob,
    float* __restrict__ out)
{
    int b = blockIdx.x, tid = threadIdx.x;
    size_t base = (size_t)b * SS * DD;
    float v0 = g_x[base + tid];
    float v1 = g_x[base + tid + 256];
    float s = v0 + v1, ss = v0 * v0 + v1 * v1;
    __shared__ float rs[8], rss[8];
    __shared__ float row[DD];
    for (int o = 16; o; o >>= 1) {
        s  += __shfl_down_sync(0xffffffffu, s, o);
        ss += __shfl_down_sync(0xffffffffu, ss, o);
    }
    int w = tid >> 5;
    if ((tid & 31) == 0) { rs[w] = s; rss[w] = ss; }
    __syncthreads();
    if (tid == 0) {
        float S1 = 0.f, S2 = 0.f;
        for (int i = 0; i < 8; i++) { S1 += rs[i]; S2 += rss[i]; }
        rs[0] = S1 / (float)DD;
        rss[0] = S2 / (float)DD;
    }
    __syncthreads();
    float mean = rs[0];
    float inv = rsqrtf(rss[0] - mean * mean + 1e-5f);
    row[tid]       = (v0 - mean) * inv * lnf_s[tid] + lnf_b[tid];
    row[tid + 256] = (v1 - mean) * inv * lnf_s[tid + 256] + lnf_b[tid + 256];
    __syncthreads();
    for (int c = 0; c < NCLS; c++) {
        float p = row[tid] * ow[tid * NCLS + c] + row[tid + 256] * ow[(tid + 256) * NCLS + c];
        for (int o = 16; o; o >>= 1) p += __shfl_down_sync(0xffffffffu, p, o);
        if ((tid & 31) == 0) rs[tid >> 5] = p;
        __syncthreads();
        if (tid == 0) {
            float t2 = 0.f;
            for (int i = 0; i < 8; i++) t2 += rs[i];
            out[b * NCLS + c] = t2 + ob[c];
        }
        __syncthreads();
    }
}

// ---------------- host driver ----------------
extern "C" void kernel_launch(void* const* d_in, const int* in_sizes, int n_in,
                              void* d_out, int out_size)
{
    const int*   inputs     = (const int*)  d_in[0];
    const float* input_mask = (const float*)d_in[1];
    const float* emb        = (const float*)d_in[2];
    const float* conv_w     = (const float*)d_in[3];
    const float* conv_b     = (const float*)d_in[4];
    const float* pos        = (const float*)d_in[5];
    const float* cls        = (const float*)d_in[6];
    const float* Wq         = (const float*)d_in[7];
    const float* bq         = (const float*)d_in[8];
    const float* Wk         = (const float*)d_in[9];
    const float* bk         = (const float*)d_in[10];
    const float* Wv         = (const float*)d_in[11];
    const float* bv         = (const float*)d_in[12];
    const float* Wo         = (const float*)d_in[13];
    const float* bo         = (const float*)d_in[14];
    const float* ln1_s      = (const float*)d_in[15];
    const float* ln1_b      = (const float*)d_in[16];
    const float* ln2_s      = (const float*)d_in[17];
    const float* ln2_b      = (const float*)d_in[18];
    const float* W1         = (const float*)d_in[19];
    const float* b1         = (const float*)d_in[20];
    const float* W2         = (const float*)d_in[21];
    const float* b2         = (const float*)d_in[22];
    const float* lnf_s      = (const float*)d_in[23];
    const float* lnf_b      = (const float*)d_in[24];
    const float* out_w      = (const float*)d_in[25];
    const float* out_b      = (const float*)d_in[26];
    float* out = (float*)d_out;

    float *px, *pxr, *pqkv, *pattn, *py, *ph;
    float *pWqkv, *pbqkv, *pWo, *pW1, *pW2, *pembt;
    cudaGetSymbolAddress((void**)&px,    g_x);
    cudaGetSymbolAddress((void**)&pxr,   g_xr);
    cudaGetSymbolAddress((void**)&pqkv,  g_qkv);
    cudaGetSymbolAddress((void**)&pattn, g_attn);
    cudaGetSymbolAddress((void**)&py,    g_y);
    cudaGetSymbolAddress((void**)&ph,    g_h);
    cudaGetSymbolAddress((void**)&pWqkv, g_Wqkv);
    cudaGetSymbolAddress((void**)&pbqkv, g_bqkv);
    cudaGetSymbolAddress((void**)&pWo,   g_Wo);
    cudaGetSymbolAddress((void**)&pW1,   g_W1);
    cudaGetSymbolAddress((void**)&pW2,   g_W2);
    cudaGetSymbolAddress((void**)&pembt, g_embt);

    cudaFuncSetAttribute(gemm_tc2_k<0>, cudaFuncAttributeMaxDynamicSharedMemorySize, SMEMB);
    cudaFuncSetAttribute(gemm_tc2_k<1>, cudaFuncAttributeMaxDynamicSharedMemorySize, SMEMB);
    cudaFuncSetAttribute(conv_gemm_tc2_k, cudaFuncAttributeMaxDynamicSharedMemorySize, SMEMB);

    // prologue: pack / round weights, lengths, padding, cls
    transpose_convw_k<<<(KCONV * DD + 255) / 256, 256>>>(conv_w);
    round_k<<<((int)(32000LL*DD) + 255) / 256, 256>>>(emb, pembt, 32000 * DD);
    pack_qkv_k<<<(NLAY * DD * NQKV + 255) / 256, 256>>>(Wq, Wk, Wv, bq, bk, bv);
    round_k<<<(NLAY * DD * DD + 255) / 256, 256>>>(Wo, pWo, NLAY * DD * DD);
    round_k<<<(NLAY * DD * FFD + 255) / 256, 256>>>(W1, pW1, NLAY * DD * FFD);
    round_k<<<(NLAY * FFD * DD + 255) / 256, 256>>>(W2, pW2, NLAY * FFD * DD);
    lengths_k<<<BB, 256>>>(input_mask);
    zero_pad_k<<<((TPAD - TT) * DD + 255) / 256, 256>>>();
    init_cls_k<<<(BB * DD + 255) / 256, 256>>>(cls, pos);
    conv_gemm_tc2_k<<<dim3(DD / 128, MCONV / 128), 256, SMEMB>>>(inputs, conv_b, pos);

    dim3 gQKV(NQKV / 128, TPAD / 128);  // (12, 65)
    dim3 gD(DD / 128, TPAD / 128);      // (4, 65)
    dim3 gF(FFD / 128, TPAD / 128);     // (16, 65)

    for (int i = 0; i < NLAY; i++) {
        gemm_tc2_k<0><<<gQKV, 256, SMEMB>>>(pxr, pWqkv + (size_t)i*DD*NQKV,
                                            pbqkv + (size_t)i*NQKV, pqkv, NQKV, DD);
        rope_feat_k<<<TT, 512>>>();
        kv2_k<<<BB * HH, 256>>>();
        attn2_k<<<BB * HH, 256>>>();
        gemm_tc2_k<0><<<gD, 256, SMEMB>>>(pattn, pWo + (size_t)i*DD*DD,
                                          bo + (size_t)i*DD, py, DD, DD);
        ln_k<<<TPAD, 256>>>(py, ln1_s + (size_t)i*DD, ln1_b + (size_t)i*DD, px, pxr);
        gemm_tc2_k<1><<<gF, 256, SMEMB>>>(pxr, pW1 + (size_t)i*DD*FFD,
                                          b1 + (size_t)i*FFD, ph, FFD, DD);
        gemm_tc2_k<0><<<gD, 256, SMEMB>>>(ph, pW2 + (size_t)i*FFD*DD,
                                          b2 + (size_t)i*DD, py, DD, FFD);
        ln_k<<<TPAD, 256>>>(py, ln2_s + (size_t)i*DD, ln2_b + (size_t)i*DD, px, pxr);
    }

    final_k<<<BB, 256>>>(lnf_s, lnf_b, out_w, out_b, out);
}

// round 7
// speedup vs baseline: 2.1244x; 1.4397x over previous
#include <cuda_runtime.h>
#include <cuda_fp16.h>
#include <mma.h>
#include <math.h>
#include <stdint.h>

using namespace nvcuda;

#define BB   32
#define LL   4096
#define PP   16
#define SS   257
#define DD   512
#define HH   8
#define DHD  64
#define NLAY 8
#define FFD  2048
#define NCLS 4
#define TT   (BB*SS)      /* 8224 */
#define TPAD 8320         /* 65*128 */
#define KCONV 8192
#define MCONV 8192
#define NQKV 1536

// ---------------- scratch (device globals; no allocations) ----------------
__device__ float  g_x[TPAD*DD];
__device__ __half g_xh[TPAD*DD];             // fp16 copy of x (GEMM A)
__device__ float  g_qkv[(size_t)TPAD*NQKV];
__device__ __half g_attn[TPAD*DD];           // fp16 (GEMM A)
__device__ float  g_y[TPAD*DD];
__device__ __half g_h[(size_t)TPAD*FFD];     // fp16 post-GELU (GEMM A)
__device__ float  g_kv[BB*HH*DHD*DHD];
__device__ float  g_ksum[BB*HH*DHD];
__device__ float  g_len[BB];
__device__ float  g_cs[SS*32*2];             // rope cos/sin table
// packed fp16 weights ([N][K], K-major)
__device__ __half g_Wc[(size_t)DD*KCONV];
__device__ __half g_embt[(size_t)32000*DD];
__device__ __half g_Wqkv[(size_t)NLAY*NQKV*DD];
__device__ float  g_bqkv[NLAY*NQKV];
__device__ __half g_Wot[(size_t)NLAY*DD*DD];
__device__ __half g_W1t[(size_t)NLAY*FFD*DD];
__device__ __half g_W2t[(size_t)NLAY*DD*FFD];

// ---------------- helpers ----------------
__device__ __forceinline__ void cpa16(const __half* dst_smem, const __half* src) {
    uint32_t d = (uint32_t)__cvta_generic_to_shared(dst_smem);
    asm volatile("cp.async.cg.shared.global [%0], [%1], 16;" :: "r"(d), "l"(src) : "memory");
}
#define CP_COMMIT() asm volatile("cp.async.commit_group;" ::: "memory")
#define CP_WAIT1()  asm volatile("cp.async.wait_group 1;" ::: "memory")

// ================= fp16 wmma GEMM, 3-stage cp.async =================
// C[M,N] = A[M,K]@Bt[N,K]^T + bias (+gelu->half).  BM=BN=128, BK=16.
// 8 warps (2x4), warp tile 64x32.  SMEM rows padded to 24 halves (48B).
#define TLD   24
#define TSTG  (128*TLD)            /* halves per tile */
#define STGB  (2*TSTG*2)           /* bytes per stage: A+B = 12288 */

template<int EPI>   // 0: float out + bias    1: half out + bias + gelu
__global__ void __launch_bounds__(256) hgemm_k(
    const __half* __restrict__ A, const __half* __restrict__ Bt,
    const float* __restrict__ bias, void* __restrict__ Cv,
    int N, int K)
{
    __shared__ __align__(16) char sbuf[3*STGB];
    int tid = threadIdx.x, wid = tid >> 5, lane = tid & 31;
    int wm = wid >> 2, wn = wid & 3;
    int m0 = blockIdx.y * 128, n0 = blockIdx.x * 128;
    int KT = K >> 4;

    wmma::fragment<wmma::accumulator,16,16,16,float> acc[4][2];
#pragma unroll
    for (int i = 0; i < 4; i++)
#pragma unroll
        for (int j = 0; j < 2; j++) wmma::fill_fragment(acc[i][j], 0.f);

    int lrow = tid >> 1, lc = (tid & 1) * 8;

#define HG_ISSUE(CH, ST) do {                                                   \
    __half* As_ = (__half*)(sbuf + (ST)*STGB);                                  \
    __half* Bs_ = As_ + TSTG;                                                   \
    int k0_ = (CH) << 4;                                                        \
    cpa16(As_ + lrow*TLD + lc, A  + (size_t)(m0 + lrow)*K + k0_ + lc);          \
    cpa16(Bs_ + lrow*TLD + lc, Bt + (size_t)(n0 + lrow)*K + k0_ + lc);          \
} while (0)

#define HG_COMP(ST) do {                                                        \
    const __half* As_ = (const __half*)(sbuf + (ST)*STGB);                      \
    const __half* Bs_ = As_ + TSTG;                                             \
    wmma::fragment<wmma::matrix_a,16,16,16,__half,wmma::row_major> af[4];       \
    wmma::fragment<wmma::matrix_b,16,16,16,__half,wmma::col_major> bf[2];       \
    _Pragma("unroll") for (int i = 0; i < 4; i++)                               \
        wmma::load_matrix_sync(af[i], As_ + (wm*64 + i*16)*TLD, TLD);           \
    _Pragma("unroll") for (int j = 0; j < 2; j++)                               \
        wmma::load_matrix_sync(bf[j], Bs_ + (wn*32 + j*16)*TLD, TLD);           \
    _Pragma("unroll") for (int i = 0; i < 4; i++)                               \
        _Pragma("unroll") for (int j = 0; j < 2; j++)                           \
            wmma::mma_sync(acc[i][j], af[i], bf[j], acc[i][j]);                 \
} while (0)

    for (int s = 0; s < 2; s++) { if (s < KT) HG_ISSUE(s, s); CP_COMMIT(); }
    for (int c = 0; c < KT; c++) {
        CP_WAIT1();
        __syncthreads();
        if (c + 2 < KT) HG_ISSUE(c + 2, (c + 2) % 3);
        CP_COMMIT();
        HG_COMP(c % 3);
    }
    __syncthreads();

    float* stg = (float*)sbuf + wid * 16 * 20;
#pragma unroll
    for (int i = 0; i < 4; i++)
#pragma unroll
        for (int j = 0; j < 2; j++) {
            wmma::store_matrix_sync(stg, acc[i][j], 20, wmma::mem_row_major);
            __syncwarp();
#pragma unroll
            for (int e = 0; e < 8; e++) {
                int idx = lane * 8 + e;
                int r = idx >> 4, cc = idx & 15;
                int m = m0 + wm*64 + i*16 + r;
                int n = n0 + wn*32 + j*16 + cc;
                float val = stg[r*20 + cc] + bias[n];
                if (EPI == 1) {
                    val = 0.5f * val * (1.0f + erff(val * 0.70710678118654752f));
                    ((__half*)Cv)[(size_t)m * N + n] = __float2half_rn(val);
                } else {
                    ((float*)Cv)[(size_t)m * N + n] = val;
                }
            }
            __syncwarp();
        }
}

// ---------------- conv-embedding GEMM (gathered A rows), fp16 ----------------
__global__ void __launch_bounds__(256) conv_hgemm_k(
    const int* __restrict__ tok, const float* __restrict__ conv_b,
    const float* __restrict__ pos)
{
    __shared__ __align__(16) char sbuf[3*STGB];
    __shared__ int toks[16][128];
    int tid = threadIdx.x, wid = tid >> 5, lane = tid & 31;
    int wm = wid >> 2, wn = wid & 3;
    int m0 = blockIdx.y * 128, n0 = blockIdx.x * 128;
    const int KT = KCONV >> 4;   // 512

    if (tid < 128) {
        int r = m0 + tid;
        int b = r >> 8, nn = r & 255;
        int base = b * LL + nn * PP;
#pragma unroll
        for (int p = 0; p < 16; p++) toks[p][tid] = tok[base + p];
    }
    __syncthreads();

    wmma::fragment<wmma::accumulator,16,16,16,float> acc[4][2];
#pragma unroll
    for (int i = 0; i < 4; i++)
#pragma unroll
        for (int j = 0; j < 2; j++) wmma::fill_fragment(acc[i][j], 0.f);

    int lrow = tid >> 1, lc = (tid & 1) * 8;

#define CV_ISSUE(CH, ST) do {                                                   \
    __half* As_ = (__half*)(sbuf + (ST)*STGB);                                  \
    __half* Bs_ = As_ + TSTG;                                                   \
    int k0_ = (CH) << 4; int p_ = k0_ >> 9, i0_ = k0_ & 511;                    \
    int tk_ = toks[p_][lrow];                                                   \
    cpa16(As_ + lrow*TLD + lc, g_embt + (size_t)tk_*DD + i0_ + lc);             \
    cpa16(Bs_ + lrow*TLD + lc, g_Wc + (size_t)(n0 + lrow)*KCONV + k0_ + lc);    \
} while (0)

    for (int s = 0; s < 2; s++) { CV_ISSUE(s, s); CP_COMMIT(); }
    for (int c = 0; c < KT; c++) {
        CP_WAIT1();
        __syncthreads();
        if (c + 2 < KT) CV_ISSUE(c + 2, (c + 2) % 3);
        CP_COMMIT();
        HG_COMP(c % 3);
    }
    __syncthreads();

    float* stg = (float*)sbuf + wid * 16 * 20;
#pragma unroll
    for (int i = 0; i < 4; i++)
#pragma unroll
        for (int j = 0; j < 2; j++) {
            wmma::store_matrix_sync(stg, acc[i][j], 20, wmma::mem_row_major);
            __syncwarp();
#pragma unroll
            for (int e = 0; e < 8; e++) {
                int idx = lane * 8 + e;
                int r = idx >> 4, cc = idx & 15;
                int mrow = m0 + wm*64 + i*16 + r;
                int b = mrow >> 8, nn = mrow & 255;
                int s = nn + 1;
                int n = n0 + wn*32 + j*16 + cc;
                float val = stg[r*20 + cc] + conv_b[n] + pos[(size_t)s*DD + n];
                size_t o = ((size_t)(b*SS + s))*DD + n;
                g_x[o]  = val;
                g_xh[o] = __float2half_rn(val);
            }
            __syncwarp();
        }
}

// ---------------- prologue pack kernels ----------------
__global__ void half_k(const float* __restrict__ src, __half* __restrict__ dst, int n) {
    int i = blockIdx.x * 256 + threadIdx.x;
    if (i < n) dst[i] = __float2half_rn(src[i]);
}

// dst[i][n][k] = half(src[i][k][n])
__global__ void pack_t_k(const float* __restrict__ src, __half* __restrict__ dst,
                         int K, int N) {
    size_t idx = (size_t)blockIdx.x * 256 + threadIdx.x;
    size_t per = (size_t)K * N;
    if (idx >= (size_t)NLAY * per) return;
    int i = (int)(idx / per);
    size_t rem = idx % per;
    int n = (int)(rem / K), k = (int)(rem % K);
    dst[idx] = __float2half_rn(src[(size_t)i * per + (size_t)k * N + n]);
}

__global__ void pack_qkv_k(const float* __restrict__ Wq, const float* __restrict__ Wk,
                           const float* __restrict__ Wv, const float* __restrict__ bq,
                           const float* __restrict__ bk, const float* __restrict__ bv) {
    size_t idx = (size_t)blockIdx.x * 256 + threadIdx.x;
    if (idx < (size_t)NLAY * NQKV * DD) {
        int i = (int)(idx / (NQKV * DD));
        int rem = (int)(idx % (NQKV * DD));
        int n = rem / DD, k = rem % DD;
        int w = n >> 9, nn = n & 511;
        const float* W = (w == 0) ? Wq : (w == 1) ? Wk : Wv;
        g_Wqkv[idx] = __float2half_rn(W[((size_t)i * DD + k) * DD + nn]);
    }
    if (idx < NLAY * NQKV) {
        int i = (int)(idx / NQKV), n = (int)(idx % NQKV);
        int w = n >> 9, nn = n & 511;
        const float* Bv = (w == 0) ? bq : (w == 1) ? bk : bv;
        g_bqkv[idx] = Bv[i * DD + nn];
    }
}

// g_Wc[o][p*512+i] = conv_w[o][i][p]
__global__ void pack_convw_k(const float* __restrict__ cw) {
    size_t idx = (size_t)blockIdx.x * 256 + threadIdx.x;
    if (idx >= (size_t)DD * KCONV) return;
    int o = (int)(idx >> 13);
    int k = (int)(idx & 8191);
    int i = k & 511, p = k >> 9;
    g_Wc[idx] = __float2half_rn(cw[((size_t)o * DD + i) * PP + p]);
}

__global__ void rope_tab_k() {
    int idx = blockIdx.x * 256 + threadIdx.x;
    if (idx >= SS * 32) return;
    int s = idx >> 5, j = idx & 31;
    float ang = (float)s * exp2f(-(float)j * (13.287712379549449f / 32.f));
    g_cs[idx * 2]     = cosf(ang);
    g_cs[idx * 2 + 1] = sinf(ang);
}

// ---------------- small kernels ----------------
__global__ void lengths_k(const float* __restrict__ mask) {
    __shared__ float sh[256];
    int b = blockIdx.x;
    float s = 0.f;
    for (int i = threadIdx.x; i < LL; i += 256) s += mask[(size_t)b * LL + i];
    sh[threadIdx.x] = s;
    __syncthreads();
    for (int st = 128; st > 0; st >>= 1) {
        if (threadIdx.x < st) sh[threadIdx.x] += sh[threadIdx.x + st];
        __syncthreads();
    }
    if (threadIdx.x == 0) g_len[b] = ceilf((sh[0] + 1.0f) / (float)PP);
}

__global__ void init_cls_k(const float* __restrict__ cls, const float* __restrict__ pos) {
    int idx = blockIdx.x * blockDim.x + threadIdx.x;
    if (idx >= BB * DD) return;
    int b = idx >> 9, d = idx & 511;
    float v = cls[d] + pos[d];
    size_t o = (size_t)b * SS * DD + d;
    g_x[o] = v; g_xh[o] = __float2half_rn(v);
}

__global__ void zero_pad_k() {
    int i = blockIdx.x * blockDim.x + threadIdx.x;
    int n = (TPAD - TT) * DD;
    if (i < n) {
        g_x[(size_t)TT * DD + i] = 0.f;
        g_xh[(size_t)TT * DD + i] = __float2half_rn(0.f);
        g_attn[(size_t)TT * DD + i] = __float2half_rn(0.f);
    }
}

// rope + elu feature map in place on g_qkv (q at +0, k at +512; k masked)
__global__ void __launch_bounds__(512) rope_feat_k() {
    int t = blockIdx.x;
    int c = threadIdx.x;
    __shared__ float qrow[DD], krow[DD];
    size_t base = (size_t)t * NQKV;
    qrow[c] = g_qkv[base + c];
    krow[c] = g_qkv[base + 512 + c];
    __syncthreads();
    int s = t % SS, b = t / SS;
    int cc = c & 63, j = cc & 31;
    float cs = g_cs[(s * 32 + j) * 2];
    float sn = g_cs[(s * 32 + j) * 2 + 1];
    int partner = (cc < 32) ? c + 32 : c - 32;
    float sgn = (cc < 32) ? -1.f : 1.f;
    float qr = qrow[c] * cs + sgn * qrow[partner] * sn;
    float kr = krow[c] * cs + sgn * krow[partner] * sn;
    float qf = qr > 0.f ? qr + 1.f : expf(qr);
    float kf = kr > 0.f ? kr + 1.f : expf(kr);
    float msk = ((float)s < g_len[b]) ? 1.f : 0.f;
    g_qkv[base + c] = qf;
    g_qkv[base + 512 + c] = kf * msk;
}

// per (b,h): kv[d][m] = sum_s kf*v ; ksum[d] = sum_s kf  (8-step chunks)
__global__ void __launch_bounds__(256) kv2_k() {
    int bh = blockIdx.x;
    int b = bh >> 3, h = bh & 7;
    __shared__ float kf_sh[8][64], v_sh[8][64];
    int tid = threadIdx.x;
    int m = tid & 63, dg = tid >> 6;
    float acc[16];
#pragma unroll
    for (int jj = 0; jj < 16; jj++) acc[jj] = 0.f;
    float ksum = 0.f;
    for (int s0 = 0; s0 < SS; s0 += 8) {
        __syncthreads();
#pragma unroll
        for (int u = 0; u < 4; u++) {
            int idx = tid + u * 256;
            int which = idx >> 9;
            int rr = (idx >> 6) & 7;
            int cc = idx & 63;
            int s = s0 + rr;
            float val = (s < SS)
                ? g_qkv[(size_t)(b*SS + s)*NQKV + (which ? 1024 : 512) + h*64 + cc]
                : 0.f;
            if (which) v_sh[rr][cc] = val; else kf_sh[rr][cc] = val;
        }
        __syncthreads();
#pragma unroll
        for (int r = 0; r < 8; r++) {
            float vr = v_sh[r][m];
#pragma unroll
            for (int jj = 0; jj < 16; jj++) acc[jj] += kf_sh[r][dg*16 + jj] * vr;
        }
        if (tid < 64) {
#pragma unroll
            for (int r = 0; r < 8; r++) ksum += kf_sh[r][tid];
        }
    }
#pragma unroll
    for (int jj = 0; jj < 16; jj++)
        g_kv[((size_t)bh * DHD + dg*16 + jj) * DHD + m] = acc[jj];
    if (tid < 64) g_ksum[bh * DHD + tid] = ksum;
}

// per (b,h): attn = z * qf @ kv (4-step chunks); stores fp16
__global__ void __launch_bounds__(256) attn2_k() {
    int bh = blockIdx.x;
    int b = bh >> 3, h = bh & 7;
    __shared__ float kvs[DHD * DHD];
    __shared__ float ks[DHD];
    __shared__ float q4[4][64];
    __shared__ float red[4][64];
    __shared__ float part[4][4][64];
    __shared__ float zsh[4];
    int tid = threadIdx.x, wid = tid >> 5, lane = tid & 31;
    int m = tid & 63, dg = tid >> 6;
    for (int i = tid; i < DHD * DHD; i += 256) kvs[i] = g_kv[(size_t)bh * DHD * DHD + i];
    if (tid < 64) ks[tid] = g_ksum[bh * DHD + tid];
    __syncthreads();
    for (int s0 = 0; s0 < SS; s0 += 4) {
        int r = tid >> 6, c = tid & 63;
        int sr = s0 + r;
        q4[r][c] = (sr < SS) ? g_qkv[(size_t)(b*SS + sr)*NQKV + h*64 + c] : 0.f;
        __syncthreads();
        red[r][c] = q4[r][c] * ks[c];
        __syncthreads();
        if (wid < 4) {
            float v = red[wid][lane] + red[wid][lane + 32];
            for (int o = 16; o; o >>= 1) v += __shfl_down_sync(0xffffffffu, v, o);
            if (lane == 0) zsh[wid] = 1.f / (v + 1e-6f);
        }
        float a[4] = {0.f, 0.f, 0.f, 0.f};
#pragma unroll
        for (int jj = 0; jj < 16; jj++) {
            int d = dg*16 + jj;
            float kc = kvs[d * DHD + m];
#pragma unroll
            for (int rr = 0; rr < 4; rr++) a[rr] += q4[rr][d] * kc;
        }
#pragma unroll
        for (int rr = 0; rr < 4; rr++) part[dg][rr][m] = a[rr];
        __syncthreads();
        {
            int rr = tid >> 6, mm = tid & 63;
            int s = s0 + rr;
            if (s < SS) {
                float o = (part[0][rr][mm] + part[1][rr][mm] +
                           part[2][rr][mm] + part[3][rr][mm]) * zsh[rr];
                g_attn[((size_t)(b*SS + s))*DD + h*64 + mm] = __float2half_rn(o);
            }
        }
        __syncthreads();
    }
}

// X = LN(X + Y); writes fp32 X and fp16 XH
__global__ void __launch_bounds__(256) ln_k(
    const float* __restrict__ Y, const float* __restrict__ sc,
    const float* __restrict__ bi, float* __restrict__ X, __half* __restrict__ XH)
{
    int t = blockIdx.x, tid = threadIdx.x;
    size_t base = (size_t)t * DD;
    float v0 = X[base + tid] + Y[base + tid];
    float v1 = X[base + tid + 256] + Y[base + tid + 256];
    float s = v0 + v1, ss = v0 * v0 + v1 * v1;
    __shared__ float rs[8], rss[8];
    for (int o = 16; o; o >>= 1) {
        s  += __shfl_down_sync(0xffffffffu, s, o);
        ss += __shfl_down_sync(0xffffffffu, ss, o);
    }
    int w = tid >> 5;
    if ((tid & 31) == 0) { rs[w] = s; rss[w] = ss; }
    __syncthreads();
    if (tid == 0) {
        float S1 = 0.f, S2 = 0.f;
        for (int i = 0; i < 8; i++) { S1 += rs[i]; S2 += rss[i]; }
        rs[0] = S1 / (float)DD;
        rss[0] = S2 / (float)DD;
    }
    __syncthreads();
    float mean = rs[0];
    float inv = rsqrtf(rss[0] - mean * mean + 1e-5f);
    float o0 = (v0 - mean) * inv * sc[tid] + bi[tid];
    float o1 = (v1 - mean) * inv * sc[tid + 256] + bi[tid + 256];
    X[base + tid] = o0;        XH[base + tid] = __float2half_rn(o0);
    X[base + tid + 256] = o1;  XH[base + tid + 256] = __float2half_rn(o1);
}

// final LN on token 0 + classifier head
__global__ void __launch_bounds__(256) final_k(
    const float* __restrict__ lnf_s, const float* __restrict__ lnf_b,
    const float* __restrict__ ow, const float* __restrict__ ob,
    float* __restrict__ out)
{
    int b = blockIdx.x, tid = threadIdx.x;
    size_t base = (size_t)b * SS * DD;
    float v0 = g_x[base + tid];
    float v1 = g_x[base + tid + 256];
    float s = v0 + v1, ss = v0 * v0 + v1 * v1;
    __shared__ float rs[8], rss[8];
    __shared__ float row[DD];
    for (int o = 16; o; o >>= 1) {
        s  += __shfl_down_sync(0xffffffffu, s, o);
        ss += __shfl_down_sync(0xffffffffu, ss, o);
    }
    int w = tid >> 5;
    if ((tid & 31) == 0) { rs[w] = s; rss[w] = ss; }
    __syncthreads();
    if (tid == 0) {
        float S1 = 0.f, S2 = 0.f;
        for (int i = 0; i < 8; i++) { S1 += rs[i]; S2 += rss[i]; }
        rs[0] = S1 / (float)DD;
        rss[0] = S2 / (float)DD;
    }
    __syncthreads();
    float mean = rs[0];
    float inv = rsqrtf(rss[0] - mean * mean + 1e-5f);
    row[tid]       = (v0 - mean) * inv * lnf_s[tid] + lnf_b[tid];
    row[tid + 256] = (v1 - mean) * inv * lnf_s[tid + 256] + lnf_b[tid + 256];
    __syncthreads();
    for (int c = 0; c < NCLS; c++) {
        float p = row[tid] * ow[tid * NCLS + c] + row[tid + 256] * ow[(tid + 256) * NCLS + c];
        for (int o = 16; o; o >>= 1) p += __shfl_down_sync(0xffffffffu, p, o);
        if ((tid & 31) == 0) rs[tid >> 5] = p;
        __syncthreads();
        if (tid == 0) {
            float t2 = 0.f;
            for (int i = 0; i < 8; i++) t2 += rs[i];
            out[b * NCLS + c] = t2 + ob[c];
        }
        __syncthreads();
    }
}

// ---------------- host driver ----------------
extern "C" void kernel_launch(void* const* d_in, const int* in_sizes, int n_in,
                              void* d_out, int out_size)
{
    const int*   inputs     = (const int*)  d_in[0];
    const float* input_mask = (const float*)d_in[1];
    const float* emb        = (const float*)d_in[2];
    const float* conv_w     = (const float*)d_in[3];
    const float* conv_b     = (const float*)d_in[4];
    const float* pos        = (const float*)d_in[5];
    const float* cls        = (const float*)d_in[6];
    const float* Wq         = (const float*)d_in[7];
    const float* bq         = (const float*)d_in[8];
    const float* Wk         = (const float*)d_in[9];
    const float* bk         = (const float*)d_in[10];
    const float* Wv         = (const float*)d_in[11];
    const float* bv         = (const float*)d_in[12];
    const float* Wo         = (const float*)d_in[13];
    const float* bo         = (const float*)d_in[14];
    const float* ln1_s      = (const float*)d_in[15];
    const float* ln1_b      = (const float*)d_in[16];
    const float* ln2_s      = (const float*)d_in[17];
    const float* ln2_b      = (const float*)d_in[18];
    const float* W1         = (const float*)d_in[19];
    const float* b1         = (const float*)d_in[20];
    const float* W2         = (const float*)d_in[21];
    const float* b2         = (const float*)d_in[22];
    const float* lnf_s      = (const float*)d_in[23];
    const float* lnf_b      = (const float*)d_in[24];
    const float* out_w      = (const float*)d_in[25];
    const float* out_b      = (const float*)d_in[26];
    float* out = (float*)d_out;

    float  *px, *pqkv, *py;
    __half *pxh, *pattn, *ph, *pWqkv, *pWot, *pW1t, *pW2t, *pembt;
    float  *pbqkv;
    cudaGetSymbolAddress((void**)&px,    g_x);
    cudaGetSymbolAddress((void**)&pxh,   g_xh);
    cudaGetSymbolAddress((void**)&pqkv,  g_qkv);
    cudaGetSymbolAddress((void**)&pattn, g_attn);
    cudaGetSymbolAddress((void**)&py,    g_y);
    cudaGetSymbolAddress((void**)&ph,    g_h);
    cudaGetSymbolAddress((void**)&pWqkv, g_Wqkv);
    cudaGetSymbolAddress((void**)&pbqkv, g_bqkv);
    cudaGetSymbolAddress((void**)&pWot,  g_Wot);
    cudaGetSymbolAddress((void**)&pW1t,  g_W1t);
    cudaGetSymbolAddress((void**)&pW2t,  g_W2t);
    cudaGetSymbolAddress((void**)&pembt, g_embt);

    // prologue: pack weights to fp16 [N][K], tables, padding
    pack_convw_k<<<(int)(((size_t)DD*KCONV + 255) / 256), 256>>>(conv_w);
    half_k<<<(32000 * DD + 255) / 256, 256>>>(emb, pembt, 32000 * DD);
    pack_qkv_k<<<(NLAY * NQKV * DD + 255) / 256, 256>>>(Wq, Wk, Wv, bq, bk, bv);
    pack_t_k<<<(NLAY * DD * DD + 255) / 256, 256>>>(Wo, pWot, DD, DD);
    pack_t_k<<<(NLAY * DD * FFD + 255) / 256, 256>>>(W1, pW1t, DD, FFD);
    pack_t_k<<<(NLAY * FFD * DD + 255) / 256, 256>>>(W2, pW2t, FFD, DD);
    rope_tab_k<<<(SS * 32 + 255) / 256, 256>>>();
    lengths_k<<<BB, 256>>>(input_mask);
    zero_pad_k<<<((TPAD - TT) * DD + 255) / 256, 256>>>();
    init_cls_k<<<(BB * DD + 255) / 256, 256>>>(cls, pos);
    conv_hgemm_k<<<dim3(DD / 128, MCONV / 128), 256>>>(inputs, conv_b, pos);

    dim3 gQKV(NQKV / 128, TPAD / 128);  // (12, 65)
    dim3 gD(DD / 128, TPAD / 128);      // (4, 65)
    dim3 gF(FFD / 128, TPAD / 128);     // (16, 65)

    for (int i = 0; i < NLAY; i++) {
        hgemm_k<0><<<gQKV, 256>>>(pxh, pWqkv + (size_t)i*NQKV*DD,
                                  pbqkv + (size_t)i*NQKV, pqkv, NQKV, DD);
        rope_feat_k<<<TT, 512>>>();
        kv2_k<<<BB * HH, 256>>>();
        attn2_k<<<BB * HH, 256>>>();
        hgemm_k<0><<<gD, 256>>>(pattn, pWot + (size_t)i*DD*DD,
                                bo + (size_t)i*DD, py, DD, DD);
        ln_k<<<TPAD, 256>>>(py, ln1_s + (size_t)i*DD, ln1_b + (size_t)i*DD, px, pxh);
        hgemm_k<1><<<gF, 256>>>(pxh, pW1t + (size_t)i*FFD*DD,
                                b1 + (size_t)i*FFD, ph, FFD, DD);
        hgemm_k<0><<<gD, 256>>>(ph, pW2t + (size_t)i*DD*FFD,
                                b2 + (size_t)i*DD, py, DD, FFD);
        ln_k<<<TPAD, 256>>>(py, ln2_s + (size_t)i*DD, ln2_b + (size_t)i*DD, px, pxh);
    }

    final_k<<<BB, 256>>>(lnf_s, lnf_b, out_w, out_b, out);
}

// round 9
// speedup vs baseline: 3.3389x; 1.5717x over previous
#include <cuda_runtime.h>
#include <cuda_fp16.h>
#include <mma.h>
#include <math.h>
#include <stdint.h>

using namespace nvcuda;

#define BB   32
#define LL   4096
#define PP   16
#define SS   257
#define DD   512
#define HH   8
#define DHD  64
#define NLAY 8
#define FFD  2048
#define NCLS 4
#define TT   (BB*SS)      /* 8224 */
#define TPAD 8320         /* 65*128 */
#define KCONV 8192
#define MCONV 8192
#define NQKV 1536

// ---------------- scratch (device globals; no allocations) ----------------
__device__ float  g_x[TPAD*DD];
__device__ __half g_xh[TPAD*DD];             // fp16 copy of x (GEMM A)
__device__ float  g_qkv[(size_t)TPAD*NQKV];
__device__ __half g_attn[TPAD*DD];           // fp16 (GEMM A)
__device__ float  g_y[TPAD*DD];
__device__ __half g_h[(size_t)TPAD*FFD];     // fp16 post-GELU (GEMM A)
__device__ float  g_kv[BB*HH*DHD*DHD];
__device__ float  g_ksum[BB*HH*DHD];
__device__ float  g_len[BB];
__device__ float  g_cs[SS*32*2];             // rope cos/sin table
// packed fp16 weights ([N][K], K-major)
__device__ __half g_Wc[(size_t)DD*KCONV];
__device__ __half g_embt[(size_t)32000*DD];
__device__ __half g_Wqkv[(size_t)NLAY*NQKV*DD];
__device__ float  g_bqkv[NLAY*NQKV];
__device__ __half g_Wot[(size_t)NLAY*DD*DD];
__device__ __half g_W1t[(size_t)NLAY*FFD*DD];
__device__ __half g_W2t[(size_t)NLAY*DD*FFD];

// ---------------- helpers ----------------
__device__ __forceinline__ void cpa16(const __half* dst_smem, const __half* src) {
    uint32_t d = (uint32_t)__cvta_generic_to_shared(dst_smem);
    asm volatile("cp.async.cg.shared.global [%0], [%1], 16;" :: "r"(d), "l"(src) : "memory");
}
#define CP_COMMIT() asm volatile("cp.async.commit_group;" ::: "memory")
#define CP_WAIT1()  asm volatile("cp.async.wait_group 1;" ::: "memory")

// ================= fp16 wmma GEMM, tile 128x256, BK=32, 3-stage =================
// C[M,N] = A[M,K]@Bt[N,K]^T + bias (+gelu->half). 8 warps (2x4), warp tile 64x64.
// SMEM rows padded to 40 halves (80B) -> LDSM conflict-free.
#define ALD   40
#define ASTG  (128*ALD)                 /* halves: A tile  */
#define BSTG  (256*ALD)                 /* halves: B tile  */
#define STGH  (ASTG+BSTG)               /* halves per stage */
#define STGB  (STGH*2)                  /* bytes per stage = 30720 */
#define SMEMH (3*STGB)                  /* 92160 bytes */

#define HG2_ISSUE(CH, ST, APTR, BPTR, KDIM) do {                                  \
    __half* As_ = (__half*)(sbuf + (ST)*STGB);                                    \
    __half* Bs_ = As_ + ASTG;                                                     \
    int k0_ = (CH) << 5;                                                          \
    _Pragma("unroll") for (int t_ = 0; t_ < 2; t_++) {                            \
        int idx_ = tid + t_*256; int row_ = idx_ >> 2, c_ = (idx_ & 3) * 8;       \
        cpa16(As_ + row_*ALD + c_, (APTR) + (size_t)(m0 + row_)*(KDIM) + k0_ + c_); } \
    _Pragma("unroll") for (int t_ = 0; t_ < 4; t_++) {                            \
        int idx_ = tid + t_*256; int row_ = idx_ >> 2, c_ = (idx_ & 3) * 8;       \
        cpa16(Bs_ + row_*ALD + c_, (BPTR) + (size_t)(n0 + row_)*(KDIM) + k0_ + c_); } \
} while (0)

#define HG2_COMP(ST) do {                                                         \
    const __half* As_ = (const __half*)(sbuf + (ST)*STGB);                        \
    const __half* Bs_ = As_ + ASTG;                                               \
    _Pragma("unroll") for (int kk = 0; kk < 2; kk++) {                            \
        wmma::fragment<wmma::matrix_a,16,16,16,__half,wmma::row_major> af[4];     \
        wmma::fragment<wmma::matrix_b,16,16,16,__half,wmma::col_major> bf[4];     \
        _Pragma("unroll") for (int i = 0; i < 4; i++)                             \
            wmma::load_matrix_sync(af[i], As_ + (wm*64 + i*16)*ALD + kk*16, ALD); \
        _Pragma("unroll") for (int j = 0; j < 4; j++)                             \
            wmma::load_matrix_sync(bf[j], Bs_ + (wn*64 + j*16)*ALD + kk*16, ALD); \
        _Pragma("unroll") for (int i = 0; i < 4; i++)                             \
            _Pragma("unroll") for (int j = 0; j < 4; j++)                         \
                wmma::mma_sync(acc[i][j], af[i], bf[j], acc[i][j]);               \
    }                                                                             \
} while (0)

template<int EPI>   // 0: float out + bias    1: half out + bias + gelu
__global__ void __launch_bounds__(256) hgemm2_k(
    const __half* __restrict__ A, const __half* __restrict__ Bt,
    const float* __restrict__ bias, void* __restrict__ Cv,
    int N, int K)
{
    extern __shared__ char sbuf[];
    int tid = threadIdx.x, wid = tid >> 5, lane = tid & 31;
    int wm = wid >> 2, wn = wid & 3;
    int m0 = blockIdx.y * 128, n0 = blockIdx.x * 256;
    int KT = K >> 5;

    wmma::fragment<wmma::accumulator,16,16,16,float> acc[4][4];
#pragma unroll
    for (int i = 0; i < 4; i++)
#pragma unroll
        for (int j = 0; j < 4; j++) wmma::fill_fragment(acc[i][j], 0.f);

    for (int s = 0; s < 2; s++) { if (s < KT) HG2_ISSUE(s, s, A, Bt, K); CP_COMMIT(); }
    for (int c = 0; c < KT; c++) {
        CP_WAIT1();
        __syncthreads();
        if (c + 2 < KT) HG2_ISSUE(c + 2, (c + 2) % 3, A, Bt, K);
        CP_COMMIT();
        HG2_COMP(c % 3);
    }
    __syncthreads();

    float* stg = (float*)sbuf + wid * 16 * 20;
#pragma unroll
    for (int i = 0; i < 4; i++)
#pragma unroll
        for (int j = 0; j < 4; j++) {
            wmma::store_matrix_sync(stg, acc[i][j], 20, wmma::mem_row_major);
            __syncwarp();
#pragma unroll
            for (int e = 0; e < 8; e++) {
                int idx = lane * 8 + e;
                int r = idx >> 4, cc = idx & 15;
                int m = m0 + wm*64 + i*16 + r;
                int n = n0 + wn*64 + j*16 + cc;
                float val = stg[r*20 + cc] + bias[n];
                if (EPI == 1) {
                    val = 0.5f * val * (1.0f + erff(val * 0.70710678118654752f));
                    ((__half*)Cv)[(size_t)m * N + n] = __float2half_rn(val);
                } else {
                    ((float*)Cv)[(size_t)m * N + n] = val;
                }
            }
            __syncwarp();
        }
}

// ---------------- conv-embedding GEMM (gathered A rows) ----------------
__global__ void __launch_bounds__(256) conv_hgemm2_k(
    const int* __restrict__ tok, const float* __restrict__ conv_b,
    const float* __restrict__ pos)
{
    extern __shared__ char sbuf[];
    __shared__ int toks[16][128];
    int tid = threadIdx.x, wid = tid >> 5, lane = tid & 31;
    int wm = wid >> 2, wn = wid & 3;
    int m0 = blockIdx.y * 128, n0 = blockIdx.x * 256;
    const int KT = KCONV >> 5;   // 256

    if (tid < 128) {
        int r = m0 + tid;
        int b = r >> 8, nn = r & 255;
        int base = b * LL + nn * PP;
#pragma unroll
        for (int p = 0; p < 16; p++) toks[p][tid] = tok[base + p];
    }
    __syncthreads();

    wmma::fragment<wmma::accumulator,16,16,16,float> acc[4][4];
#pragma unroll
    for (int i = 0; i < 4; i++)
#pragma unroll
        for (int j = 0; j < 4; j++) wmma::fill_fragment(acc[i][j], 0.f);

#define CV2_ISSUE(CH, ST) do {                                                    \
    __half* As_ = (__half*)(sbuf + (ST)*STGB);                                    \
    __half* Bs_ = As_ + ASTG;                                                     \
    int k0_ = (CH) << 5; int p_ = k0_ >> 9, i0_ = k0_ & 511;                      \
    _Pragma("unroll") for (int t_ = 0; t_ < 2; t_++) {                            \
        int idx_ = tid + t_*256; int row_ = idx_ >> 2, c_ = (idx_ & 3) * 8;       \
        int tk_ = toks[p_][row_];                                                 \
        cpa16(As_ + row_*ALD + c_, g_embt + (size_t)tk_*DD + i0_ + c_); }         \
    _Pragma("unroll") for (int t_ = 0; t_ < 4; t_++) {                            \
        int idx_ = tid + t_*256; int row_ = idx_ >> 2, c_ = (idx_ & 3) * 8;       \
        cpa16(Bs_ + row_*ALD + c_, g_Wc + (size_t)(n0 + row_)*KCONV + k0_ + c_); } \
} while (0)

    for (int s = 0; s < 2; s++) { CV2_ISSUE(s, s); CP_COMMIT(); }
    for (int c = 0; c < KT; c++) {
        CP_WAIT1();
        __syncthreads();
        if (c + 2 < KT) CV2_ISSUE(c + 2, (c + 2) % 3);
        CP_COMMIT();
        HG2_COMP(c % 3);
    }
    __syncthreads();

    float* stg = (float*)sbuf + wid * 16 * 20;
#pragma unroll
    for (int i = 0; i < 4; i++)
#pragma unroll
        for (int j = 0; j < 4; j++) {
            wmma::store_matrix_sync(stg, acc[i][j], 20, wmma::mem_row_major);
            __syncwarp();
#pragma unroll
            for (int e = 0; e < 8; e++) {
                int idx = lane * 8 + e;
                int r = idx >> 4, cc = idx & 15;
                int mrow = m0 + wm*64 + i*16 + r;
                int b = mrow >> 8, nn = mrow & 255;
                int s = nn + 1;
                int n = n0 + wn*64 + j*16 + cc;
                float val = stg[r*20 + cc] + conv_b[n] + pos[(size_t)s*DD + n];
                size_t o = ((size_t)(b*SS + s))*DD + n;
                g_x[o]  = val;
                g_xh[o] = __float2half_rn(val);
            }
            __syncwarp();
        }
}

// ---------------- prologue pack kernels ----------------
// float4 -> half conversion (coalesced both sides)
__global__ void half4_k(const float4* __restrict__ src, __half* __restrict__ dst, int n4) {
    int i = blockIdx.x * 256 + threadIdx.x;
    if (i >= n4) return;
    float4 v = src[i];
    __half2 a = __floats2half2_rn(v.x, v.y);
    __half2 b = __floats2half2_rn(v.z, v.w);
    __half2* d = (__half2*)(dst + (size_t)i * 4);
    d[0] = a; d[1] = b;
}

// tiled transpose pack: dst[l][n][k] = half(src[l][k][n]); grid (N/32, K/32, NLAY)
__global__ void pack_t2_k(const float* __restrict__ src, __half* __restrict__ dst,
                          int K, int N) {
    __shared__ float tile[32][33];
    int n0 = blockIdx.x * 32, k0 = blockIdx.y * 32;
    size_t per = (size_t)K * N;
    const float* s = src + (size_t)blockIdx.z * per;
    __half* d = dst + (size_t)blockIdx.z * per;
    int tx = threadIdx.x, ty = threadIdx.y;
#pragma unroll
    for (int r = 0; r < 4; r++) {
        int k = k0 + ty + r * 8;
        tile[ty + r * 8][tx] = s[(size_t)k * N + n0 + tx];
    }
    __syncthreads();
#pragma unroll
    for (int r = 0; r < 4; r++) {
        int n = n0 + ty + r * 8;
        d[(size_t)n * K + k0 + tx] = __float2half_rn(tile[tx][ty + r * 8]);
    }
}

// qkv pack (fused 3 weights): grid (NQKV/32, DD/32, NLAY)
__global__ void pack_qkv2_k(const float* __restrict__ Wq, const float* __restrict__ Wk,
                            const float* __restrict__ Wv) {
    __shared__ float tile[32][33];
    int n0 = blockIdx.x * 32, k0 = blockIdx.y * 32;
    int l = blockIdx.z;
    int w = n0 >> 9, nn0 = n0 & 511;
    const float* W = ((w == 0) ? Wq : (w == 1) ? Wk : Wv) + (size_t)l * DD * DD;
    __half* d = g_Wqkv + (size_t)l * NQKV * DD;
    int tx = threadIdx.x, ty = threadIdx.y;
#pragma unroll
    for (int r = 0; r < 4; r++) {
        int k = k0 + ty + r * 8;
        tile[ty + r * 8][tx] = W[(size_t)k * DD + nn0 + tx];
    }
    __syncthreads();
#pragma unroll
    for (int r = 0; r < 4; r++) {
        int n = n0 + ty + r * 8;
        d[(size_t)n * DD + k0 + tx] = __float2half_rn(tile[tx][ty + r * 8]);
    }
}

__global__ void pack_qkvb_k(const float* __restrict__ bq, const float* __restrict__ bk,
                            const float* __restrict__ bv) {
    int idx = blockIdx.x * 256 + threadIdx.x;
    if (idx >= NLAY * NQKV) return;
    int i = idx / NQKV, n = idx % NQKV;
    int w = n >> 9, nn = n & 511;
    const float* Bv = (w == 0) ? bq : (w == 1) ? bk : bv;
    g_bqkv[idx] = Bv[i * DD + nn];
}

// g_Wc[o][p*512+i] = conv_w[o][i][p]
__global__ void pack_convw_k(const float* __restrict__ cw) {
    size_t idx = (size_t)blockIdx.x * 256 + threadIdx.x;
    if (idx >= (size_t)DD * KCONV) return;
    int o = (int)(idx >> 13);
    int k = (int)(idx & 8191);
    int i = k & 511, p = k >> 9;
    g_Wc[idx] = __float2half_rn(cw[((size_t)o * DD + i) * PP + p]);
}

__global__ void rope_tab_k() {
    int idx = blockIdx.x * 256 + threadIdx.x;
    if (idx >= SS * 32) return;
    int s = idx >> 5, j = idx & 31;
    float ang = (float)s * exp2f(-(float)j * (13.287712379549449f / 32.f));
    g_cs[idx * 2]     = cosf(ang);
    g_cs[idx * 2 + 1] = sinf(ang);
}

// ---------------- small kernels ----------------
__global__ void lengths_k(const float* __restrict__ mask) {
    __shared__ float sh[256];
    int b = blockIdx.x;
    float s = 0.f;
    for (int i = threadIdx.x; i < LL; i += 256) s += mask[(size_t)b * LL + i];
    sh[threadIdx.x] = s;
    __syncthreads();
    for (int st = 128; st > 0; st >>= 1) {
        if (threadIdx.x < st) sh[threadIdx.x] += sh[threadIdx.x + st];
        __syncthreads();
    }
    if (threadIdx.x == 0) g_len[b] = ceilf((sh[0] + 1.0f) / (float)PP);
}

__global__ void init_cls_k(const float* __restrict__ cls, const float* __restrict__ pos) {
    int idx = blockIdx.x * blockDim.x + threadIdx.x;
    if (idx >= BB * DD) return;
    int b = idx >> 9, d = idx & 511;
    float v = cls[d] + pos[d];
    size_t o = (size_t)b * SS * DD + d;
    g_x[o] = v; g_xh[o] = __float2half_rn(v);
}

__global__ void zero_pad_k() {
    int i = blockIdx.x * blockDim.x + threadIdx.x;
    int n = (TPAD - TT) * DD;
    if (i < n) {
        g_x[(size_t)TT * DD + i] = 0.f;
        g_xh[(size_t)TT * DD + i] = __float2half_rn(0.f);
        g_attn[(size_t)TT * DD + i] = __float2half_rn(0.f);
    }
}

// rope + elu feature map in place on g_qkv (q at +0, k at +512; k masked)
__global__ void __launch_bounds__(512) rope_feat_k() {
    int t = blockIdx.x;
    int c = threadIdx.x;
    __shared__ float qrow[DD], krow[DD];
    size_t base = (size_t)t * NQKV;
    qrow[c] = g_qkv[base + c];
    krow[c] = g_qkv[base + 512 + c];
    __syncthreads();
    int s = t % SS, b = t / SS;
    int cc = c & 63, j = cc & 31;
    float cs = g_cs[(s * 32 + j) * 2];
    float sn = g_cs[(s * 32 + j) * 2 + 1];
    int partner = (cc < 32) ? c + 32 : c - 32;
    float sgn = (cc < 32) ? -1.f : 1.f;
    float qr = qrow[c] * cs + sgn * qrow[partner] * sn;
    float kr = krow[c] * cs + sgn * krow[partner] * sn;
    float qf = qr > 0.f ? qr + 1.f : expf(qr);
    float kf = kr > 0.f ? kr + 1.f : expf(kr);
    float msk = ((float)s < g_len[b]) ? 1.f : 0.f;
    g_qkv[base + c] = qf;
    g_qkv[base + 512 + c] = kf * msk;
}

// per (b,h): kv[d][m] = sum_s kf*v ; ksum[d] = sum_s kf  (8-step chunks)
__global__ void __launch_bounds__(256) kv2_k() {
    int bh = blockIdx.x;
    int b = bh >> 3, h = bh & 7;
    __shared__ float kf_sh[8][64], v_sh[8][64];
    int tid = threadIdx.x;
    int m = tid & 63, dg = tid >> 6;
    float acc[16];
#pragma unroll
    for (int jj = 0; jj < 16; jj++) acc[jj] = 0.f;
    float ksum = 0.f;
    for (int s0 = 0; s0 < SS; s0 += 8) {
        __syncthreads();
#pragma unroll
        for (int u = 0; u < 4; u++) {
            int idx = tid + u * 256;
            int which = idx >> 9;
            int rr = (idx >> 6) & 7;
            int cc = idx & 63;
            int s = s0 + rr;
            float val = (s < SS)
                ? g_qkv[(size_t)(b*SS + s)*NQKV + (which ? 1024 : 512) + h*64 + cc]
                : 0.f;
            if (which) v_sh[rr][cc] = val; else kf_sh[rr][cc] = val;
        }
        __syncthreads();
#pragma unroll
        for (int r = 0; r < 8; r++) {
            float vr = v_sh[r][m];
#pragma unroll
            for (int jj = 0; jj < 16; jj++) acc[jj] += kf_sh[r][dg*16 + jj] * vr;
        }
        if (tid < 64) {
#pragma unroll
            for (int r = 0; r < 8; r++) ksum += kf_sh[r][tid];
        }
    }
#pragma unroll
    for (int jj = 0; jj < 16; jj++)
        g_kv[((size_t)bh * DHD + dg*16 + jj) * DHD + m] = acc[jj];
    if (tid < 64) g_ksum[bh * DHD + tid] = ksum;
}

// per (b,h): attn = z * qf @ kv (4-step chunks); stores fp16
__global__ void __launch_bounds__(256) attn2_k() {
    int bh = blockIdx.x;
    int b = bh >> 3, h = bh & 7;
    __shared__ float kvs[DHD * DHD];
    __shared__ float ks[DHD];
    __shared__ float q4[4][64];
    __shared__ float red[4][64];
    __shared__ float part[4][4][64];
    __shared__ float zsh[4];
    int tid = threadIdx.x, wid = tid >> 5, lane = tid & 31;
    int m = tid & 63, dg = tid >> 6;
    for (int i = tid; i < DHD * DHD; i += 256) kvs[i] = g_kv[(size_t)bh * DHD * DHD + i];
    if (tid < 64) ks[tid] = g_ksum[bh * DHD + tid];
    __syncthreads();
    for (int s0 = 0; s0 < SS; s0 += 4) {
        int r = tid >> 6, c = tid & 63;
        int sr = s0 + r;
        q4[r][c] = (sr < SS) ? g_qkv[(size_t)(b*SS + sr)*NQKV + h*64 + c] : 0.f;
        __syncthreads();
        red[r][c] = q4[r][c] * ks[c];
        __syncthreads();
        if (wid < 4) {
            float v = red[wid][lane] + red[wid][lane + 32];
            for (int o = 16; o; o >>= 1) v += __shfl_down_sync(0xffffffffu, v, o);
            if (lane == 0) zsh[wid] = 1.f / (v + 1e-6f);
        }
        float a[4] = {0.f, 0.f, 0.f, 0.f};
#pragma unroll
        for (int jj = 0; jj < 16; jj++) {
            int d = dg*16 + jj;
            float kc = kvs[d * DHD + m];
#pragma unroll
            for (int rr = 0; rr < 4; rr++) a[rr] += q4[rr][d] * kc;
        }
#pragma unroll
        for (int rr = 0; rr < 4; rr++) part[dg][rr][m] = a[rr];
        __syncthreads();
        {
            int rr = tid >> 6, mm = tid & 63;
            int s = s0 + rr;
            if (s < SS) {
                float o = (part[0][rr][mm] + part[1][rr][mm] +
                           part[2][rr][mm] + part[3][rr][mm]) * zsh[rr];
                g_attn[((size_t)(b*SS + s))*DD + h*64 + mm] = __float2half_rn(o);
            }
        }
        __syncthreads();
    }
}

// X = LN(X + Y); writes fp32 X and fp16 XH
__global__ void __launch_bounds__(256) ln_k(
    const float* __restrict__ Y, const float* __restrict__ sc,
    const float* __restrict__ bi, float* __restrict__ X, __half* __restrict__ XH)
{
    int t = blockIdx.x, tid = threadIdx.x;
    size_t base = (size_t)t * DD;
    float v0 = X[base + tid] + Y[base + tid];
    float v1 = X[base + tid + 256] + Y[base + tid + 256];
    float s = v0 + v1, ss = v0 * v0 + v1 * v1;
    __shared__ float rs[8], rss[8];
    for (int o = 16; o; o >>= 1) {
        s  += __shfl_down_sync(0xffffffffu, s, o);
        ss += __shfl_down_sync(0xffffffffu, ss, o);
    }
    int w = tid >> 5;
    if ((tid & 31) == 0) { rs[w] = s; rss[w] = ss; }
    __syncthreads();
    if (tid == 0) {
        float S1 = 0.f, S2 = 0.f;
        for (int i = 0; i < 8; i++) { S1 += rs[i]; S2 += rss[i]; }
        rs[0] = S1 / (float)DD;
        rss[0] = S2 / (float)DD;
    }
    __syncthreads();
    float mean = rs[0];
    float inv = rsqrtf(rss[0] - mean * mean + 1e-5f);
    float o0 = (v0 - mean) * inv * sc[tid] + bi[tid];
    float o1 = (v1 - mean) * inv * sc[tid + 256] + bi[tid + 256];
    X[base + tid] = o0;        XH[base + tid] = __float2half_rn(o0);
    X[base + tid + 256] = o1;  XH[base + tid + 256] = __float2half_rn(o1);
}

// final LN on token 0 + classifier head
__global__ void __launch_bounds__(256) final_k(
    const float* __restrict__ lnf_s, const float* __restrict__ lnf_b,
    const float* __restrict__ ow, const float* __restrict__ ob,
    float* __restrict__ out)
{
    int b = blockIdx.x, tid = threadIdx.x;
    size_t base = (size_t)b * SS * DD;
    float v0 = g_x[base + tid];
    float v1 = g_x[base + tid + 256];
    float s = v0 + v1, ss = v0 * v0 + v1 * v1;
    __shared__ float rs[8], rss[8];
    __shared__ float row[DD];
    for (int o = 16; o; o >>= 1) {
        s  += __shfl_down_sync(0xffffffffu, s, o);
        ss += __shfl_down_sync(0xffffffffu, ss, o);
    }
    int w = tid >> 5;
    if ((tid & 31) == 0) { rs[w] = s; rss[w] = ss; }
    __syncthreads();
    if (tid == 0) {
        float S1 = 0.f, S2 = 0.f;
        for (int i = 0; i < 8; i++) { S1 += rs[i]; S2 += rss[i]; }
        rs[0] = S1 / (float)DD;
        rss[0] = S2 / (float)DD;
    }
    __syncthreads();
    float mean = rs[0];
    float inv = rsqrtf(rss[0] - mean * mean + 1e-5f);
    row[tid]       = (v0 - mean) * inv * lnf_s[tid] + lnf_b[tid];
    row[tid + 256] = (v1 - mean) * inv * lnf_s[tid + 256] + lnf_b[tid + 256];
    __syncthreads();
    for (int c = 0; c < NCLS; c++) {
        float p = row[tid] * ow[tid * NCLS + c] + row[tid + 256] * ow[(tid + 256) * NCLS + c];
        for (int o = 16; o; o >>= 1) p += __shfl_down_sync(0xffffffffu, p, o);
        if ((tid & 31) == 0) rs[tid >> 5] = p;
        __syncthreads();
        if (tid == 0) {
            float t2 = 0.f;
            for (int i = 0; i < 8; i++) t2 += rs[i];
            out[b * NCLS + c] = t2 + ob[c];
        }
        __syncthreads();
    }
}

// ---------------- host driver ----------------
extern "C" void kernel_launch(void* const* d_in, const int* in_sizes, int n_in,
                              void* d_out, int out_size)
{
    const int*   inputs     = (const int*)  d_in[0];
    const float* input_mask = (const float*)d_in[1];
    const float* emb        = (const float*)d_in[2];
    const float* conv_w     = (const float*)d_in[3];
    const float* conv_b     = (const float*)d_in[4];
    const float* pos        = (const float*)d_in[5];
    const float* cls        = (const float*)d_in[6];
    const float* Wq         = (const float*)d_in[7];
    const float* bq         = (const float*)d_in[8];
    const float* Wk         = (const float*)d_in[9];
    const float* bk         = (const float*)d_in[10];
    const float* Wv         = (const float*)d_in[11];
    const float* bv         = (const float*)d_in[12];
    const float* Wo         = (const float*)d_in[13];
    const float* bo         = (const float*)d_in[14];
    const float* ln1_s      = (const float*)d_in[15];
    const float* ln1_b      = (const float*)d_in[16];
    const float* ln2_s      = (const float*)d_in[17];
    const float* ln2_b      = (const float*)d_in[18];
    const float* W1         = (const float*)d_in[19];
    const float* b1         = (const float*)d_in[20];
    const float* W2         = (const float*)d_in[21];
    const float* b2         = (const float*)d_in[22];
    const float* lnf_s      = (const float*)d_in[23];
    const float* lnf_b      = (const float*)d_in[24];
    const float* out_w      = (const float*)d_in[25];
    const float* out_b      = (const float*)d_in[26];
    float* out = (float*)d_out;

    float  *px, *pqkv, *py, *pbqkv;
    __half *pxh, *pattn, *ph, *pWqkv, *pWot, *pW1t, *pW2t, *pembt;
    cudaGetSymbolAddress((void**)&px,    g_x);
    cudaGetSymbolAddress((void**)&pxh,   g_xh);
    cudaGetSymbolAddress((void**)&pqkv,  g_qkv);
    cudaGetSymbolAddress((void**)&pattn, g_attn);
    cudaGetSymbolAddress((void**)&py,    g_y);
    cudaGetSymbolAddress((void**)&ph,    g_h);
    cudaGetSymbolAddress((void**)&pWqkv, g_Wqkv);
    cudaGetSymbolAddress((void**)&pbqkv, g_bqkv);
    cudaGetSymbolAddress((void**)&pWot,  g_Wot);
    cudaGetSymbolAddress((void**)&pW1t,  g_W1t);
    cudaGetSymbolAddress((void**)&pW2t,  g_W2t);
    cudaGetSymbolAddress((void**)&pembt, g_embt);

    cudaFuncSetAttribute(hgemm2_k<0>,   cudaFuncAttributeMaxDynamicSharedMemorySize, SMEMH);
    cudaFuncSetAttribute(hgemm2_k<1>,   cudaFuncAttributeMaxDynamicSharedMemorySize, SMEMH);
    cudaFuncSetAttribute(conv_hgemm2_k, cudaFuncAttributeMaxDynamicSharedMemorySize, SMEMH);

    // prologue: pack weights to fp16 [N][K] (tiled transposes), tables, padding
    pack_convw_k<<<(int)(((size_t)DD*KCONV + 255) / 256), 256>>>(conv_w);
    half4_k<<<(32000 * DD / 4 + 255) / 256, 256>>>((const float4*)emb, pembt, 32000 * DD / 4);
    pack_qkv2_k<<<dim3(NQKV/32, DD/32, NLAY), dim3(32, 8)>>>(Wq, Wk, Wv);
    pack_qkvb_k<<<(NLAY * NQKV + 255) / 256, 256>>>(bq, bk, bv);
    pack_t2_k<<<dim3(DD/32, DD/32, NLAY),  dim3(32, 8)>>>(Wo, pWot, DD, DD);
    pack_t2_k<<<dim3(FFD/32, DD/32, NLAY), dim3(32, 8)>>>(W1, pW1t, DD, FFD);
    pack_t2_k<<<dim3(DD/32, FFD/32, NLAY), dim3(32, 8)>>>(W2, pW2t, FFD, DD);
    rope_tab_k<<<(SS * 32 + 255) / 256, 256>>>();
    lengths_k<<<BB, 256>>>(input_mask);
    zero_pad_k<<<((TPAD - TT) * DD + 255) / 256, 256>>>();
    init_cls_k<<<(BB * DD + 255) / 256, 256>>>(cls, pos);
    conv_hgemm2_k<<<dim3(DD / 256, MCONV / 128), 256, SMEMH>>>(inputs, conv_b, pos);

    dim3 gQKV(NQKV / 256, TPAD / 128);  // (6, 65)
    dim3 gD(DD / 256, TPAD / 128);      // (2, 65)
    dim3 gF(FFD / 256, TPAD / 128);     // (8, 65)

    for (int i = 0; i < NLAY; i++) {
        hgemm2_k<0><<<gQKV, 256, SMEMH>>>(pxh, pWqkv + (size_t)i*NQKV*DD,
                                          pbqkv + (size_t)i*NQKV, pqkv, NQKV, DD);
        rope_feat_k<<<TT, 512>>>();
        kv2_k<<<BB * HH, 256>>>();
        attn2_k<<<BB * HH, 256>>>();
        hgemm2_k<0><<<gD, 256, SMEMH>>>(pattn, pWot + (size_t)i*DD*DD,
                                        bo + (size_t)i*DD, py, DD, DD);
        ln_k<<<TPAD, 256>>>(py, ln1_s + (size_t)i*DD, ln1_b + (size_t)i*DD, px, pxh);
        hgemm2_k<1><<<gF, 256, SMEMH>>>(pxh, pW1t + (size_t)i*FFD*DD,
                                        b1 + (size_t)i*FFD, ph, FFD, DD);
        hgemm2_k<0><<<gD, 256, SMEMH>>>(ph, pW2t + (size_t)i*DD*FFD,
                                        b2 + (size_t)i*DD, py, DD, FFD);
        ln_k<<<TPAD, 256>>>(py, ln2_s + (size_t)i*DD, ln2_b + (size_t)i*DD, px, pxh);
    }

    final_k<<<BB, 256>>>(lnf_s, lnf_b, out_w, out_b, out);
}

// round 11
// speedup vs baseline: 3.5010x; 1.0485x over previous
#include <cuda_runtime.h>
#include <cuda_fp16.h>
#include <mma.h>
#include <math.h>
#include <stdint.h>

using namespace nvcuda;

#define BB   32
#define LL   4096
#define PP   16
#define SS   257
#define DD   512
#define HH   8
#define DHD  64
#define NLAY 8
#define FFD  2048
#define NCLS 4
#define TT   (BB*SS)      /* 8224 */
#define TPAD 8320         /* 65*128 */
#define KCONV 8192
#define MCONV 8192
#define NQKV 1536
#define KVPARTS 4
#define SPART 72          /* ceil(257/4) rounded to mult of 8 */

// ---------------- scratch (device globals; no allocations) ----------------
__device__ float  g_x[TPAD*DD];
__device__ __half g_xh[TPAD*DD];             // fp16 copy of x (GEMM A)
__device__ float  g_qkv[(size_t)TPAD*NQKV];  // post rope/elu q,k + raw v
__device__ __half g_attn[TPAD*DD];           // fp16 (GEMM A)
__device__ float  g_y[TPAD*DD];
__device__ __half g_h[(size_t)TPAD*FFD];     // fp16 post-GELU (GEMM A)
__device__ float  g_kvp[KVPARTS][BB*HH*DHD*DHD];
__device__ float  g_ksump[KVPARTS][BB*HH*DHD];
__device__ float  g_len[BB];
__device__ float  g_cs[SS*32*2];             // rope cos/sin table
// packed fp16 weights ([N][K], K-major)
__device__ __half g_Wc[(size_t)DD*KCONV];
__device__ __half g_embt[(size_t)32000*DD];
__device__ __half g_Wqkv[(size_t)NLAY*NQKV*DD];
__device__ float  g_bqkv[NLAY*NQKV];
__device__ __half g_Wot[(size_t)NLAY*DD*DD];
__device__ __half g_W1t[(size_t)NLAY*FFD*DD];
__device__ __half g_W2t[(size_t)NLAY*DD*FFD];

// ---------------- helpers ----------------
__device__ __forceinline__ void cpa16(const __half* dst_smem, const __half* src) {
    uint32_t d = (uint32_t)__cvta_generic_to_shared(dst_smem);
    asm volatile("cp.async.cg.shared.global [%0], [%1], 16;" :: "r"(d), "l"(src) : "memory");
}
#define CP_COMMIT() asm volatile("cp.async.commit_group;" ::: "memory")
#define CP_WAIT1()  asm volatile("cp.async.wait_group 1;" ::: "memory")

// ================= fp16 wmma GEMM, tile 128x256, BK=32, 3-stage =================
#define ALD   40
#define ASTG  (128*ALD)
#define BSTG  (256*ALD)
#define STGH  (ASTG+BSTG)
#define STGB  (STGH*2)                  /* bytes per stage = 30720 */
#define SMEMH (3*STGB)                  /* 92160 bytes */

#define HG2_ISSUE(CH, ST, APTR, BPTR, KDIM) do {                                  \
    __half* As_ = (__half*)(sbuf + (ST)*STGB);                                    \
    __half* Bs_ = As_ + ASTG;                                                     \
    int k0_ = (CH) << 5;                                                          \
    _Pragma("unroll") for (int t_ = 0; t_ < 2; t_++) {                            \
        int idx_ = tid + t_*256; int row_ = idx_ >> 2, c_ = (idx_ & 3) * 8;       \
        cpa16(As_ + row_*ALD + c_, (APTR) + (size_t)(m0 + row_)*(KDIM) + k0_ + c_); } \
    _Pragma("unroll") for (int t_ = 0; t_ < 4; t_++) {                            \
        int idx_ = tid + t_*256; int row_ = idx_ >> 2, c_ = (idx_ & 3) * 8;       \
        cpa16(Bs_ + row_*ALD + c_, (BPTR) + (size_t)(n0 + row_)*(KDIM) + k0_ + c_); } \
} while (0)

#define HG2_COMP(ST) do {                                                         \
    const __half* As_ = (const __half*)(sbuf + (ST)*STGB);                        \
    const __half* Bs_ = As_ + ASTG;                                               \
    _Pragma("unroll") for (int kk = 0; kk < 2; kk++) {                            \
        wmma::fragment<wmma::matrix_a,16,16,16,__half,wmma::row_major> af[4];     \
        wmma::fragment<wmma::matrix_b,16,16,16,__half,wmma::col_major> bf[4];     \
        _Pragma("unroll") for (int i = 0; i < 4; i++)                             \
            wmma::load_matrix_sync(af[i], As_ + (wm*64 + i*16)*ALD + kk*16, ALD); \
        _Pragma("unroll") for (int j = 0; j < 4; j++)                             \
            wmma::load_matrix_sync(bf[j], Bs_ + (wn*64 + j*16)*ALD + kk*16, ALD); \
        _Pragma("unroll") for (int i = 0; i < 4; i++)                             \
            _Pragma("unroll") for (int j = 0; j < 4; j++)                         \
                wmma::mma_sync(acc[i][j], af[i], bf[j], acc[i][j]);               \
    }                                                                             \
} while (0)

// EPI 0: float out + bias   1: half out + bias + gelu   2: qkv out (bias+rope+elu+mask)
template<int EPI>
__global__ void __launch_bounds__(256) hgemm2_k(
    const __half* __restrict__ A, const __half* __restrict__ Bt,
    const float* __restrict__ bias, void* __restrict__ Cv,
    int N, int K)
{
    extern __shared__ char sbuf[];
    int tid = threadIdx.x, wid = tid >> 5, lane = tid & 31;
    int wm = wid >> 2, wn = wid & 3;
    int m0 = blockIdx.y * 128, n0 = blockIdx.x * 256;
    int KT = K >> 5;

    wmma::fragment<wmma::accumulator,16,16,16,float> acc[4][4];
#pragma unroll
    for (int i = 0; i < 4; i++)
#pragma unroll
        for (int j = 0; j < 4; j++) wmma::fill_fragment(acc[i][j], 0.f);

    for (int s = 0; s < 2; s++) { if (s < KT) HG2_ISSUE(s, s, A, Bt, K); CP_COMMIT(); }
    for (int c = 0; c < KT; c++) {
        CP_WAIT1();
        __syncthreads();
        if (c + 2 < KT) HG2_ISSUE(c + 2, (c + 2) % 3, A, Bt, K);
        CP_COMMIT();
        HG2_COMP(c % 3);
    }
    __syncthreads();

    if (EPI == 2) {
        // stage all 4 j-fragments per row-block: warp tile N=64 == one head
        float* st = (float*)sbuf + wid * (16 * 68);
        int nb = n0 + wn * 64;        // head-aligned col base
        int wtype = nb >> 9;          // 0=q 1=k 2=v
#pragma unroll
        for (int i = 0; i < 4; i++) {
#pragma unroll
            for (int j = 0; j < 4; j++)
                wmma::store_matrix_sync(st + j * 16, acc[i][j], 68, wmma::mem_row_major);
            __syncwarp();
#pragma unroll
            for (int e = 0; e < 32; e++) {
                int idx = e * 32 + lane;
                int r = idx >> 6, c = idx & 63;
                int m = m0 + wm*64 + i*16 + r;
                int n = nb + c;
                float val = st[r*68 + c] + bias[n];
                float outv;
                if (wtype < 2) {
                    int s = m % SS, b = m / SS;
                    if (b > BB - 1) b = BB - 1;
                    int jj = c & 31;
                    float cs = g_cs[(s*32 + jj)*2];
                    float sn = g_cs[(s*32 + jj)*2 + 1];
                    float partner = st[r*68 + (c ^ 32)] + bias[nb + (c ^ 32)];
                    float sgn = (c < 32) ? -1.f : 1.f;
                    float rot = val * cs + sgn * partner * sn;
                    float f = rot > 0.f ? rot + 1.f : expf(rot);
                    if (wtype == 1) f *= ((float)s < g_len[b]) ? 1.f : 0.f;
                    outv = f;
                } else {
                    outv = val;
                }
                g_qkv[(size_t)m * NQKV + n] = outv;
            }
            __syncwarp();
        }
        return;
    }

    float* stg = (float*)sbuf + wid * 16 * 20;
#pragma unroll
    for (int i = 0; i < 4; i++)
#pragma unroll
        for (int j = 0; j < 4; j++) {
            wmma::store_matrix_sync(stg, acc[i][j], 20, wmma::mem_row_major);
            __syncwarp();
#pragma unroll
            for (int e = 0; e < 8; e++) {
                int idx = lane * 8 + e;
                int r = idx >> 4, cc = idx & 15;
                int m = m0 + wm*64 + i*16 + r;
                int n = n0 + wn*64 + j*16 + cc;
                float val = stg[r*20 + cc] + bias[n];
                if (EPI == 1) {
                    val = 0.5f * val * (1.0f + erff(val * 0.70710678118654752f));
                    ((__half*)Cv)[(size_t)m * N + n] = __float2half_rn(val);
                } else {
                    ((float*)Cv)[(size_t)m * N + n] = val;
                }
            }
            __syncwarp();
        }
}

// ---------------- conv-embedding GEMM (gathered A rows) ----------------
__global__ void __launch_bounds__(256) conv_hgemm2_k(
    const int* __restrict__ tok, const float* __restrict__ conv_b,
    const float* __restrict__ pos)
{
    extern __shared__ char sbuf[];
    __shared__ int toks[16][128];
    int tid = threadIdx.x, wid = tid >> 5, lane = tid & 31;
    int wm = wid >> 2, wn = wid & 3;
    int m0 = blockIdx.y * 128, n0 = blockIdx.x * 256;
    const int KT = KCONV >> 5;   // 256

    if (tid < 128) {
        int r = m0 + tid;
        int b = r >> 8, nn = r & 255;
        int base = b * LL + nn * PP;
#pragma unroll
        for (int p = 0; p < 16; p++) toks[p][tid] = tok[base + p];
    }
    __syncthreads();

    wmma::fragment<wmma::accumulator,16,16,16,float> acc[4][4];
#pragma unroll
    for (int i = 0; i < 4; i++)
#pragma unroll
        for (int j = 0; j < 4; j++) wmma::fill_fragment(acc[i][j], 0.f);

#define CV2_ISSUE(CH, ST) do {                                                    \
    __half* As_ = (__half*)(sbuf + (ST)*STGB);                                    \
    __half* Bs_ = As_ + ASTG;                                                     \
    int k0_ = (CH) << 5; int p_ = k0_ >> 9, i0_ = k0_ & 511;                      \
    _Pragma("unroll") for (int t_ = 0; t_ < 2; t_++) {                            \
        int idx_ = tid + t_*256; int row_ = idx_ >> 2, c_ = (idx_ & 3) * 8;       \
        int tk_ = toks[p_][row_];                                                 \
        cpa16(As_ + row_*ALD + c_, g_embt + (size_t)tk_*DD + i0_ + c_); }         \
    _Pragma("unroll") for (int t_ = 0; t_ < 4; t_++) {                            \
        int idx_ = tid + t_*256; int row_ = idx_ >> 2, c_ = (idx_ & 3) * 8;       \
        cpa16(Bs_ + row_*ALD + c_, g_Wc + (size_t)(n0 + row_)*KCONV + k0_ + c_); } \
} while (0)

    for (int s = 0; s < 2; s++) { CV2_ISSUE(s, s); CP_COMMIT(); }
    for (int c = 0; c < KT; c++) {
        CP_WAIT1();
        __syncthreads();
        if (c + 2 < KT) CV2_ISSUE(c + 2, (c + 2) % 3);
        CP_COMMIT();
        HG2_COMP(c % 3);
    }
    __syncthreads();

    float* stg = (float*)sbuf + wid * 16 * 20;
#pragma unroll
    for (int i = 0; i < 4; i++)
#pragma unroll
        for (int j = 0; j < 4; j++) {
            wmma::store_matrix_sync(stg, acc[i][j], 20, wmma::mem_row_major);
            __syncwarp();
#pragma unroll
            for (int e = 0; e < 8; e++) {
                int idx = lane * 8 + e;
                int r = idx >> 4, cc = idx & 15;
                int mrow = m0 + wm*64 + i*16 + r;
                int b = mrow >> 8, nn = mrow & 255;
                int s = nn + 1;
                int n = n0 + wn*64 + j*16 + cc;
                float val = stg[r*20 + cc] + conv_b[n] + pos[(size_t)s*DD + n];
                size_t o = ((size_t)(b*SS + s))*DD + n;
                g_x[o]  = val;
                g_xh[o] = __float2half_rn(val);
            }
            __syncwarp();
        }
}

// ---------------- prologue pack kernels ----------------
__global__ void half4_k(const float4* __restrict__ src, __half* __restrict__ dst, int n4) {
    int i = blockIdx.x * 256 + threadIdx.x;
    if (i >= n4) return;
    float4 v = src[i];
    __half2 a = __floats2half2_rn(v.x, v.y);
    __half2 b = __floats2half2_rn(v.z, v.w);
    __half2* d = (__half2*)(dst + (size_t)i * 4);
    d[0] = a; d[1] = b;
}

__global__ void pack_t2_k(const float* __restrict__ src, __half* __restrict__ dst,
                          int K, int N) {
    __shared__ float tile[32][33];
    int n0 = blockIdx.x * 32, k0 = blockIdx.y * 32;
    size_t per = (size_t)K * N;
    const float* s = src + (size_t)blockIdx.z * per;
    __half* d = dst + (size_t)blockIdx.z * per;
    int tx = threadIdx.x, ty = threadIdx.y;
#pragma unroll
    for (int r = 0; r < 4; r++) {
        int k = k0 + ty + r * 8;
        tile[ty + r * 8][tx] = s[(size_t)k * N + n0 + tx];
    }
    __syncthreads();
#pragma unroll
    for (int r = 0; r < 4; r++) {
        int n = n0 + ty + r * 8;
        d[(size_t)n * K + k0 + tx] = __float2half_rn(tile[tx][ty + r * 8]);
    }
}

__global__ void pack_qkv2_k(const float* __restrict__ Wq, const float* __restrict__ Wk,
                            const float* __restrict__ Wv) {
    __shared__ float tile[32][33];
    int n0 = blockIdx.x * 32, k0 = blockIdx.y * 32;
    int l = blockIdx.z;
    int w = n0 >> 9, nn0 = n0 & 511;
    const float* W = ((w == 0) ? Wq : (w == 1) ? Wk : Wv) + (size_t)l * DD * DD;
    __half* d = g_Wqkv + (size_t)l * NQKV * DD;
    int tx = threadIdx.x, ty = threadIdx.y;
#pragma unroll
    for (int r = 0; r < 4; r++) {
        int k = k0 + ty + r * 8;
        tile[ty + r * 8][tx] = W[(size_t)k * DD + nn0 + tx];
    }
    __syncthreads();
#pragma unroll
    for (int r = 0; r < 4; r++) {
        int n = n0 + ty + r * 8;
        d[(size_t)n * DD + k0 + tx] = __float2half_rn(tile[tx][ty + r * 8]);
    }
}

__global__ void pack_qkvb_k(const float* __restrict__ bq, const float* __restrict__ bk,
                            const float* __restrict__ bv) {
    int idx = blockIdx.x * 256 + threadIdx.x;
    if (idx >= NLAY * NQKV) return;
    int i = idx / NQKV, n = idx % NQKV;
    int w = n >> 9, nn = n & 511;
    const float* Bv = (w == 0) ? bq : (w == 1) ? bk : bv;
    g_bqkv[idx] = Bv[i * DD + nn];
}

__global__ void pack_convw_k(const float* __restrict__ cw) {
    size_t idx = (size_t)blockIdx.x * 256 + threadIdx.x;
    if (idx >= (size_t)DD * KCONV) return;
    int o = (int)(idx >> 13);
    int k = (int)(idx & 8191);
    int i = k & 511, p = k >> 9;
    g_Wc[idx] = __float2half_rn(cw[((size_t)o * DD + i) * PP + p]);
}

__global__ void rope_tab_k() {
    int idx = blockIdx.x * 256 + threadIdx.x;
    if (idx >= SS * 32) return;
    int s = idx >> 5, j = idx & 31;
    float ang = (float)s * exp2f(-(float)j * (13.287712379549449f / 32.f));
    g_cs[idx * 2]     = cosf(ang);
    g_cs[idx * 2 + 1] = sinf(ang);
}

// ---------------- small kernels ----------------
__global__ void lengths_k(const float* __restrict__ mask) {
    __shared__ float sh[256];
    int b = blockIdx.x;
    float s = 0.f;
    for (int i = threadIdx.x; i < LL; i += 256) s += mask[(size_t)b * LL + i];
    sh[threadIdx.x] = s;
    __syncthreads();
    for (int st = 128; st > 0; st >>= 1) {
        if (threadIdx.x < st) sh[threadIdx.x] += sh[threadIdx.x + st];
        __syncthreads();
    }
    if (threadIdx.x == 0) g_len[b] = ceilf((sh[0] + 1.0f) / (float)PP);
}

__global__ void init_cls_k(const float* __restrict__ cls, const float* __restrict__ pos) {
    int idx = blockIdx.x * blockDim.x + threadIdx.x;
    if (idx >= BB * DD) return;
    int b = idx >> 9, d = idx & 511;
    float v = cls[d] + pos[d];
    size_t o = (size_t)b * SS * DD + d;
    g_x[o] = v; g_xh[o] = __float2half_rn(v);
}

__global__ void zero_pad_k() {
    int i = blockIdx.x * blockDim.x + threadIdx.x;
    int n = (TPAD - TT) * DD;
    if (i < n) {
        g_x[(size_t)TT * DD + i] = 0.f;
        g_xh[(size_t)TT * DD + i] = __float2half_rn(0.f);
        g_attn[(size_t)TT * DD + i] = __float2half_rn(0.f);
    }
}

// kv partial: part p covers s in [p*SPART, min(SS, (p+1)*SPART))
__global__ void __launch_bounds__(256) kv3_k() {
    int bh = blockIdx.x, part = blockIdx.y;
    int b = bh >> 3, h = bh & 7;
    int sbeg = part * SPART;
    int send = min(SS, sbeg + SPART);
    __shared__ float kf_sh[8][64], v_sh[8][64];
    int tid = threadIdx.x;
    int m = tid & 63, dg = tid >> 6;
    float acc[16];
#pragma unroll
    for (int jj = 0; jj < 16; jj++) acc[jj] = 0.f;
    float ksum = 0.f;
    for (int s0 = sbeg; s0 < send; s0 += 8) {
        __syncthreads();
#pragma unroll
        for (int u = 0; u < 4; u++) {
            int idx = tid + u * 256;
            int which = idx >> 9;
            int rr = (idx >> 6) & 7;
            int cc = idx & 63;
            int s = s0 + rr;
            float val = (s < send)
                ? g_qkv[(size_t)(b*SS + s)*NQKV + (which ? 1024 : 512) + h*64 + cc]
                : 0.f;
            if (which) v_sh[rr][cc] = val; else kf_sh[rr][cc] = val;
        }
        __syncthreads();
#pragma unroll
        for (int r = 0; r < 8; r++) {
            float vr = v_sh[r][m];
#pragma unroll
            for (int jj = 0; jj < 16; jj++) acc[jj] += kf_sh[r][dg*16 + jj] * vr;
        }
        if (tid < 64) {
#pragma unroll
            for (int r = 0; r < 8; r++) ksum += kf_sh[r][tid];
        }
    }
#pragma unroll
    for (int jj = 0; jj < 16; jj++)
        g_kvp[part][((size_t)bh * DHD + dg*16 + jj) * DHD + m] = acc[jj];
    if (tid < 64) g_ksump[part][bh * DHD + tid] = ksum;
}

// attn chunk: block (bh, ch) handles tokens [ch*32, min(SS, ch*32+32))
__global__ void __launch_bounds__(256) attn3_k() {
    int bh = blockIdx.x, ch = blockIdx.y;
    int b = bh >> 3, h = bh & 7;
    int sbeg = ch * 32;
    int send = min(SS, sbeg + 32);
    __shared__ float kvs[DHD * DHD];
    __shared__ float ks[DHD];
    __shared__ float q4[4][64];
    __shared__ float red[4][64];
    __shared__ float part[4][4][64];
    __shared__ float zsh[4];
    int tid = threadIdx.x, wid = tid >> 5, lane = tid & 31;
    int m = tid & 63, dg = tid >> 6;
    for (int i = tid; i < DHD * DHD; i += 256) {
        size_t o = (size_t)bh * DHD * DHD + i;
        kvs[i] = g_kvp[0][o] + g_kvp[1][o] + g_kvp[2][o] + g_kvp[3][o];
    }
    if (tid < 64) {
        int o = bh * DHD + tid;
        ks[tid] = g_ksump[0][o] + g_ksump[1][o] + g_ksump[2][o] + g_ksump[3][o];
    }
    __syncthreads();
    for (int s0 = sbeg; s0 < send; s0 += 4) {
        int r = tid >> 6, c = tid & 63;
        int sr = s0 + r;
        q4[r][c] = (sr < send) ? g_qkv[(size_t)(b*SS + sr)*NQKV + h*64 + c] : 0.f;
        __syncthreads();
        red[r][c] = q4[r][c] * ks[c];
        __syncthreads();
        if (wid < 4) {
            float v = red[wid][lane] + red[wid][lane + 32];
            for (int o = 16; o; o >>= 1) v += __shfl_down_sync(0xffffffffu, v, o);
            if (lane == 0) zsh[wid] = 1.f / (v + 1e-6f);
        }
        float a[4] = {0.f, 0.f, 0.f, 0.f};
#pragma unroll
        for (int jj = 0; jj < 16; jj++) {
            int d = dg*16 + jj;
            float kc = kvs[d * DHD + m];
#pragma unroll
            for (int rr = 0; rr < 4; rr++) a[rr] += q4[rr][d] * kc;
        }
#pragma unroll
        for (int rr = 0; rr < 4; rr++) part[dg][rr][m] = a[rr];
        __syncthreads();
        {
            int rr = tid >> 6, mm = tid & 63;
            int s = s0 + rr;
            if (s < send) {
                float o = (part[0][rr][mm] + part[1][rr][mm] +
                           part[2][rr][mm] + part[3][rr][mm]) * zsh[rr];
                g_attn[((size_t)(b*SS + s))*DD + h*64 + mm] = __float2half_rn(o);
            }
        }
        __syncthreads();
    }
}

// X = LN(X + Y); writes fp32 X and fp16 XH
__global__ void __launch_bounds__(256) ln_k(
    const float* __restrict__ Y, const float* __restrict__ sc,
    const float* __restrict__ bi, float* __restrict__ X, __half* __restrict__ XH)
{
    int t = blockIdx.x, tid = threadIdx.x;
    size_t base = (size_t)t * DD;
    float v0 = X[base + tid] + Y[base + tid];
    float v1 = X[base + tid + 256] + Y[base + tid + 256];
    float s = v0 + v1, ss = v0 * v0 + v1 * v1;
    __shared__ float rs[8], rss[8];
    for (int o = 16; o; o >>= 1) {
        s  += __shfl_down_sync(0xffffffffu, s, o);
        ss += __shfl_down_sync(0xffffffffu, ss, o);
    }
    int w = tid >> 5;
    if ((tid & 31) == 0) { rs[w] = s; rss[w] = ss; }
    __syncthreads();
    if (tid == 0) {
        float S1 = 0.f, S2 = 0.f;
        for (int i = 0; i < 8; i++) { S1 += rs[i]; S2 += rss[i]; }
        rs[0] = S1 / (float)DD;
        rss[0] = S2 / (float)DD;
    }
    __syncthreads();
    float mean = rs[0];
    float inv = rsqrtf(rss[0] - mean * mean + 1e-5f);
    float o0 = (v0 - mean) * inv * sc[tid] + bi[tid];
    float o1 = (v1 - mean) * inv * sc[tid + 256] + bi[tid + 256];
    X[base + tid] = o0;        XH[base + tid] = __float2half_rn(o0);
    X[base + tid + 256] = o1;  XH[base + tid + 256] = __float2half_rn(o1);
}

// final LN on token 0 + classifier head
__global__ void __launch_bounds__(256) final_k(
    const float* __restrict__ lnf_s, const float* __restrict__ lnf_b,
    const float* __restrict__ ow, const float* __restrict__ ob,
    float* __restrict__ out)
{
    int b = blockIdx.x, tid = threadIdx.x;
    size_t base = (size_t)b * SS * DD;
    float v0 = g_x[base + tid];
    float v1 = g_x[base + tid + 256];
    float s = v0 + v1, ss = v0 * v0 + v1 * v1;
    __shared__ float rs[8], rss[8];
    __shared__ float row[DD];
    for (int o = 16; o; o >>= 1) {
        s  += __shfl_down_sync(0xffffffffu, s, o);
        ss += __shfl_down_sync(0xffffffffu, ss, o);
    }
    int w = tid >> 5;
    if ((tid & 31) == 0) { rs[w] = s; rss[w] = ss; }
    __syncthreads();
    if (tid == 0) {
        float S1 = 0.f, S2 = 0.f;
        for (int i = 0; i < 8; i++) { S1 += rs[i]; S2 += rss[i]; }
        rs[0] = S1 / (float)DD;
        rss[0] = S2 / (float)DD;
    }
    __syncthreads();
    float mean = rs[0];
    float inv = rsqrtf(rss[0] - mean * mean + 1e-5f);
    row[tid]       = (v0 - mean) * inv * lnf_s[tid] + lnf_b[tid];
    row[tid + 256] = (v1 - mean) * inv * lnf_s[tid + 256] + lnf_b[tid + 256];
    __syncthreads();
    for (int c = 0; c < NCLS; c++) {
        float p = row[tid] * ow[tid * NCLS + c] + row[tid + 256] * ow[(tid + 256) * NCLS + c];
        for (int o = 16; o; o >>= 1) p += __shfl_down_sync(0xffffffffu, p, o);
        if ((tid & 31) == 0) rs[tid >> 5] = p;
        __syncthreads();
        if (tid == 0) {
            float t2 = 0.f;
            for (int i = 0; i < 8; i++) t2 += rs[i];
            out[b * NCLS + c] = t2 + ob[c];
        }
        __syncthreads();
    }
}

// ---------------- host driver ----------------
extern "C" void kernel_launch(void* const* d_in, const int* in_sizes, int n_in,
                              void* d_out, int out_size)
{
    const int*   inputs     = (const int*)  d_in[0];
    const float* input_mask = (const float*)d_in[1];
    const float* emb        = (const float*)d_in[2];
    const float* conv_w     = (const float*)d_in[3];
    const float* conv_b     = (const float*)d_in[4];
    const float* pos        = (const float*)d_in[5];
    const float* cls        = (const float*)d_in[6];
    const float* Wq         = (const float*)d_in[7];
    const float* bq         = (const float*)d_in[8];
    const float* Wk         = (const float*)d_in[9];
    const float* bk         = (const float*)d_in[10];
    const float* Wv         = (const float*)d_in[11];
    const float* bv         = (const float*)d_in[12];
    const float* Wo         = (const float*)d_in[13];
    const float* bo         = (const float*)d_in[14];
    const float* ln1_s      = (const float*)d_in[15];
    const float* ln1_b      = (const float*)d_in[16];
    const float* ln2_s      = (const float*)d_in[17];
    const float* ln2_b      = (const float*)d_in[18];
    const float* W1         = (const float*)d_in[19];
    const float* b1         = (const float*)d_in[20];
    const float* W2         = (const float*)d_in[21];
    const float* b2         = (const float*)d_in[22];
    const float* lnf_s      = (const float*)d_in[23];
    const float* lnf_b      = (const float*)d_in[24];
    const float* out_w      = (const float*)d_in[25];
    const float* out_b      = (const float*)d_in[26];
    float* out = (float*)d_out;

    float  *px, *pqkv, *py, *pbqkv;
    __half *pxh, *pattn, *ph, *pWqkv, *pWot, *pW1t, *pW2t, *pembt;
    cudaGetSymbolAddress((void**)&px,    g_x);
    cudaGetSymbolAddress((void**)&pxh,   g_xh);
    cudaGetSymbolAddress((void**)&pqkv,  g_qkv);
    cudaGetSymbolAddress((void**)&pattn, g_attn);
    cudaGetSymbolAddress((void**)&py,    g_y);
    cudaGetSymbolAddress((void**)&ph,    g_h);
    cudaGetSymbolAddress((void**)&pWqkv, g_Wqkv);
    cudaGetSymbolAddress((void**)&pbqkv, g_bqkv);
    cudaGetSymbolAddress((void**)&pWot,  g_Wot);
    cudaGetSymbolAddress((void**)&pW1t,  g_W1t);
    cudaGetSymbolAddress((void**)&pW2t,  g_W2t);
    cudaGetSymbolAddress((void**)&pembt, g_embt);

    cudaFuncSetAttribute(hgemm2_k<0>,   cudaFuncAttributeMaxDynamicSharedMemorySize, SMEMH);
    cudaFuncSetAttribute(hgemm2_k<1>,   cudaFuncAttributeMaxDynamicSharedMemorySize, SMEMH);
    cudaFuncSetAttribute(hgemm2_k<2>,   cudaFuncAttributeMaxDynamicSharedMemorySize, SMEMH);
    cudaFuncSetAttribute(conv_hgemm2_k, cudaFuncAttributeMaxDynamicSharedMemorySize, SMEMH);

    // prologue
    pack_convw_k<<<(int)(((size_t)DD*KCONV + 255) / 256), 256>>>(conv_w);
    half4_k<<<(32000 * DD / 4 + 255) / 256, 256>>>((const float4*)emb, pembt, 32000 * DD / 4);
    pack_qkv2_k<<<dim3(NQKV/32, DD/32, NLAY), dim3(32, 8)>>>(Wq, Wk, Wv);
    pack_qkvb_k<<<(NLAY * NQKV + 255) / 256, 256>>>(bq, bk, bv);
    pack_t2_k<<<dim3(DD/32, DD/32, NLAY),  dim3(32, 8)>>>(Wo, pWot, DD, DD);
    pack_t2_k<<<dim3(FFD/32, DD/32, NLAY), dim3(32, 8)>>>(W1, pW1t, DD, FFD);
    pack_t2_k<<<dim3(DD/32, FFD/32, NLAY), dim3(32, 8)>>>(W2, pW2t, FFD, DD);
    rope_tab_k<<<(SS * 32 + 255) / 256, 256>>>();
    lengths_k<<<BB, 256>>>(input_mask);
    zero_pad_k<<<((TPAD - TT) * DD + 255) / 256, 256>>>();
    init_cls_k<<<(BB * DD + 255) / 256, 256>>>(cls, pos);
    conv_hgemm2_k<<<dim3(DD / 256, MCONV / 128), 256, SMEMH>>>(inputs, conv_b, pos);

    dim3 gQKV(NQKV / 256, TPAD / 128);  // (6, 65)
    dim3 gD(DD / 256, TPAD / 128);      // (2, 65)
    dim3 gF(FFD / 256, TPAD / 128);     // (8, 65)

    for (int i = 0; i < NLAY; i++) {
        hgemm2_k<2><<<gQKV, 256, SMEMH>>>(pxh, pWqkv + (size_t)i*NQKV*DD,
                                          pbqkv + (size_t)i*NQKV, pqkv, NQKV, DD);
        kv3_k<<<dim3(BB * HH, KVPARTS), 256>>>();
        attn3_k<<<dim3(BB * HH, 9), 256>>>();
        hgemm2_k<0><<<gD, 256, SMEMH>>>(pattn, pWot + (size_t)i*DD*DD,
                                        bo + (size_t)i*DD, py, DD, DD);
        ln_k<<<TPAD, 256>>>(py, ln1_s + (size_t)i*DD, ln1_b + (size_t)i*DD, px, pxh);
        hgemm2_k<1><<<gF, 256, SMEMH>>>(pxh, pW1t + (size_t)i*FFD*DD,
                                        b1 + (size_t)i*FFD, ph, FFD, DD);
        hgemm2_k<0><<<gD, 256, SMEMH>>>(ph, pW2t + (size_t)i*DD*FFD,
                                        b2 + (size_t)i*DD, py, DD, FFD);
        ln_k<<<TPAD, 256>>>(py, ln2_s + (size_t)i*DD, ln2_b + (size_t)i*DD, px, pxh);
    }

    final_k<<<BB, 256>>>(lnf_s, lnf_b, out_w, out_b, out);
}

// round 12
// speedup vs baseline: 3.6065x; 1.0301x over previous
#include <cuda_runtime.h>
#include <cuda_fp16.h>
#include <mma.h>
#include <math.h>
#include <stdint.h>

using namespace nvcuda;

#define BB   32
#define LL   4096
#define PP   16
#define SS   257
#define DD   512
#define HH   8
#define DHD  64
#define NLAY 8
#define FFD  2048
#define NCLS 4
#define TT   (BB*SS)      /* 8224 */
#define TPAD 8320         /* 65*128 */
#define KCONV 8192
#define MCONV 8192
#define NQKV 1536
#define KVPARTS 4
#define SPART 72

// ---------------- scratch (device globals; no allocations) ----------------
__device__ float  g_x[TPAD*DD];
__device__ __half g_xh[TPAD*DD];
__device__ __half g_qkvh[(size_t)TPAD*NQKV];   // fp16 q,k (post rope/elu) + v
__device__ __half g_attn[TPAD*DD];
__device__ float  g_y[TPAD*DD];
__device__ __half g_h[(size_t)TPAD*FFD];
__device__ float  g_kvp[KVPARTS][BB*HH*DHD*DHD];
__device__ float  g_ksump[KVPARTS][BB*HH*DHD];
__device__ float  g_len[BB];
__device__ float  g_cs[SS*32*2];
// packed fp16 weights ([N][K], K-major)
__device__ __half g_Wc[(size_t)DD*KCONV];
__device__ __half g_embt[(size_t)32000*DD];
__device__ __half g_Wqkv[(size_t)NLAY*NQKV*DD];
__device__ float  g_bqkv[NLAY*NQKV];
__device__ __half g_Wot[(size_t)NLAY*DD*DD];
__device__ __half g_W1t[(size_t)NLAY*FFD*DD];
__device__ __half g_W2t[(size_t)NLAY*DD*FFD];

// ---------------- helpers ----------------
__device__ __forceinline__ void cpa16(const __half* dst_smem, const __half* src) {
    uint32_t d = (uint32_t)__cvta_generic_to_shared(dst_smem);
    asm volatile("cp.async.cg.shared.global [%0], [%1], 16;" :: "r"(d), "l"(src) : "memory");
}
#define CP_COMMIT() asm volatile("cp.async.commit_group;" ::: "memory")
#define CP_WAIT1()  asm volatile("cp.async.wait_group 1;" ::: "memory")

// ================= fp16 wmma GEMM, tile 128x256, BK=64, 3-stage =================
#define ALD   72                        /* halves per SMEM row (144B, LDSM conflict-free) */
#define ASTG  (128*ALD)
#define BSTG  (256*ALD)
#define STGH  (ASTG+BSTG)
#define STGB  (STGH*2)                  /* 55296 bytes per stage */
#define SMEMH (3*STGB)                  /* 165888 bytes */

#define HG2_ISSUE(CH, ST, APTR, BPTR, KDIM) do {                                  \
    __half* As_ = (__half*)(sbuf + (ST)*STGB);                                    \
    __half* Bs_ = As_ + ASTG;                                                     \
    int k0_ = (CH) << 6;                                                          \
    _Pragma("unroll") for (int t_ = 0; t_ < 4; t_++) {                            \
        int idx_ = tid + t_*256; int row_ = idx_ >> 3, c_ = (idx_ & 7) * 8;       \
        cpa16(As_ + row_*ALD + c_, (APTR) + (size_t)(m0 + row_)*(KDIM) + k0_ + c_); } \
    _Pragma("unroll") for (int t_ = 0; t_ < 8; t_++) {                            \
        int idx_ = tid + t_*256; int row_ = idx_ >> 3, c_ = (idx_ & 7) * 8;       \
        cpa16(Bs_ + row_*ALD + c_, (BPTR) + (size_t)(n0 + row_)*(KDIM) + k0_ + c_); } \
} while (0)

#define HG2_COMP(ST) do {                                                         \
    const __half* As_ = (const __half*)(sbuf + (ST)*STGB);                        \
    const __half* Bs_ = As_ + ASTG;                                               \
    _Pragma("unroll") for (int kk = 0; kk < 4; kk++) {                            \
        wmma::fragment<wmma::matrix_a,16,16,16,__half,wmma::row_major> af[4];     \
        wmma::fragment<wmma::matrix_b,16,16,16,__half,wmma::col_major> bf[4];     \
        _Pragma("unroll") for (int i = 0; i < 4; i++)                             \
            wmma::load_matrix_sync(af[i], As_ + (wm*64 + i*16)*ALD + kk*16, ALD); \
        _Pragma("unroll") for (int j = 0; j < 4; j++)                             \
            wmma::load_matrix_sync(bf[j], Bs_ + (wn*64 + j*16)*ALD + kk*16, ALD); \
        _Pragma("unroll") for (int i = 0; i < 4; i++)                             \
            _Pragma("unroll") for (int j = 0; j < 4; j++)                         \
                wmma::mma_sync(acc[i][j], af[i], bf[j], acc[i][j]);               \
    }                                                                             \
} while (0)

// EPI 0: float out + bias   1: half out + bias + gelu   2: qkv half out (bias+rope+elu+mask)
template<int EPI>
__global__ void __launch_bounds__(256) hgemm2_k(
    const __half* __restrict__ A, const __half* __restrict__ Bt,
    const float* __restrict__ bias, void* __restrict__ Cv,
    int N, int K)
{
    extern __shared__ char sbuf[];
    int tid = threadIdx.x, wid = tid >> 5, lane = tid & 31;
    int wm = wid >> 2, wn = wid & 3;
    int m0 = blockIdx.y * 128, n0 = blockIdx.x * 256;
    int KT = K >> 6;

    wmma::fragment<wmma::accumulator,16,16,16,float> acc[4][4];
#pragma unroll
    for (int i = 0; i < 4; i++)
#pragma unroll
        for (int j = 0; j < 4; j++) wmma::fill_fragment(acc[i][j], 0.f);

    for (int s = 0; s < 2; s++) { if (s < KT) HG2_ISSUE(s, s, A, Bt, K); CP_COMMIT(); }
    for (int c = 0; c < KT; c++) {
        CP_WAIT1();
        __syncthreads();
        if (c + 2 < KT) HG2_ISSUE(c + 2, (c + 2) % 3, A, Bt, K);
        CP_COMMIT();
        HG2_COMP(c % 3);
    }
    __syncthreads();

    if (EPI == 2) {
        // warp tile N=64 == one head; rope partner c^32 inside the tile
        float* st = (float*)sbuf + wid * (16 * 68);
        int nb = n0 + wn * 64;
        int wtype = nb >> 9;          // 0=q 1=k 2=v
#pragma unroll
        for (int i = 0; i < 4; i++) {
#pragma unroll
            for (int j = 0; j < 4; j++)
                wmma::store_matrix_sync(st + j * 16, acc[i][j], 68, wmma::mem_row_major);
            __syncwarp();
#pragma unroll
            for (int e = 0; e < 32; e++) {
                int idx = e * 32 + lane;
                int r = idx >> 6, c = idx & 63;
                int m = m0 + wm*64 + i*16 + r;
                int n = nb + c;
                float val = st[r*68 + c] + bias[n];
                float outv;
                if (wtype < 2) {
                    int s = m % SS, b = m / SS;
                    if (b > BB - 1) b = BB - 1;
                    int jj = c & 31;
                    float cs = g_cs[(s*32 + jj)*2];
                    float sn = g_cs[(s*32 + jj)*2 + 1];
                    float partner = st[r*68 + (c ^ 32)] + bias[nb + (c ^ 32)];
                    float sgn = (c < 32) ? -1.f : 1.f;
                    float rot = val * cs + sgn * partner * sn;
                    float f = rot > 0.f ? rot + 1.f : expf(rot);
                    if (wtype == 1) f *= ((float)s < g_len[b]) ? 1.f : 0.f;
                    outv = f;
                } else {
                    outv = val;
                }
                g_qkvh[(size_t)m * NQKV + n] = __float2half_rn(outv);
            }
            __syncwarp();
        }
        return;
    }

    float* stg = (float*)sbuf + wid * 16 * 20;
#pragma unroll
    for (int i = 0; i < 4; i++)
#pragma unroll
        for (int j = 0; j < 4; j++) {
            wmma::store_matrix_sync(stg, acc[i][j], 20, wmma::mem_row_major);
            __syncwarp();
#pragma unroll
            for (int e = 0; e < 8; e++) {
                int idx = lane * 8 + e;
                int r = idx >> 4, cc = idx & 15;
                int m = m0 + wm*64 + i*16 + r;
                int n = n0 + wn*64 + j*16 + cc;
                float val = stg[r*20 + cc] + bias[n];
                if (EPI == 1) {
                    val = 0.5f * val * (1.0f + erff(val * 0.70710678118654752f));
                    ((__half*)Cv)[(size_t)m * N + n] = __float2half_rn(val);
                } else {
                    ((float*)Cv)[(size_t)m * N + n] = val;
                }
            }
            __syncwarp();
        }
}

// ---------------- conv-embedding GEMM (gathered A rows) ----------------
__global__ void __launch_bounds__(256) conv_hgemm2_k(
    const int* __restrict__ tok, const float* __restrict__ conv_b,
    const float* __restrict__ pos)
{
    extern __shared__ char sbuf[];
    __shared__ int toks[16][128];
    int tid = threadIdx.x, wid = tid >> 5, lane = tid & 31;
    int wm = wid >> 2, wn = wid & 3;
    int m0 = blockIdx.y * 128, n0 = blockIdx.x * 256;
    const int KT = KCONV >> 6;   // 128

    if (tid < 128) {
        int r = m0 + tid;
        int b = r >> 8, nn = r & 255;
        int base = b * LL + nn * PP;
#pragma unroll
        for (int p = 0; p < 16; p++) toks[p][tid] = tok[base + p];
    }
    __syncthreads();

    wmma::fragment<wmma::accumulator,16,16,16,float> acc[4][4];
#pragma unroll
    for (int i = 0; i < 4; i++)
#pragma unroll
        for (int j = 0; j < 4; j++) wmma::fill_fragment(acc[i][j], 0.f);

// BK=64 stays inside one p (k0&511 spans [i0, i0+64), i0 multiple of 64 < 512)
#define CV2_ISSUE(CH, ST) do {                                                    \
    __half* As_ = (__half*)(sbuf + (ST)*STGB);                                    \
    __half* Bs_ = As_ + ASTG;                                                     \
    int k0_ = (CH) << 6; int p_ = k0_ >> 9, i0_ = k0_ & 511;                      \
    _Pragma("unroll") for (int t_ = 0; t_ < 4; t_++) {                            \
        int idx_ = tid + t_*256; int row_ = idx_ >> 3, c_ = (idx_ & 7) * 8;       \
        int tk_ = toks[p_][row_];                                                 \
        cpa16(As_ + row_*ALD + c_, g_embt + (size_t)tk_*DD + i0_ + c_); }         \
    _Pragma("unroll") for (int t_ = 0; t_ < 8; t_++) {                            \
        int idx_ = tid + t_*256; int row_ = idx_ >> 3, c_ = (idx_ & 7) * 8;       \
        cpa16(Bs_ + row_*ALD + c_, g_Wc + (size_t)(n0 + row_)*KCONV + k0_ + c_); } \
} while (0)

    for (int s = 0; s < 2; s++) { CV2_ISSUE(s, s); CP_COMMIT(); }
    for (int c = 0; c < KT; c++) {
        CP_WAIT1();
        __syncthreads();
        if (c + 2 < KT) CV2_ISSUE(c + 2, (c + 2) % 3);
        CP_COMMIT();
        HG2_COMP(c % 3);
    }
    __syncthreads();

    float* stg = (float*)sbuf + wid * 16 * 20;
#pragma unroll
    for (int i = 0; i < 4; i++)
#pragma unroll
        for (int j = 0; j < 4; j++) {
            wmma::store_matrix_sync(stg, acc[i][j], 20, wmma::mem_row_major);
            __syncwarp();
#pragma unroll
            for (int e = 0; e < 8; e++) {
                int idx = lane * 8 + e;
                int r = idx >> 4, cc = idx & 15;
                int mrow = m0 + wm*64 + i*16 + r;
                int b = mrow >> 8, nn = mrow & 255;
                int s = nn + 1;
                int n = n0 + wn*64 + j*16 + cc;
                float val = stg[r*20 + cc] + conv_b[n] + pos[(size_t)s*DD + n];
                size_t o = ((size_t)(b*SS + s))*DD + n;
                g_x[o]  = val;
                g_xh[o] = __float2half_rn(val);
            }
            __syncwarp();
        }
}

// ---------------- prologue pack kernels ----------------
__global__ void half4_k(const float4* __restrict__ src, __half* __restrict__ dst, int n4) {
    int i = blockIdx.x * 256 + threadIdx.x;
    if (i >= n4) return;
    float4 v = src[i];
    __half2 a = __floats2half2_rn(v.x, v.y);
    __half2 b = __floats2half2_rn(v.z, v.w);
    __half2* d = (__half2*)(dst + (size_t)i * 4);
    d[0] = a; d[1] = b;
}

__global__ void pack_t2_k(const float* __restrict__ src, __half* __restrict__ dst,
                          int K, int N) {
    __shared__ float tile[32][33];
    int n0 = blockIdx.x * 32, k0 = blockIdx.y * 32;
    size_t per = (size_t)K * N;
    const float* s = src + (size_t)blockIdx.z * per;
    __half* d = dst + (size_t)blockIdx.z * per;
    int tx = threadIdx.x, ty = threadIdx.y;
#pragma unroll
    for (int r = 0; r < 4; r++) {
        int k = k0 + ty + r * 8;
        tile[ty + r * 8][tx] = s[(size_t)k * N + n0 + tx];
    }
    __syncthreads();
#pragma unroll
    for (int r = 0; r < 4; r++) {
        int n = n0 + ty + r * 8;
        d[(size_t)n * K + k0 + tx] = __float2half_rn(tile[tx][ty + r * 8]);
    }
}

__global__ void pack_qkv2_k(const float* __restrict__ Wq, const float* __restrict__ Wk,
                            const float* __restrict__ Wv) {
    __shared__ float tile[32][33];
    int n0 = blockIdx.x * 32, k0 = blockIdx.y * 32;
    int l = blockIdx.z;
    int w = n0 >> 9, nn0 = n0 & 511;
    const float* W = ((w == 0) ? Wq : (w == 1) ? Wk : Wv) + (size_t)l * DD * DD;
    __half* d = g_Wqkv + (size_t)l * NQKV * DD;
    int tx = threadIdx.x, ty = threadIdx.y;
#pragma unroll
    for (int r = 0; r < 4; r++) {
        int k = k0 + ty + r * 8;
        tile[ty + r * 8][tx] = W[(size_t)k * DD + nn0 + tx];
    }
    __syncthreads();
#pragma unroll
    for (int r = 0; r < 4; r++) {
        int n = n0 + ty + r * 8;
        d[(size_t)n * DD + k0 + tx] = __float2half_rn(tile[tx][ty + r * 8]);
    }
}

__global__ void pack_qkvb_k(const float* __restrict__ bq, const float* __restrict__ bk,
                            const float* __restrict__ bv) {
    int idx = blockIdx.x * 256 + threadIdx.x;
    if (idx >= NLAY * NQKV) return;
    int i = idx / NQKV, n = idx % NQKV;
    int w = n >> 9, nn = n & 511;
    const float* Bv = (w == 0) ? bq : (w == 1) ? bk : bv;
    g_bqkv[idx] = Bv[i * DD + nn];
}

// coalesced conv-w pack: one block per o row; g_Wc[o][p*512+i] = conv_w[o][i][p]
__global__ void __launch_bounds__(256) pack_convw2_k(const float* __restrict__ cw) {
    __shared__ float row[KCONV];
    int o = blockIdx.x;
    int tid = threadIdx.x;
    for (int i = tid; i < KCONV; i += 256) row[i] = cw[(size_t)o * KCONV + i];
    __syncthreads();
    for (int k = tid; k < KCONV; k += 256) {
        int i = k & 511, p = k >> 9;
        g_Wc[(size_t)o * KCONV + k] = __float2half_rn(row[i * PP + p]);
    }
}

__global__ void rope_tab_k() {
    int idx = blockIdx.x * 256 + threadIdx.x;
    if (idx >= SS * 32) return;
    int s = idx >> 5, j = idx & 31;
    float ang = (float)s * exp2f(-(float)j * (13.287712379549449f / 32.f));
    g_cs[idx * 2]     = cosf(ang);
    g_cs[idx * 2 + 1] = sinf(ang);
}

// ---------------- small kernels ----------------
__global__ void lengths_k(const float* __restrict__ mask) {
    __shared__ float sh[256];
    int b = blockIdx.x;
    float s = 0.f;
    for (int i = threadIdx.x; i < LL; i += 256) s += mask[(size_t)b * LL + i];
    sh[threadIdx.x] = s;
    __syncthreads();
    for (int st = 128; st > 0; st >>= 1) {
        if (threadIdx.x < st) sh[threadIdx.x] += sh[threadIdx.x + st];
        __syncthreads();
    }
    if (threadIdx.x == 0) g_len[b] = ceilf((sh[0] + 1.0f) / (float)PP);
}

__global__ void init_cls_k(const float* __restrict__ cls, const float* __restrict__ pos) {
    int idx = blockIdx.x * blockDim.x + threadIdx.x;
    if (idx >= BB * DD) return;
    int b = idx >> 9, d = idx & 511;
    float v = cls[d] + pos[d];
    size_t o = (size_t)b * SS * DD + d;
    g_x[o] = v; g_xh[o] = __float2half_rn(v);
}

__global__ void zero_pad_k() {
    int i = blockIdx.x * blockDim.x + threadIdx.x;
    int n = (TPAD - TT) * DD;
    if (i < n) {
        g_x[(size_t)TT * DD + i] = 0.f;
        g_xh[(size_t)TT * DD + i] = __float2half_rn(0.f);
        g_attn[(size_t)TT * DD + i] = __float2half_rn(0.f);
    }
}

// kv partial: part p covers s in [p*SPART, min(SS, (p+1)*SPART))
__global__ void __launch_bounds__(256) kv3_k() {
    int bh = blockIdx.x, part = blockIdx.y;
    int b = bh >> 3, h = bh & 7;
    int sbeg = part * SPART;
    int send = min(SS, sbeg + SPART);
    __shared__ float kf_sh[8][64], v_sh[8][64];
    int tid = threadIdx.x;
    int m = tid & 63, dg = tid >> 6;
    float acc[16];
#pragma unroll
    for (int jj = 0; jj < 16; jj++) acc[jj] = 0.f;
    float ksum = 0.f;
    for (int s0 = sbeg; s0 < send; s0 += 8) {
        __syncthreads();
#pragma unroll
        for (int u = 0; u < 4; u++) {
            int idx = tid + u * 256;
            int which = idx >> 9;
            int rr = (idx >> 6) & 7;
            int cc = idx & 63;
            int s = s0 + rr;
            float val = (s < send)
                ? __half2float(g_qkvh[(size_t)(b*SS + s)*NQKV + (which ? 1024 : 512) + h*64 + cc])
                : 0.f;
            if (which) v_sh[rr][cc] = val; else kf_sh[rr][cc] = val;
        }
        __syncthreads();
#pragma unroll
        for (int r = 0; r < 8; r++) {
            float vr = v_sh[r][m];
#pragma unroll
            for (int jj = 0; jj < 16; jj++) acc[jj] += kf_sh[r][dg*16 + jj] * vr;
        }
        if (tid < 64) {
#pragma unroll
            for (int r = 0; r < 8; r++) ksum += kf_sh[r][tid];
        }
    }
#pragma unroll
    for (int jj = 0; jj < 16; jj++)
        g_kvp[part][((size_t)bh * DHD + dg*16 + jj) * DHD + m] = acc[jj];
    if (tid < 64) g_ksump[part][bh * DHD + tid] = ksum;
}

// attn chunk: block (bh, ch) handles tokens [ch*32, min(SS, ch*32+32))
__global__ void __launch_bounds__(256) attn3_k() {
    int bh = blockIdx.x, ch = blockIdx.y;
    int b = bh >> 3, h = bh & 7;
    int sbeg = ch * 32;
    int send = min(SS, sbeg + 32);
    __shared__ float kvs[DHD * DHD];
    __shared__ float ks[DHD];
    __shared__ float q4[4][64];
    __shared__ float red[4][64];
    __shared__ float part[4][4][64];
    __shared__ float zsh[4];
    int tid = threadIdx.x, wid = tid >> 5, lane = tid & 31;
    int m = tid & 63, dg = tid >> 6;
    for (int i = tid; i < DHD * DHD; i += 256) {
        size_t o = (size_t)bh * DHD * DHD + i;
        kvs[i] = g_kvp[0][o] + g_kvp[1][o] + g_kvp[2][o] + g_kvp[3][o];
    }
    if (tid < 64) {
        int o = bh * DHD + tid;
        ks[tid] = g_ksump[0][o] + g_ksump[1][o] + g_ksump[2][o] + g_ksump[3][o];
    }
    __syncthreads();
    for (int s0 = sbeg; s0 < send; s0 += 4) {
        int r = tid >> 6, c = tid & 63;
        int sr = s0 + r;
        q4[r][c] = (sr < send)
            ? __half2float(g_qkvh[(size_t)(b*SS + sr)*NQKV + h*64 + c]) : 0.f;
        __syncthreads();
        red[r][c] = q4[r][c] * ks[c];
        __syncthreads();
        if (wid < 4) {
            float v = red[wid][lane] + red[wid][lane + 32];
            for (int o = 16; o; o >>= 1) v += __shfl_down_sync(0xffffffffu, v, o);
            if (lane == 0) zsh[wid] = 1.f / (v + 1e-6f);
        }
        float a[4] = {0.f, 0.f, 0.f, 0.f};
#pragma unroll
        for (int jj = 0; jj < 16; jj++) {
            int d = dg*16 + jj;
            float kc = kvs[d * DHD + m];
#pragma unroll
            for (int rr = 0; rr < 4; rr++) a[rr] += q4[rr][d] * kc;
        }
#pragma unroll
        for (int rr = 0; rr < 4; rr++) part[dg][rr][m] = a[rr];
        __syncthreads();
        {
            int rr = tid >> 6, mm = tid & 63;
            int s = s0 + rr;
            if (s < send) {
                float o = (part[0][rr][mm] + part[1][rr][mm] +
                           part[2][rr][mm] + part[3][rr][mm]) * zsh[rr];
                g_attn[((size_t)(b*SS + s))*DD + h*64 + mm] = __float2half_rn(o);
            }
        }
        __syncthreads();
    }
}

// X = LN(X + Y); writes fp32 X and fp16 XH
__global__ void __launch_bounds__(256) ln_k(
    const float* __restrict__ Y, const float* __restrict__ sc,
    const float* __restrict__ bi, float* __restrict__ X, __half* __restrict__ XH)
{
    int t = blockIdx.x, tid = threadIdx.x;
    size_t base = (size_t)t * DD;
    float v0 = X[base + tid] + Y[base + tid];
    float v1 = X[base + tid + 256] + Y[base + tid + 256];
    float s = v0 + v1, ss = v0 * v0 + v1 * v1;
    __shared__ float rs[8], rss[8];
    for (int o = 16; o; o >>= 1) {
        s  += __shfl_down_sync(0xffffffffu, s, o);
        ss += __shfl_down_sync(0xffffffffu, ss, o);
    }
    int w = tid >> 5;
    if ((tid & 31) == 0) { rs[w] = s; rss[w] = ss; }
    __syncthreads();
    if (tid == 0) {
        float S1 = 0.f, S2 = 0.f;
        for (int i = 0; i < 8; i++) { S1 += rs[i]; S2 += rss[i]; }
        rs[0] = S1 / (float)DD;
        rss[0] = S2 / (float)DD;
    }
    __syncthreads();
    float mean = rs[0];
    float inv = rsqrtf(rss[0] - mean * mean + 1e-5f);
    float o0 = (v0 - mean) * inv * sc[tid] + bi[tid];
    float o1 = (v1 - mean) * inv * sc[tid + 256] + bi[tid + 256];
    X[base + tid] = o0;        XH[base + tid] = __float2half_rn(o0);
    X[base + tid + 256] = o1;  XH[base + tid + 256] = __float2half_rn(o1);
}

// final LN on token 0 + classifier head
__global__ void __launch_bounds__(256) final_k(
    const float* __restrict__ lnf_s, const float* __restrict__ lnf_b,
    const float* __restrict__ ow, const float* __restrict__ ob,
    float* __restrict__ out)
{
    int b = blockIdx.x, tid = threadIdx.x;
    size_t base = (size_t)b * SS * DD;
    float v0 = g_x[base + tid];
    float v1 = g_x[base + tid + 256];
    float s = v0 + v1, ss = v0 * v0 + v1 * v1;
    __shared__ float rs[8], rss[8];
    __shared__ float row[DD];
    for (int o = 16; o; o >>= 1) {
        s  += __shfl_down_sync(0xffffffffu, s, o);
        ss += __shfl_down_sync(0xffffffffu, ss, o);
    }
    int w = tid >> 5;
    if ((tid & 31) == 0) { rs[w] = s; rss[w] = ss; }
    __syncthreads();
    if (tid == 0) {
        float S1 = 0.f, S2 = 0.f;
        for (int i = 0; i < 8; i++) { S1 += rs[i]; S2 += rss[i]; }
        rs[0] = S1 / (float)DD;
        rss[0] = S2 / (float)DD;
    }
    __syncthreads();
    float mean = rs[0];
    float inv = rsqrtf(rss[0] - mean * mean + 1e-5f);
    row[tid]       = (v0 - mean) * inv * lnf_s[tid] + lnf_b[tid];
    row[tid + 256] = (v1 - mean) * inv * lnf_s[tid + 256] + lnf_b[tid + 256];
    __syncthreads();
    for (int c = 0; c < NCLS; c++) {
        float p = row[tid] * ow[tid * NCLS + c] + row[tid + 256] * ow[(tid + 256) * NCLS + c];
        for (int o = 16; o; o >>= 1) p += __shfl_down_sync(0xffffffffu, p, o);
        if ((tid & 31) == 0) rs[tid >> 5] = p;
        __syncthreads();
        if (tid == 0) {
            float t2 = 0.f;
            for (int i = 0; i < 8; i++) t2 += rs[i];
            out[b * NCLS + c] = t2 + ob[c];
        }
        __syncthreads();
    }
}

// ---------------- host driver ----------------
extern "C" void kernel_launch(void* const* d_in, const int* in_sizes, int n_in,
                              void* d_out, int out_size)
{
    const int*   inputs     = (const int*)  d_in[0];
    const float* input_mask = (const float*)d_in[1];
    const float* emb        = (const float*)d_in[2];
    const float* conv_w     = (const float*)d_in[3];
    const float* conv_b     = (const float*)d_in[4];
    const float* pos        = (const float*)d_in[5];
    const float* cls        = (const float*)d_in[6];
    const float* Wq         = (const float*)d_in[7];
    const float* bq         = (const float*)d_in[8];
    const float* Wk         = (const float*)d_in[9];
    const float* bk         = (const float*)d_in[10];
    const float* Wv         = (const float*)d_in[11];
    const float* bv         = (const float*)d_in[12];
    const float* Wo         = (const float*)d_in[13];
    const float* bo         = (const float*)d_in[14];
    const float* ln1_s      = (const float*)d_in[15];
    const float* ln1_b      = (const float*)d_in[16];
    const float* ln2_s      = (const float*)d_in[17];
    const float* ln2_b      = (const float*)d_in[18];
    const float* W1         = (const float*)d_in[19];
    const float* b1         = (const float*)d_in[20];
    const float* W2         = (const float*)d_in[21];
    const float* b2         = (const float*)d_in[22];
    const float* lnf_s      = (const float*)d_in[23];
    const float* lnf_b      = (const float*)d_in[24];
    const float* out_w      = (const float*)d_in[25];
    const float* out_b      = (const float*)d_in[26];
    float* out = (float*)d_out;

    float  *px, *py, *pbqkv;
    __half *pxh, *pattn, *ph, *pWqkv, *pWot, *pW1t, *pW2t, *pembt;
    cudaGetSymbolAddress((void**)&px,    g_x);
    cudaGetSymbolAddress((void**)&pxh,   g_xh);
    cudaGetSymbolAddress((void**)&pattn, g_attn);
    cudaGetSymbolAddress((void**)&py,    g_y);
    cudaGetSymbolAddress((void**)&ph,    g_h);
    cudaGetSymbolAddress((void**)&pWqkv, g_Wqkv);
    cudaGetSymbolAddress((void**)&pbqkv, g_bqkv);
    cudaGetSymbolAddress((void**)&pWot,  g_Wot);
    cudaGetSymbolAddress((void**)&pW1t,  g_W1t);
    cudaGetSymbolAddress((void**)&pW2t,  g_W2t);
    cudaGetSymbolAddress((void**)&pembt, g_embt);

    cudaFuncSetAttribute(hgemm2_k<0>,   cudaFuncAttributeMaxDynamicSharedMemorySize, SMEMH);
    cudaFuncSetAttribute(hgemm2_k<1>,   cudaFuncAttributeMaxDynamicSharedMemorySize, SMEMH);
    cudaFuncSetAttribute(hgemm2_k<2>,   cudaFuncAttributeMaxDynamicSharedMemorySize, SMEMH);
    cudaFuncSetAttribute(conv_hgemm2_k, cudaFuncAttributeMaxDynamicSharedMemorySize, SMEMH);

    // prologue
    pack_convw2_k<<<DD, 256>>>(conv_w);
    half4_k<<<(32000 * DD / 4 + 255) / 256, 256>>>((const float4*)emb, pembt, 32000 * DD / 4);
    pack_qkv2_k<<<dim3(NQKV/32, DD/32, NLAY), dim3(32, 8)>>>(Wq, Wk, Wv);
    pack_qkvb_k<<<(NLAY * NQKV + 255) / 256, 256>>>(bq, bk, bv);
    pack_t2_k<<<dim3(DD/32, DD/32, NLAY),  dim3(32, 8)>>>(Wo, pWot, DD, DD);
    pack_t2_k<<<dim3(FFD/32, DD/32, NLAY), dim3(32, 8)>>>(W1, pW1t, DD, FFD);
    pack_t2_k<<<dim3(DD/32, FFD/32, NLAY), dim3(32, 8)>>>(W2, pW2t, FFD, DD);
    rope_tab_k<<<(SS * 32 + 255) / 256, 256>>>();
    lengths_k<<<BB, 256>>>(input_mask);
    zero_pad_k<<<((TPAD - TT) * DD + 255) / 256, 256>>>();
    init_cls_k<<<(BB * DD + 255) / 256, 256>>>(cls, pos);
    conv_hgemm2_k<<<dim3(DD / 256, MCONV / 128), 256, SMEMH>>>(inputs, conv_b, pos);

    dim3 gQKV(NQKV / 256, TPAD / 128);  // (6, 65)
    dim3 gD(DD / 256, TPAD / 128);      // (2, 65)
    dim3 gF(FFD / 256, TPAD / 128);     // (8, 65)

    for (int i = 0; i < NLAY; i++) {
        hgemm2_k<2><<<gQKV, 256, SMEMH>>>(pxh, pWqkv + (size_t)i*NQKV*DD,
                                          pbqkv + (size_t)i*NQKV, nullptr, NQKV, DD);
        kv3_k<<<dim3(BB * HH, KVPARTS), 256>>>();
        attn3_k<<<dim3(BB * HH, 9), 256>>>();
        hgemm2_k<0><<<gD, 256, SMEMH>>>(pattn, pWot + (size_t)i*DD*DD,
                                        bo + (size_t)i*DD, py, DD, DD);
        ln_k<<<TPAD, 256>>>(py, ln1_s + (size_t)i*DD, ln1_b + (size_t)i*DD, px, pxh);
        hgemm2_k<1><<<gF, 256, SMEMH>>>(pxh, pW1t + (size_t)i*FFD*DD,
                                        b1 + (size_t)i*FFD, ph, FFD, DD);
        hgemm2_k<0><<<gD, 256, SMEMH>>>(ph, pW2t + (size_t)i*DD*FFD,
                                        b2 + (size_t)i*DD, py, DD, FFD);
        ln_k<<<TPAD, 256>>>(py, ln2_s + (size_t)i*DD, ln2_b + (size_t)i*DD, px, pxh);
    }

    final_k<<<BB, 256>>>(lnf_s, lnf_b, out_w, out_b, out);
}

// round 13
// speedup vs baseline: 3.6941x; 1.0243x over previous
#include <cuda_runtime.h>
#include <cuda_fp16.h>
#include <mma.h>
#include <math.h>
#include <stdint.h>

using namespace nvcuda;

#define BB   32
#define LL   4096
#define PP   16
#define SS   257
#define DD   512
#define HH   8
#define DHD  64
#define NLAY 8
#define FFD  2048
#define NCLS 4
#define TT   (BB*SS)      /* 8224 */
#define TPAD 8320         /* 65*128 */
#define KCONV 8192
#define MCONV 8192
#define NQKV 1536
#define KVPARTS 4
#define SPART 72

// ---------------- scratch (device globals; no allocations) ----------------
__device__ float  g_x[TPAD*DD];
__device__ __half g_xh[TPAD*DD];
__device__ __half g_qkvh[(size_t)TPAD*NQKV];   // fp16 q,k (post rope/elu) + v
__device__ __half g_attn[TPAD*DD];
__device__ __half g_h[(size_t)TPAD*FFD];
__device__ float  g_kvp[KVPARTS][BB*HH*DHD*DHD];
__device__ float  g_ksump[KVPARTS][BB*HH*DHD];
__device__ float  g_len[BB];
__device__ float  g_cs[SS*32*2];
// packed fp16 weights ([N][K], K-major)
__device__ __half g_Wc[(size_t)DD*KCONV];
__device__ __half g_embt[(size_t)32000*DD];
__device__ __half g_Wqkv[(size_t)NLAY*NQKV*DD];
__device__ float  g_bqkv[NLAY*NQKV];
__device__ __half g_Wot[(size_t)NLAY*DD*DD];
__device__ __half g_W1t[(size_t)NLAY*FFD*DD];
__device__ __half g_W2t[(size_t)NLAY*DD*FFD];

// ---------------- helpers ----------------
__device__ __forceinline__ void cpa16(const __half* dst_smem, const __half* src) {
    uint32_t d = (uint32_t)__cvta_generic_to_shared(dst_smem);
    asm volatile("cp.async.cg.shared.global [%0], [%1], 16;" :: "r"(d), "l"(src) : "memory");
}
#define CP_COMMIT() asm volatile("cp.async.commit_group;" ::: "memory")
#define CP_WAIT1()  asm volatile("cp.async.wait_group 1;" ::: "memory")

// ================= fp16 wmma GEMM, tile 128x256, BK=64, 3-stage =================
#define ALD   72
#define ASTG  (128*ALD)
#define BSTG  (256*ALD)
#define STGH  (ASTG+BSTG)
#define STGB  (STGH*2)                  /* 55296 bytes per stage */
#define SMEMH (3*STGB)                  /* 165888 bytes */

#define HG2_ISSUE(CH, ST, APTR, BPTR, KDIM) do {                                  \
    __half* As_ = (__half*)(sbuf + (ST)*STGB);                                    \
    __half* Bs_ = As_ + ASTG;                                                     \
    int k0_ = (CH) << 6;                                                          \
    _Pragma("unroll") for (int t_ = 0; t_ < 4; t_++) {                            \
        int idx_ = tid + t_*256; int row_ = idx_ >> 3, c_ = (idx_ & 7) * 8;       \
        cpa16(As_ + row_*ALD + c_, (APTR) + (size_t)(m0 + row_)*(KDIM) + k0_ + c_); } \
    _Pragma("unroll") for (int t_ = 0; t_ < 8; t_++) {                            \
        int idx_ = tid + t_*256; int row_ = idx_ >> 3, c_ = (idx_ & 7) * 8;       \
        cpa16(Bs_ + row_*ALD + c_, (BPTR) + (size_t)(n0 + row_)*(KDIM) + k0_ + c_); } \
} while (0)

#define HG2_COMP(ST) do {                                                         \
    const __half* As_ = (const __half*)(sbuf + (ST)*STGB);                        \
    const __half* Bs_ = As_ + ASTG;                                               \
    _Pragma("unroll") for (int kk = 0; kk < 4; kk++) {                            \
        wmma::fragment<wmma::matrix_a,16,16,16,__half,wmma::row_major> af[4];     \
        wmma::fragment<wmma::matrix_b,16,16,16,__half,wmma::col_major> bf[4];     \
        _Pragma("unroll") for (int i = 0; i < 4; i++)                             \
            wmma::load_matrix_sync(af[i], As_ + (wm*64 + i*16)*ALD + kk*16, ALD); \
        _Pragma("unroll") for (int j = 0; j < 4; j++)                             \
            wmma::load_matrix_sync(bf[j], Bs_ + (wn*64 + j*16)*ALD + kk*16, ALD); \
        _Pragma("unroll") for (int i = 0; i < 4; i++)                             \
            _Pragma("unroll") for (int j = 0; j < 4; j++)                         \
                wmma::mma_sync(acc[i][j], af[i], bf[j], acc[i][j]);               \
    }                                                                             \
} while (0)

// EPI 1: half out + bias + gelu   2: qkv half out (bias+rope+elu+mask)
template<int EPI>
__global__ void __launch_bounds__(256) hgemm2_k(
    const __half* __restrict__ A, const __half* __restrict__ Bt,
    const float* __restrict__ bias, void* __restrict__ Cv,
    int N, int K)
{
    extern __shared__ char sbuf[];
    int tid = threadIdx.x, wid = tid >> 5, lane = tid & 31;
    int wm = wid >> 2, wn = wid & 3;
    int m0 = blockIdx.y * 128, n0 = blockIdx.x * 256;
    int KT = K >> 6;

    wmma::fragment<wmma::accumulator,16,16,16,float> acc[4][4];
#pragma unroll
    for (int i = 0; i < 4; i++)
#pragma unroll
        for (int j = 0; j < 4; j++) wmma::fill_fragment(acc[i][j], 0.f);

    for (int s = 0; s < 2; s++) { if (s < KT) HG2_ISSUE(s, s, A, Bt, K); CP_COMMIT(); }
    for (int c = 0; c < KT; c++) {
        CP_WAIT1();
        __syncthreads();
        if (c + 2 < KT) HG2_ISSUE(c + 2, (c + 2) % 3, A, Bt, K);
        CP_COMMIT();
        HG2_COMP(c % 3);
    }
    __syncthreads();

    if (EPI == 2) {
        float* st = (float*)sbuf + wid * (16 * 68);
        int nb = n0 + wn * 64;
        int wtype = nb >> 9;          // 0=q 1=k 2=v
#pragma unroll
        for (int i = 0; i < 4; i++) {
#pragma unroll
            for (int j = 0; j < 4; j++)
                wmma::store_matrix_sync(st + j * 16, acc[i][j], 68, wmma::mem_row_major);
            __syncwarp();
#pragma unroll
            for (int e = 0; e < 32; e++) {
                int idx = e * 32 + lane;
                int r = idx >> 6, c = idx & 63;
                int m = m0 + wm*64 + i*16 + r;
                int n = nb + c;
                float val = st[r*68 + c] + bias[n];
                float outv;
                if (wtype < 2) {
                    int s = m % SS, b = m / SS;
                    if (b > BB - 1) b = BB - 1;
                    int jj = c & 31;
                    float cs = g_cs[(s*32 + jj)*2];
                    float sn = g_cs[(s*32 + jj)*2 + 1];
                    float partner = st[r*68 + (c ^ 32)] + bias[nb + (c ^ 32)];
                    float sgn = (c < 32) ? -1.f : 1.f;
                    float rot = val * cs + sgn * partner * sn;
                    float f = rot > 0.f ? rot + 1.f : expf(rot);
                    if (wtype == 1) f *= ((float)s < g_len[b]) ? 1.f : 0.f;
                    outv = f;
                } else {
                    outv = val;
                }
                g_qkvh[(size_t)m * NQKV + n] = __float2half_rn(outv);
            }
            __syncwarp();
        }
        return;
    }

    float* stg = (float*)sbuf + wid * 16 * 20;
#pragma unroll
    for (int i = 0; i < 4; i++)
#pragma unroll
        for (int j = 0; j < 4; j++) {
            wmma::store_matrix_sync(stg, acc[i][j], 20, wmma::mem_row_major);
            __syncwarp();
#pragma unroll
            for (int e = 0; e < 8; e++) {
                int idx = lane * 8 + e;
                int r = idx >> 4, cc = idx & 15;
                int m = m0 + wm*64 + i*16 + r;
                int n = n0 + wn*64 + j*16 + cc;
                float val = stg[r*20 + cc] + bias[n];
                val = 0.5f * val * (1.0f + erff(val * 0.70710678118654752f));
                ((__half*)Cv)[(size_t)m * N + n] = __float2half_rn(val);
            }
            __syncwarp();
        }
}

// ======= GEMM + residual + LayerNorm fused: tile 64x512, 512 thr, BK=32 =======
// out = LN(g_x + A@Bt^T + bias) -> writes g_x (fp32) and g_xh (fp16)
#define LALD  40
#define LASTG (64*LALD)
#define LBSTG (512*LALD)
#define LSTGH (LASTG+LBSTG)
#define LSTGB (LSTGH*2)                 /* 46080 bytes */
#define LSMEM (3*LSTGB)                 /* 138240 bytes */
#define ELD   520

#define LG_ISSUE(CH, ST, APTR, BPTR, KDIM) do {                                   \
    __half* As_ = (__half*)(sbuf + (ST)*LSTGB);                                   \
    __half* Bs_ = As_ + LASTG;                                                    \
    int k0_ = (CH) << 5;                                                          \
    if (tid < 256) { int row_ = tid >> 2, c_ = (tid & 3) * 8;                     \
        cpa16(As_ + row_*LALD + c_, (APTR) + (size_t)(m0 + row_)*(KDIM) + k0_ + c_); } \
    _Pragma("unroll") for (int t_ = 0; t_ < 4; t_++) {                            \
        int idx_ = tid + t_*512; int row_ = idx_ >> 2, c_ = (idx_ & 3) * 8;       \
        cpa16(Bs_ + row_*LALD + c_, (BPTR) + (size_t)row_*(KDIM) + k0_ + c_); }   \
} while (0)

#define LG_COMP(ST) do {                                                          \
    const __half* As_ = (const __half*)(sbuf + (ST)*LSTGB);                       \
    const __half* Bs_ = As_ + LASTG;                                              \
    _Pragma("unroll") for (int kk = 0; kk < 2; kk++) {                            \
        wmma::fragment<wmma::matrix_a,16,16,16,__half,wmma::row_major> af[2];     \
        wmma::fragment<wmma::matrix_b,16,16,16,__half,wmma::col_major> bf[4];     \
        _Pragma("unroll") for (int i = 0; i < 2; i++)                             \
            wmma::load_matrix_sync(af[i], As_ + (wm*32 + i*16)*LALD + kk*16, LALD); \
        _Pragma("unroll") for (int j = 0; j < 4; j++)                             \
            wmma::load_matrix_sync(bf[j], Bs_ + (wn*64 + j*16)*LALD + kk*16, LALD); \
        _Pragma("unroll") for (int i = 0; i < 2; i++)                             \
            _Pragma("unroll") for (int j = 0; j < 4; j++)                         \
                wmma::mma_sync(acc[i][j], af[i], bf[j], acc[i][j]);               \
    }                                                                             \
} while (0)

__global__ void __launch_bounds__(512) gemm_ln_k(
    const __half* __restrict__ A, const __half* __restrict__ Bt,
    const float* __restrict__ bias, const float* __restrict__ ln_s,
    const float* __restrict__ ln_b, int K)
{
    extern __shared__ char sbuf[];
    __shared__ float rmean[64], rinv[64];
    int tid = threadIdx.x, wid = tid >> 5;
    int wm = wid >> 3, wn = wid & 7;    // 2 x 8
    int m0 = blockIdx.x * 64;
    int KT = K >> 5;

    wmma::fragment<wmma::accumulator,16,16,16,float> acc[2][4];
#pragma unroll
    for (int i = 0; i < 2; i++)
#pragma unroll
        for (int j = 0; j < 4; j++) wmma::fill_fragment(acc[i][j], 0.f);

    for (int s = 0; s < 2; s++) { if (s < KT) LG_ISSUE(s, s, A, Bt, K); CP_COMMIT(); }
    for (int c = 0; c < KT; c++) {
        CP_WAIT1();
        __syncthreads();
        if (c + 2 < KT) LG_ISSUE(c + 2, (c + 2) % 3, A, Bt, K);
        CP_COMMIT();
        LG_COMP(c % 3);
    }
    __syncthreads();

    // stage accumulators into epilogue buffer (64 x ELD fp32, reuses pipe SMEM)
    float* ebuf = (float*)sbuf;
#pragma unroll
    for (int i = 0; i < 2; i++)
#pragma unroll
        for (int j = 0; j < 4; j++)
            wmma::store_matrix_sync(ebuf + (wm*32 + i*16)*ELD + wn*64 + j*16,
                                    acc[i][j], ELD, wmma::mem_row_major);
    __syncthreads();

    // phase 1: add bias + residual, accumulate row sums (8 threads per row)
    {
        int r = tid >> 3, sub = tid & 7;
        size_t mrow = (size_t)(m0 + r) * DD;
        float s = 0.f, ss = 0.f;
        for (int c = sub; c < DD; c += 8) {
            float v = ebuf[r*ELD + c] + bias[c] + g_x[mrow + c];
            ebuf[r*ELD + c] = v;
            s += v; ss += v * v;
        }
        s  += __shfl_down_sync(0xffffffffu, s, 4, 8);
        ss += __shfl_down_sync(0xffffffffu, ss, 4, 8);
        s  += __shfl_down_sync(0xffffffffu, s, 2, 8);
        ss += __shfl_down_sync(0xffffffffu, ss, 2, 8);
        s  += __shfl_down_sync(0xffffffffu, s, 1, 8);
        ss += __shfl_down_sync(0xffffffffu, ss, 1, 8);
        if (sub == 0) {
            float mean = s / (float)DD;
            float var = ss / (float)DD - mean * mean;
            rmean[r] = mean;
            rinv[r]  = rsqrtf(var + 1e-5f);
        }
    }
    __syncthreads();

    // phase 2: normalize + scale/shift, coalesced dual write
#pragma unroll 4
    for (int it = 0; it < 64; it++) {
        int idx = it * 512 + tid;
        int rr = idx >> 9, c = idx & 511;
        float v = ebuf[rr*ELD + c];
        float o = (v - rmean[rr]) * rinv[rr] * ln_s[c] + ln_b[c];
        size_t oo = (size_t)(m0 + rr) * DD + c;
        g_x[oo]  = o;
        g_xh[oo] = __float2half_rn(o);
    }
}

// ---------------- conv-embedding GEMM (gathered A rows) ----------------
__global__ void __launch_bounds__(256) conv_hgemm2_k(
    const int* __restrict__ tok, const float* __restrict__ conv_b,
    const float* __restrict__ pos)
{
    extern __shared__ char sbuf[];
    __shared__ int toks[16][128];
    int tid = threadIdx.x, wid = tid >> 5, lane = tid & 31;
    int wm = wid >> 2, wn = wid & 3;
    int m0 = blockIdx.y * 128, n0 = blockIdx.x * 256;
    const int KT = KCONV >> 6;   // 128

    if (tid < 128) {
        int r = m0 + tid;
        int b = r >> 8, nn = r & 255;
        int base = b * LL + nn * PP;
#pragma unroll
        for (int p = 0; p < 16; p++) toks[p][tid] = tok[base + p];
    }
    __syncthreads();

    wmma::fragment<wmma::accumulator,16,16,16,float> acc[4][4];
#pragma unroll
    for (int i = 0; i < 4; i++)
#pragma unroll
        for (int j = 0; j < 4; j++) wmma::fill_fragment(acc[i][j], 0.f);

#define CV2_ISSUE(CH, ST) do {                                                    \
    __half* As_ = (__half*)(sbuf + (ST)*STGB);                                    \
    __half* Bs_ = As_ + ASTG;                                                     \
    int k0_ = (CH) << 6; int p_ = k0_ >> 9, i0_ = k0_ & 511;                      \
    _Pragma("unroll") for (int t_ = 0; t_ < 4; t_++) {                            \
        int idx_ = tid + t_*256; int row_ = idx_ >> 3, c_ = (idx_ & 7) * 8;       \
        int tk_ = toks[p_][row_];                                                 \
        cpa16(As_ + row_*ALD + c_, g_embt + (size_t)tk_*DD + i0_ + c_); }         \
    _Pragma("unroll") for (int t_ = 0; t_ < 8; t_++) {                            \
        int idx_ = tid + t_*256; int row_ = idx_ >> 3, c_ = (idx_ & 7) * 8;       \
        cpa16(Bs_ + row_*ALD + c_, g_Wc + (size_t)(n0 + row_)*KCONV + k0_ + c_); } \
} while (0)

    for (int s = 0; s < 2; s++) { CV2_ISSUE(s, s); CP_COMMIT(); }
    for (int c = 0; c < KT; c++) {
        CP_WAIT1();
        __syncthreads();
        if (c + 2 < KT) CV2_ISSUE(c + 2, (c + 2) % 3);
        CP_COMMIT();
        HG2_COMP(c % 3);
    }
    __syncthreads();

    float* stg = (float*)sbuf + wid * 16 * 20;
#pragma unroll
    for (int i = 0; i < 4; i++)
#pragma unroll
        for (int j = 0; j < 4; j++) {
            wmma::store_matrix_sync(stg, acc[i][j], 20, wmma::mem_row_major);
            __syncwarp();
#pragma unroll
            for (int e = 0; e < 8; e++) {
                int idx = lane * 8 + e;
                int r = idx >> 4, cc = idx & 15;
                int mrow = m0 + wm*64 + i*16 + r;
                int b = mrow >> 8, nn = mrow & 255;
                int s = nn + 1;
                int n = n0 + wn*64 + j*16 + cc;
                float val = stg[r*20 + cc] + conv_b[n] + pos[(size_t)s*DD + n];
                size_t o = ((size_t)(b*SS + s))*DD + n;
                g_x[o]  = val;
                g_xh[o] = __float2half_rn(val);
            }
            __syncwarp();
        }
}

// ---------------- prologue pack kernels ----------------
__global__ void half4_k(const float4* __restrict__ src, __half* __restrict__ dst, int n4) {
    int i = blockIdx.x * 256 + threadIdx.x;
    if (i >= n4) return;
    float4 v = src[i];
    __half2 a = __floats2half2_rn(v.x, v.y);
    __half2 b = __floats2half2_rn(v.z, v.w);
    __half2* d = (__half2*)(dst + (size_t)i * 4);
    d[0] = a; d[1] = b;
}

__global__ void pack_t2_k(const float* __restrict__ src, __half* __restrict__ dst,
                          int K, int N) {
    __shared__ float tile[32][33];
    int n0 = blockIdx.x * 32, k0 = blockIdx.y * 32;
    size_t per = (size_t)K * N;
    const float* s = src + (size_t)blockIdx.z * per;
    __half* d = dst + (size_t)blockIdx.z * per;
    int tx = threadIdx.x, ty = threadIdx.y;
#pragma unroll
    for (int r = 0; r < 4; r++) {
        int k = k0 + ty + r * 8;
        tile[ty + r * 8][tx] = s[(size_t)k * N + n0 + tx];
    }
    __syncthreads();
#pragma unroll
    for (int r = 0; r < 4; r++) {
        int n = n0 + ty + r * 8;
        d[(size_t)n * K + k0 + tx] = __float2half_rn(tile[tx][ty + r * 8]);
    }
}

__global__ void pack_qkv2_k(const float* __restrict__ Wq, const float* __restrict__ Wk,
                            const float* __restrict__ Wv) {
    __shared__ float tile[32][33];
    int n0 = blockIdx.x * 32, k0 = blockIdx.y * 32;
    int l = blockIdx.z;
    int w = n0 >> 9, nn0 = n0 & 511;
    const float* W = ((w == 0) ? Wq : (w == 1) ? Wk : Wv) + (size_t)l * DD * DD;
    __half* d = g_Wqkv + (size_t)l * NQKV * DD;
    int tx = threadIdx.x, ty = threadIdx.y;
#pragma unroll
    for (int r = 0; r < 4; r++) {
        int k = k0 + ty + r * 8;
        tile[ty + r * 8][tx] = W[(size_t)k * DD + nn0 + tx];
    }
    __syncthreads();
#pragma unroll
    for (int r = 0; r < 4; r++) {
        int n = n0 + ty + r * 8;
        d[(size_t)n * DD + k0 + tx] = __float2half_rn(tile[tx][ty + r * 8]);
    }
}

__global__ void pack_qkvb_k(const float* __restrict__ bq, const float* __restrict__ bk,
                            const float* __restrict__ bv) {
    int idx = blockIdx.x * 256 + threadIdx.x;
    if (idx >= NLAY * NQKV) return;
    int i = idx / NQKV, n = idx % NQKV;
    int w = n >> 9, nn = n & 511;
    const float* Bv = (w == 0) ? bq : (w == 1) ? bk : bv;
    g_bqkv[idx] = Bv[i * DD + nn];
}

__global__ void __launch_bounds__(256) pack_convw2_k(const float* __restrict__ cw) {
    __shared__ float row[KCONV];
    int o = blockIdx.x;
    int tid = threadIdx.x;
    for (int i = tid; i < KCONV; i += 256) row[i] = cw[(size_t)o * KCONV + i];
    __syncthreads();
    for (int k = tid; k < KCONV; k += 256) {
        int i = k & 511, p = k >> 9;
        g_Wc[(size_t)o * KCONV + k] = __float2half_rn(row[i * PP + p]);
    }
}

__global__ void rope_tab_k() {
    int idx = blockIdx.x * 256 + threadIdx.x;
    if (idx >= SS * 32) return;
    int s = idx >> 5, j = idx & 31;
    float ang = (float)s * exp2f(-(float)j * (13.287712379549449f / 32.f));
    g_cs[idx * 2]     = cosf(ang);
    g_cs[idx * 2 + 1] = sinf(ang);
}

// ---------------- small kernels ----------------
__global__ void lengths_k(const float* __restrict__ mask) {
    __shared__ float sh[256];
    int b = blockIdx.x;
    float s = 0.f;
    for (int i = threadIdx.x; i < LL; i += 256) s += mask[(size_t)b * LL + i];
    sh[threadIdx.x] = s;
    __syncthreads();
    for (int st = 128; st > 0; st >>= 1) {
        if (threadIdx.x < st) sh[threadIdx.x] += sh[threadIdx.x + st];
        __syncthreads();
    }
    if (threadIdx.x == 0) g_len[b] = ceilf((sh[0] + 1.0f) / (float)PP);
}

__global__ void init_cls_k(const float* __restrict__ cls, const float* __restrict__ pos) {
    int idx = blockIdx.x * blockDim.x + threadIdx.x;
    if (idx >= BB * DD) return;
    int b = idx >> 9, d = idx & 511;
    float v = cls[d] + pos[d];
    size_t o = (size_t)b * SS * DD + d;
    g_x[o] = v; g_xh[o] = __float2half_rn(v);
}

__global__ void zero_pad_k() {
    int i = blockIdx.x * blockDim.x + threadIdx.x;
    int n = (TPAD - TT) * DD;
    if (i < n) {
        g_x[(size_t)TT * DD + i] = 0.f;
        g_xh[(size_t)TT * DD + i] = __float2half_rn(0.f);
        g_attn[(size_t)TT * DD + i] = __float2half_rn(0.f);
    }
}

// kv partial: part p covers s in [p*SPART, min(SS, (p+1)*SPART))
__global__ void __launch_bounds__(256) kv3_k() {
    int bh = blockIdx.x, part = blockIdx.y;
    int b = bh >> 3, h = bh & 7;
    int sbeg = part * SPART;
    int send = min(SS, sbeg + SPART);
    __shared__ float kf_sh[8][64], v_sh[8][64];
    int tid = threadIdx.x;
    int m = tid & 63, dg = tid >> 6;
    float acc[16];
#pragma unroll
    for (int jj = 0; jj < 16; jj++) acc[jj] = 0.f;
    float ksum = 0.f;
    for (int s0 = sbeg; s0 < send; s0 += 8) {
        __syncthreads();
#pragma unroll
        for (int u = 0; u < 4; u++) {
            int idx = tid + u * 256;
            int which = idx >> 9;
            int rr = (idx >> 6) & 7;
            int cc = idx & 63;
            int s = s0 + rr;
            float val = (s < send)
                ? __half2float(g_qkvh[(size_t)(b*SS + s)*NQKV + (which ? 1024 : 512) + h*64 + cc])
                : 0.f;
            if (which) v_sh[rr][cc] = val; else kf_sh[rr][cc] = val;
        }
        __syncthreads();
#pragma unroll
        for (int r = 0; r < 8; r++) {
            float vr = v_sh[r][m];
#pragma unroll
            for (int jj = 0; jj < 16; jj++) acc[jj] += kf_sh[r][dg*16 + jj] * vr;
        }
        if (tid < 64) {
#pragma unroll
            for (int r = 0; r < 8; r++) ksum += kf_sh[r][tid];
        }
    }
#pragma unroll
    for (int jj = 0; jj < 16; jj++)
        g_kvp[part][((size_t)bh * DHD + dg*16 + jj) * DHD + m] = acc[jj];
    if (tid < 64) g_ksump[part][bh * DHD + tid] = ksum;
}

// attn chunk: block (bh, ch) handles tokens [ch*32, min(SS, ch*32+32))
__global__ void __launch_bounds__(256) attn3_k() {
    int bh = blockIdx.x, ch = blockIdx.y;
    int b = bh >> 3, h = bh & 7;
    int sbeg = ch * 32;
    int send = min(SS, sbeg + 32);
    __shared__ float kvs[DHD * DHD];
    __shared__ float ks[DHD];
    __shared__ float q4[4][64];
    __shared__ float red[4][64];
    __shared__ float part[4][4][64];
    __shared__ float zsh[4];
    int tid = threadIdx.x, wid = tid >> 5, lane = tid & 31;
    int m = tid & 63, dg = tid >> 6;
    for (int i = tid; i < DHD * DHD; i += 256) {
        size_t o = (size_t)bh * DHD * DHD + i;
        kvs[i] = g_kvp[0][o] + g_kvp[1][o] + g_kvp[2][o] + g_kvp[3][o];
    }
    if (tid < 64) {
        int o = bh * DHD + tid;
        ks[tid] = g_ksump[0][o] + g_ksump[1][o] + g_ksump[2][o] + g_ksump[3][o];
    }
    __syncthreads();
    for (int s0 = sbeg; s0 < send; s0 += 4) {
        int r = tid >> 6, c = tid & 63;
        int sr = s0 + r;
        q4[r][c] = (sr < send)
            ? __half2float(g_qkvh[(size_t)(b*SS + sr)*NQKV + h*64 + c]) : 0.f;
        __syncthreads();
        red[r][c] = q4[r][c] * ks[c];
        __syncthreads();
        if (wid < 4) {
            float v = red[wid][lane] + red[wid][lane + 32];
            for (int o = 16; o; o >>= 1) v += __shfl_down_sync(0xffffffffu, v, o);
            if (lane == 0) zsh[wid] = 1.f / (v + 1e-6f);
        }
        float a[4] = {0.f, 0.f, 0.f, 0.f};
#pragma unroll
        for (int jj = 0; jj < 16; jj++) {
            int d = dg*16 + jj;
            float kc = kvs[d * DHD + m];
#pragma unroll
            for (int rr = 0; rr < 4; rr++) a[rr] += q4[rr][d] * kc;
        }
#pragma unroll
        for (int rr = 0; rr < 4; rr++) part[dg][rr][m] = a[rr];
        __syncthreads();
        {
            int rr = tid >> 6, mm = tid & 63;
            int s = s0 + rr;
            if (s < send) {
                float o = (part[0][rr][mm] + part[1][rr][mm] +
                           part[2][rr][mm] + part[3][rr][mm]) * zsh[rr];
                g_attn[((size_t)(b*SS + s))*DD + h*64 + mm] = __float2half_rn(o);
            }
        }
        __syncthreads();
    }
}

// final LN on token 0 + classifier head
__global__ void __launch_bounds__(256) final_k(
    const float* __restrict__ lnf_s, const float* __restrict__ lnf_b,
    const float* __restrict__ ow, const float* __restrict__ ob,
    float* __restrict__ out)
{
    int b = blockIdx.x, tid = threadIdx.x;
    size_t base = (size_t)b * SS * DD;
    float v0 = g_x[base + tid];
    float v1 = g_x[base + tid + 256];
    float s = v0 + v1, ss = v0 * v0 + v1 * v1;
    __shared__ float rs[8], rss[8];
    __shared__ float row[DD];
    for (int o = 16; o; o >>= 1) {
        s  += __shfl_down_sync(0xffffffffu, s, o);
        ss += __shfl_down_sync(0xffffffffu, ss, o);
    }
    int w = tid >> 5;
    if ((tid & 31) == 0) { rs[w] = s; rss[w] = ss; }
    __syncthreads();
    if (tid == 0) {
        float S1 = 0.f, S2 = 0.f;
        for (int i = 0; i < 8; i++) { S1 += rs[i]; S2 += rss[i]; }
        rs[0] = S1 / (float)DD;
        rss[0] = S2 / (float)DD;
    }
    __syncthreads();
    float mean = rs[0];
    float inv = rsqrtf(rss[0] - mean * mean + 1e-5f);
    row[tid]       = (v0 - mean) * inv * lnf_s[tid] + lnf_b[tid];
    row[tid + 256] = (v1 - mean) * inv * lnf_s[tid + 256] + lnf_b[tid + 256];
    __syncthreads();
    for (int c = 0; c < NCLS; c++) {
        float p = row[tid] * ow[tid * NCLS + c] + row[tid + 256] * ow[(tid + 256) * NCLS + c];
        for (int o = 16; o; o >>= 1) p += __shfl_down_sync(0xffffffffu, p, o);
        if ((tid & 31) == 0) rs[tid >> 5] = p;
        __syncthreads();
        if (tid == 0) {
            float t2 = 0.f;
            for (int i = 0; i < 8; i++) t2 += rs[i];
            out[b * NCLS + c] = t2 + ob[c];
        }
        __syncthreads();
    }
}

// ---------------- host driver ----------------
extern "C" void kernel_launch(void* const* d_in, const int* in_sizes, int n_in,
                              void* d_out, int out_size)
{
    const int*   inputs     = (const int*)  d_in[0];
    const float* input_mask = (const float*)d_in[1];
    const float* emb        = (const float*)d_in[2];
    const float* conv_w     = (const float*)d_in[3];
    const float* conv_b     = (const float*)d_in[4];
    const float* pos        = (const float*)d_in[5];
    const float* cls        = (const float*)d_in[6];
    const float* Wq         = (const float*)d_in[7];
    const float* bq         = (const float*)d_in[8];
    const float* Wk         = (const float*)d_in[9];
    const float* bk         = (const float*)d_in[10];
    const float* Wv         = (const float*)d_in[11];
    const float* bv         = (const float*)d_in[12];
    const float* Wo         = (const float*)d_in[13];
    const float* bo         = (const float*)d_in[14];
    const float* ln1_s      = (const float*)d_in[15];
    const float* ln1_b      = (const float*)d_in[16];
    const float* ln2_s      = (const float*)d_in[17];
    const float* ln2_b      = (const float*)d_in[18];
    const float* W1         = (const float*)d_in[19];
    const float* b1         = (const float*)d_in[20];
    const float* W2         = (const float*)d_in[21];
    const float* b2         = (const float*)d_in[22];
    const float* lnf_s      = (const float*)d_in[23];
    const float* lnf_b      = (const float*)d_in[24];
    const float* out_w      = (const float*)d_in[25];
    const float* out_b      = (const float*)d_in[26];
    float* out = (float*)d_out;

    float  *pbqkv;
    __half *pxh, *pattn, *ph, *pWqkv, *pWot, *pW1t, *pW2t;
    cudaGetSymbolAddress((void**)&pxh,   g_xh);
    cudaGetSymbolAddress((void**)&pattn, g_attn);
    cudaGetSymbolAddress((void**)&ph,    g_h);
    cudaGetSymbolAddress((void**)&pWqkv, g_Wqkv);
    cudaGetSymbolAddress((void**)&pbqkv, g_bqkv);
    cudaGetSymbolAddress((void**)&pWot,  g_Wot);
    cudaGetSymbolAddress((void**)&pW1t,  g_W1t);
    cudaGetSymbolAddress((void**)&pW2t,  g_W2t);

    cudaFuncSetAttribute(hgemm2_k<1>,   cudaFuncAttributeMaxDynamicSharedMemorySize, SMEMH);
    cudaFuncSetAttribute(hgemm2_k<2>,   cudaFuncAttributeMaxDynamicSharedMemorySize, SMEMH);
    cudaFuncSetAttribute(conv_hgemm2_k, cudaFuncAttributeMaxDynamicSharedMemorySize, SMEMH);
    cudaFuncSetAttribute(gemm_ln_k,     cudaFuncAttributeMaxDynamicSharedMemorySize, LSMEM);

    // prologue
    pack_convw2_k<<<DD, 256>>>(conv_w);
    half4_k<<<(32000 * DD / 4 + 255) / 256, 256>>>((const float4*)emb,
        (__half*)[]{ __half* p; cudaGetSymbolAddress((void**)&p, g_embt); return p; }(),
        32000 * DD / 4);
    pack_qkv2_k<<<dim3(NQKV/32, DD/32, NLAY), dim3(32, 8)>>>(Wq, Wk, Wv);
    pack_qkvb_k<<<(NLAY * NQKV + 255) / 256, 256>>>(bq, bk, bv);
    pack_t2_k<<<dim3(DD/32, DD/32, NLAY),  dim3(32, 8)>>>(Wo, pWot, DD, DD);
    pack_t2_k<<<dim3(FFD/32, DD/32, NLAY), dim3(32, 8)>>>(W1, pW1t, DD, FFD);
    pack_t2_k<<<dim3(DD/32, FFD/32, NLAY), dim3(32, 8)>>>(W2, pW2t, FFD, DD);
    rope_tab_k<<<(SS * 32 + 255) / 256, 256>>>();
    lengths_k<<<BB, 256>>>(input_mask);
    zero_pad_k<<<((TPAD - TT) * DD + 255) / 256, 256>>>();
    init_cls_k<<<(BB * DD + 255) / 256, 256>>>(cls, pos);
    conv_hgemm2_k<<<dim3(DD / 256, MCONV / 128), 256, SMEMH>>>(inputs, conv_b, pos);

    dim3 gQKV(NQKV / 256, TPAD / 128);  // (6, 65)
    dim3 gF(FFD / 256, TPAD / 128);     // (8, 65)
    int gLN = TPAD / 64;                // 130

    for (int i = 0; i < NLAY; i++) {
        hgemm2_k<2><<<gQKV, 256, SMEMH>>>(pxh, pWqkv + (size_t)i*NQKV*DD,
                                          pbqkv + (size_t)i*NQKV, nullptr, NQKV, DD);
        kv3_k<<<dim3(BB * HH, KVPARTS), 256>>>();
        attn3_k<<<dim3(BB * HH, 9), 256>>>();
        gemm_ln_k<<<gLN, 512, LSMEM>>>(pattn, pWot + (size_t)i*DD*DD,
                                       bo + (size_t)i*DD,
                                       ln1_s + (size_t)i*DD, ln1_b + (size_t)i*DD, DD);
        hgemm2_k<1><<<gF, 256, SMEMH>>>(pxh, pW1t + (size_t)i*FFD*DD,
                                        b1 + (size_t)i*FFD, ph, FFD, DD);
        gemm_ln_k<<<gLN, 512, LSMEM>>>(ph, pW2t + (size_t)i*DD*FFD,
                                       b2 + (size_t)i*DD,
                                       ln2_s + (size_t)i*DD, ln2_b + (size_t)i*DD, FFD);
    }

    final_k<<<BB, 256>>>(lnf_s, lnf_b, out_w, out_b, out);
}

// round 14
// speedup vs baseline: 3.8131x; 1.0322x over previous
#include <cuda_runtime.h>
#include <cuda_fp16.h>
#include <mma.h>
#include <math.h>
#include <stdint.h>

using namespace nvcuda;

#define BB   32
#define LL   4096
#define PP   16
#define SS   257
#define DD   512
#define HH   8
#define DHD  64
#define NLAY 8
#define FFD  2048
#define NCLS 4
#define TT   (BB*SS)      /* 8224 */
#define TPAD 8320         /* 65*128 */
#define KCONV 8192
#define MCONV 8192
#define NQKV 1536
#define KVPARTS 4
#define SPART 72

// ---------------- scratch (device globals; no allocations) ----------------
__device__ float  g_x[TPAD*DD];
__device__ __half g_xh[TPAD*DD];
__device__ __half g_qkvh[(size_t)TPAD*NQKV];
__device__ __half g_attn[TPAD*DD];
__device__ __half g_h[(size_t)TPAD*FFD];
__device__ float  g_kvp[KVPARTS][BB*HH*DHD*DHD];
__device__ float  g_ksump[KVPARTS][BB*HH*DHD];
__device__ float  g_len[BB];
__device__ float  g_cs[SS*32*2];
// fp16 weights, native [K][N] layout (no transpose) except conv ([N][K])
__device__ __half g_Wc[(size_t)DD*KCONV];        // [o][k] col-major path
__device__ __half g_embt[(size_t)32000*DD];
__device__ __half g_Wqkv[(size_t)NLAY*DD*NQKV];  // [l][k][n]
__device__ float  g_bqkv[NLAY*NQKV];
__device__ __half g_Woh[(size_t)NLAY*DD*DD];
__device__ __half g_W1h[(size_t)NLAY*DD*FFD];
__device__ __half g_W2h[(size_t)NLAY*FFD*DD];

// ---------------- helpers ----------------
__device__ __forceinline__ void cpa16(const __half* dst_smem, const __half* src) {
    uint32_t d = (uint32_t)__cvta_generic_to_shared(dst_smem);
    asm volatile("cp.async.cg.shared.global [%0], [%1], 16;" :: "r"(d), "l"(src) : "memory");
}
#define CP_COMMIT() asm volatile("cp.async.commit_group;" ::: "memory")
#define CP_WAIT1()  asm volatile("cp.async.wait_group 1;" ::: "memory")

// ====== dense fp16 wmma GEMM, tile 128x256, BK=64, 3-stage, B row-major ======
#define ALD   72                        /* A row stride (halves) */
#define BLD   264                       /* B row stride (halves) */
#define DASTG (128*ALD)
#define DBSTG (64*BLD)
#define DSTGB ((DASTG+DBSTG)*2)         /* 52224 bytes per stage */
#define DSMEM (3*DSTGB)                 /* 156672 bytes */

#define HG2_ISSUE(CH, ST, APTR, BPTR, KDIM, NDIM) do {                            \
    __half* As_ = (__half*)(sbuf + (ST)*DSTGB);                                   \
    __half* Bs_ = As_ + DASTG;                                                    \
    int k0_ = (CH) << 6;                                                          \
    _Pragma("unroll") for (int t_ = 0; t_ < 4; t_++) {                            \
        int idx_ = tid + t_*256; int row_ = idx_ >> 3, c_ = (idx_ & 7) * 8;       \
        cpa16(As_ + row_*ALD + c_, (APTR) + (size_t)(m0 + row_)*(KDIM) + k0_ + c_); } \
    _Pragma("unroll") for (int t_ = 0; t_ < 8; t_++) {                            \
        int idx_ = tid + t_*256; int row_ = idx_ >> 5, c_ = (idx_ & 31) * 8;      \
        cpa16(Bs_ + row_*BLD + c_, (BPTR) + (size_t)(k0_ + row_)*(NDIM) + n0 + c_); } \
} while (0)

#define HG2_COMP(ST) do {                                                         \
    const __half* As_ = (const __half*)(sbuf + (ST)*DSTGB);                       \
    const __half* Bs_ = As_ + DASTG;                                              \
    _Pragma("unroll") for (int kk = 0; kk < 4; kk++) {                            \
        wmma::fragment<wmma::matrix_a,16,16,16,__half,wmma::row_major> af[4];     \
        wmma::fragment<wmma::matrix_b,16,16,16,__half,wmma::row_major> bf[4];     \
        _Pragma("unroll") for (int i = 0; i < 4; i++)                             \
            wmma::load_matrix_sync(af[i], As_ + (wm*64 + i*16)*ALD + kk*16, ALD); \
        _Pragma("unroll") for (int j = 0; j < 4; j++)                             \
            wmma::load_matrix_sync(bf[j], Bs_ + (kk*16)*BLD + wn*64 + j*16, BLD); \
        _Pragma("unroll") for (int i = 0; i < 4; i++)                             \
            _Pragma("unroll") for (int j = 0; j < 4; j++)                         \
                wmma::mma_sync(acc[i][j], af[i], bf[j], acc[i][j]);               \
    }                                                                             \
} while (0)

// EPI 1: half out + bias + gelu   2: qkv half out (bias+rope+elu+mask)
template<int EPI>
__global__ void __launch_bounds__(256) hgemm2_k(
    const __half* __restrict__ A, const __half* __restrict__ Bm,
    const float* __restrict__ bias, void* __restrict__ Cv,
    int N, int K)
{
    extern __shared__ char sbuf[];
    int tid = threadIdx.x, wid = tid >> 5, lane = tid & 31;
    int wm = wid >> 2, wn = wid & 3;
    int m0 = blockIdx.y * 128, n0 = blockIdx.x * 256;
    int KT = K >> 6;

    wmma::fragment<wmma::accumulator,16,16,16,float> acc[4][4];
#pragma unroll
    for (int i = 0; i < 4; i++)
#pragma unroll
        for (int j = 0; j < 4; j++) wmma::fill_fragment(acc[i][j], 0.f);

    for (int s = 0; s < 2; s++) { if (s < KT) HG2_ISSUE(s, s, A, Bm, K, N); CP_COMMIT(); }
    for (int c = 0; c < KT; c++) {
        CP_WAIT1();
        __syncthreads();
        if (c + 2 < KT) HG2_ISSUE(c + 2, (c + 2) % 3, A, Bm, K, N);
        CP_COMMIT();
        HG2_COMP(c % 3);
    }
    __syncthreads();

    if (EPI == 2) {
        float* st = (float*)sbuf + wid * (16 * 68);
        int nb = n0 + wn * 64;
        int wtype = nb >> 9;          // 0=q 1=k 2=v
#pragma unroll
        for (int i = 0; i < 4; i++) {
#pragma unroll
            for (int j = 0; j < 4; j++)
                wmma::store_matrix_sync(st + j * 16, acc[i][j], 68, wmma::mem_row_major);
            __syncwarp();
#pragma unroll
            for (int e = 0; e < 32; e++) {
                int idx = e * 32 + lane;
                int r = idx >> 6, c = idx & 63;
                int m = m0 + wm*64 + i*16 + r;
                int n = nb + c;
                float val = st[r*68 + c] + bias[n];
                float outv;
                if (wtype < 2) {
                    int s = m % SS, b = m / SS;
                    if (b > BB - 1) b = BB - 1;
                    int jj = c & 31;
                    float cs = g_cs[(s*32 + jj)*2];
                    float sn = g_cs[(s*32 + jj)*2 + 1];
                    float partner = st[r*68 + (c ^ 32)] + bias[nb + (c ^ 32)];
                    float sgn = (c < 32) ? -1.f : 1.f;
                    float rot = val * cs + sgn * partner * sn;
                    float f = rot > 0.f ? rot + 1.f : expf(rot);
                    if (wtype == 1) f *= ((float)s < g_len[b]) ? 1.f : 0.f;
                    outv = f;
                } else {
                    outv = val;
                }
                g_qkvh[(size_t)m * NQKV + n] = __float2half_rn(outv);
            }
            __syncwarp();
        }
        return;
    }

    float* stg = (float*)sbuf + wid * 16 * 20;
#pragma unroll
    for (int i = 0; i < 4; i++)
#pragma unroll
        for (int j = 0; j < 4; j++) {
            wmma::store_matrix_sync(stg, acc[i][j], 20, wmma::mem_row_major);
            __syncwarp();
#pragma unroll
            for (int e = 0; e < 8; e++) {
                int idx = lane * 8 + e;
                int r = idx >> 4, cc = idx & 15;
                int m = m0 + wm*64 + i*16 + r;
                int n = n0 + wn*64 + j*16 + cc;
                float val = stg[r*20 + cc] + bias[n];
                val = 0.5f * val * (1.0f + erff(val * 0.70710678118654752f));
                ((__half*)Cv)[(size_t)m * N + n] = __float2half_rn(val);
            }
            __syncwarp();
        }
}

// ======= GEMM + residual + LayerNorm fused: tile 64x512, 512 thr, BK=32 =======
// out = LN(g_x + A@B + bias) -> g_x (fp32) and g_xh (fp16).  B row-major [K][512].
#define LALD  40
#define LBLD  520
#define LASTG (64*LALD)
#define LBSTG (32*LBLD)
#define LSTGB ((LASTG+LBSTG)*2)         /* 38400 bytes */
#define LSMEM 138240                    /* >= max(3*LSTGB, 64*ELD*4) */
#define ELD   520

#define LG_ISSUE(CH, ST, APTR, BPTR, KDIM) do {                                   \
    __half* As_ = (__half*)(sbuf + (ST)*LSTGB);                                   \
    __half* Bs_ = As_ + LASTG;                                                    \
    int k0_ = (CH) << 5;                                                          \
    if (tid < 256) { int row_ = tid >> 2, c_ = (tid & 3) * 8;                     \
        cpa16(As_ + row_*LALD + c_, (APTR) + (size_t)(m0 + row_)*(KDIM) + k0_ + c_); } \
    _Pragma("unroll") for (int t_ = 0; t_ < 4; t_++) {                            \
        int idx_ = tid + t_*512; int row_ = idx_ >> 6, c_ = (idx_ & 63) * 8;      \
        cpa16(Bs_ + row_*LBLD + c_, (BPTR) + (size_t)(k0_ + row_)*DD + c_); }     \
} while (0)

#define LG_COMP(ST) do {                                                          \
    const __half* As_ = (const __half*)(sbuf + (ST)*LSTGB);                       \
    const __half* Bs_ = As_ + LASTG;                                              \
    _Pragma("unroll") for (int kk = 0; kk < 2; kk++) {                            \
        wmma::fragment<wmma::matrix_a,16,16,16,__half,wmma::row_major> af[2];     \
        wmma::fragment<wmma::matrix_b,16,16,16,__half,wmma::row_major> bf[4];     \
        _Pragma("unroll") for (int i = 0; i < 2; i++)                             \
            wmma::load_matrix_sync(af[i], As_ + (wm*32 + i*16)*LALD + kk*16, LALD); \
        _Pragma("unroll") for (int j = 0; j < 4; j++)                             \
            wmma::load_matrix_sync(bf[j], Bs_ + (kk*16)*LBLD + wn*64 + j*16, LBLD); \
        _Pragma("unroll") for (int i = 0; i < 2; i++)                             \
            _Pragma("unroll") for (int j = 0; j < 4; j++)                         \
                wmma::mma_sync(acc[i][j], af[i], bf[j], acc[i][j]);               \
    }                                                                             \
} while (0)

__global__ void __launch_bounds__(512) gemm_ln_k(
    const __half* __restrict__ A, const __half* __restrict__ Bm,
    const float* __restrict__ bias, const float* __restrict__ ln_s,
    const float* __restrict__ ln_b, int K)
{
    extern __shared__ char sbuf[];
    __shared__ float rmean[64], rinv[64];
    int tid = threadIdx.x, wid = tid >> 5;
    int wm = wid >> 3, wn = wid & 7;    // 2 x 8
    int m0 = blockIdx.x * 64;
    int KT = K >> 5;

    wmma::fragment<wmma::accumulator,16,16,16,float> acc[2][4];
#pragma unroll
    for (int i = 0; i < 2; i++)
#pragma unroll
        for (int j = 0; j < 4; j++) wmma::fill_fragment(acc[i][j], 0.f);

    for (int s = 0; s < 2; s++) { if (s < KT) LG_ISSUE(s, s, A, Bm, K); CP_COMMIT(); }
    for (int c = 0; c < KT; c++) {
        CP_WAIT1();
        __syncthreads();
        if (c + 2 < KT) LG_ISSUE(c + 2, (c + 2) % 3, A, Bm, K);
        CP_COMMIT();
        LG_COMP(c % 3);
    }
    __syncthreads();

    float* ebuf = (float*)sbuf;
#pragma unroll
    for (int i = 0; i < 2; i++)
#pragma unroll
        for (int j = 0; j < 4; j++)
            wmma::store_matrix_sync(ebuf + (wm*32 + i*16)*ELD + wn*64 + j*16,
                                    acc[i][j], ELD, wmma::mem_row_major);
    __syncthreads();

    {
        int r = tid >> 3, sub = tid & 7;
        size_t mrow = (size_t)(m0 + r) * DD;
        float s = 0.f, ss = 0.f;
        for (int c = sub; c < DD; c += 8) {
            float v = ebuf[r*ELD + c] + bias[c] + g_x[mrow + c];
            ebuf[r*ELD + c] = v;
            s += v; ss += v * v;
        }
        s  += __shfl_down_sync(0xffffffffu, s, 4, 8);
        ss += __shfl_down_sync(0xffffffffu, ss, 4, 8);
        s  += __shfl_down_sync(0xffffffffu, s, 2, 8);
        ss += __shfl_down_sync(0xffffffffu, ss, 2, 8);
        s  += __shfl_down_sync(0xffffffffu, s, 1, 8);
        ss += __shfl_down_sync(0xffffffffu, ss, 1, 8);
        if (sub == 0) {
            float mean = s / (float)DD;
            float var = ss / (float)DD - mean * mean;
            rmean[r] = mean;
            rinv[r]  = rsqrtf(var + 1e-5f);
        }
    }
    __syncthreads();

#pragma unroll 4
    for (int it = 0; it < 64; it++) {
        int idx = it * 512 + tid;
        int rr = idx >> 9, c = idx & 511;
        float v = ebuf[rr*ELD + c];
        float o = (v - rmean[rr]) * rinv[rr] * ln_s[c] + ln_b[c];
        size_t oo = (size_t)(m0 + rr) * DD + c;
        g_x[oo]  = o;
        g_xh[oo] = __float2half_rn(o);
    }
}

// ------ conv-embedding GEMM (gathered A, B col-major [N][K] as before) ------
#define CASTG (128*ALD)
#define CBSTG (256*ALD)
#define CSTGB ((CASTG+CBSTG)*2)         /* 55296 */
#define CSMEM (3*CSTGB)                 /* 165888 */

__global__ void __launch_bounds__(256) conv_hgemm2_k(
    const int* __restrict__ tok, const float* __restrict__ conv_b,
    const float* __restrict__ pos)
{
    extern __shared__ char sbuf[];
    __shared__ int toks[16][128];
    int tid = threadIdx.x, wid = tid >> 5, lane = tid & 31;
    int wm = wid >> 2, wn = wid & 3;
    int m0 = blockIdx.y * 128, n0 = blockIdx.x * 256;
    const int KT = KCONV >> 6;   // 128

    if (tid < 128) {
        int r = m0 + tid;
        int b = r >> 8, nn = r & 255;
        int base = b * LL + nn * PP;
#pragma unroll
        for (int p = 0; p < 16; p++) toks[p][tid] = tok[base + p];
    }
    __syncthreads();

    wmma::fragment<wmma::accumulator,16,16,16,float> acc[4][4];
#pragma unroll
    for (int i = 0; i < 4; i++)
#pragma unroll
        for (int j = 0; j < 4; j++) wmma::fill_fragment(acc[i][j], 0.f);

#define CV2_ISSUE(CH, ST) do {                                                    \
    __half* As_ = (__half*)(sbuf + (ST)*CSTGB);                                   \
    __half* Bs_ = As_ + CASTG;                                                    \
    int k0_ = (CH) << 6; int p_ = k0_ >> 9, i0_ = k0_ & 511;                      \
    _Pragma("unroll") for (int t_ = 0; t_ < 4; t_++) {                            \
        int idx_ = tid + t_*256; int row_ = idx_ >> 3, c_ = (idx_ & 7) * 8;       \
        int tk_ = toks[p_][row_];                                                 \
        cpa16(As_ + row_*ALD + c_, g_embt + (size_t)tk_*DD + i0_ + c_); }         \
    _Pragma("unroll") for (int t_ = 0; t_ < 8; t_++) {                            \
        int idx_ = tid + t_*256; int row_ = idx_ >> 3, c_ = (idx_ & 7) * 8;       \
        cpa16(Bs_ + row_*ALD + c_, g_Wc + (size_t)(n0 + row_)*KCONV + k0_ + c_); } \
} while (0)

#define CVC_COMP(ST) do {                                                         \
    const __half* As_ = (const __half*)(sbuf + (ST)*CSTGB);                       \
    const __half* Bs_ = As_ + CASTG;                                              \
    _Pragma("unroll") for (int kk = 0; kk < 4; kk++) {                            \
        wmma::fragment<wmma::matrix_a,16,16,16,__half,wmma::row_major> af[4];     \
        wmma::fragment<wmma::matrix_b,16,16,16,__half,wmma::col_major> bf[4];     \
        _Pragma("unroll") for (int i = 0; i < 4; i++)                             \
            wmma::load_matrix_sync(af[i], As_ + (wm*64 + i*16)*ALD + kk*16, ALD); \
        _Pragma("unroll") for (int j = 0; j < 4; j++)                             \
            wmma::load_matrix_sync(bf[j], Bs_ + (wn*64 + j*16)*ALD + kk*16, ALD); \
        _Pragma("unroll") for (int i = 0; i < 4; i++)                             \
            _Pragma("unroll") for (int j = 0; j < 4; j++)                         \
                wmma::mma_sync(acc[i][j], af[i], bf[j], acc[i][j]);               \
    }                                                                             \
} while (0)

    for (int s = 0; s < 2; s++) { CV2_ISSUE(s, s); CP_COMMIT(); }
    for (int c = 0; c < KT; c++) {
        CP_WAIT1();
        __syncthreads();
        if (c + 2 < KT) CV2_ISSUE(c + 2, (c + 2) % 3);
        CP_COMMIT();
        CVC_COMP(c % 3);
    }
    __syncthreads();

    float* stg = (float*)sbuf + wid * 16 * 20;
#pragma unroll
    for (int i = 0; i < 4; i++)
#pragma unroll
        for (int j = 0; j < 4; j++) {
            wmma::store_matrix_sync(stg, acc[i][j], 20, wmma::mem_row_major);
            __syncwarp();
#pragma unroll
            for (int e = 0; e < 8; e++) {
                int idx = lane * 8 + e;
                int r = idx >> 4, cc = idx & 15;
                int mrow = m0 + wm*64 + i*16 + r;
                int b = mrow >> 8, nn = mrow & 255;
                int s = nn + 1;
                int n = n0 + wn*64 + j*16 + cc;
                float val = stg[r*20 + cc] + conv_b[n] + pos[(size_t)s*DD + n];
                size_t o = ((size_t)(b*SS + s))*DD + n;
                g_x[o]  = val;
                g_xh[o] = __float2half_rn(val);
            }
            __syncwarp();
        }
}

// ---------------- prologue pack kernels (pure converts now) ----------------
__global__ void half4_k(const float4* __restrict__ src, __half* __restrict__ dst, int n4) {
    int i = blockIdx.x * 256 + threadIdx.x;
    if (i >= n4) return;
    float4 v = src[i];
    __half2 a = __floats2half2_rn(v.x, v.y);
    __half2 b = __floats2half2_rn(v.z, v.w);
    __half2* d = (__half2*)(dst + (size_t)i * 4);
    d[0] = a; d[1] = b;
}

// g_Wqkv[l][k][w*512+n] = half(W_w[l][k][n])  (coalesced read & write)
__global__ void pack_qkvc_k(const float* __restrict__ Wq, const float* __restrict__ Wk,
                            const float* __restrict__ Wv) {
    size_t idx = (size_t)blockIdx.x * 256 + threadIdx.x;
    if (idx >= (size_t)NLAY * DD * NQKV) return;
    int l = (int)(idx / (DD * NQKV));
    int rem = (int)(idx % (DD * NQKV));
    int k = rem / NQKV, n = rem % NQKV;
    int w = n >> 9, nn = n & 511;
    const float* W = (w == 0) ? Wq : (w == 1) ? Wk : Wv;
    g_Wqkv[idx] = __float2half_rn(W[((size_t)l * DD + k) * DD + nn]);
}

__global__ void pack_qkvb_k(const float* __restrict__ bq, const float* __restrict__ bk,
                            const float* __restrict__ bv) {
    int idx = blockIdx.x * 256 + threadIdx.x;
    if (idx >= NLAY * NQKV) return;
    int i = idx / NQKV, n = idx % NQKV;
    int w = n >> 9, nn = n & 511;
    const float* Bv = (w == 0) ? bq : (w == 1) ? bk : bv;
    g_bqkv[idx] = Bv[i * DD + nn];
}

__global__ void __launch_bounds__(256) pack_convw2_k(const float* __restrict__ cw) {
    __shared__ float row[KCONV];
    int o = blockIdx.x;
    int tid = threadIdx.x;
    for (int i = tid; i < KCONV; i += 256) row[i] = cw[(size_t)o * KCONV + i];
    __syncthreads();
    for (int k = tid; k < KCONV; k += 256) {
        int i = k & 511, p = k >> 9;
        g_Wc[(size_t)o * KCONV + k] = __float2half_rn(row[i * PP + p]);
    }
}

__global__ void rope_tab_k() {
    int idx = blockIdx.x * 256 + threadIdx.x;
    if (idx >= SS * 32) return;
    int s = idx >> 5, j = idx & 31;
    float ang = (float)s * exp2f(-(float)j * (13.287712379549449f / 32.f));
    g_cs[idx * 2]     = cosf(ang);
    g_cs[idx * 2 + 1] = sinf(ang);
}

// ---------------- small kernels ----------------
__global__ void lengths_k(const float* __restrict__ mask) {
    __shared__ float sh[256];
    int b = blockIdx.x;
    float s = 0.f;
    for (int i = threadIdx.x; i < LL; i += 256) s += mask[(size_t)b * LL + i];
    sh[threadIdx.x] = s;
    __syncthreads();
    for (int st = 128; st > 0; st >>= 1) {
        if (threadIdx.x < st) sh[threadIdx.x] += sh[threadIdx.x + st];
        __syncthreads();
    }
    if (threadIdx.x == 0) g_len[b] = ceilf((sh[0] + 1.0f) / (float)PP);
}

__global__ void init_cls_k(const float* __restrict__ cls, const float* __restrict__ pos) {
    int idx = blockIdx.x * blockDim.x + threadIdx.x;
    if (idx >= BB * DD) return;
    int b = idx >> 9, d = idx & 511;
    float v = cls[d] + pos[d];
    size_t o = (size_t)b * SS * DD + d;
    g_x[o] = v; g_xh[o] = __float2half_rn(v);
}

__global__ void zero_pad_k() {
    int i = blockIdx.x * blockDim.x + threadIdx.x;
    int n = (TPAD - TT) * DD;
    if (i < n) {
        g_x[(size_t)TT * DD + i] = 0.f;
        g_xh[(size_t)TT * DD + i] = __float2half_rn(0.f);
        g_attn[(size_t)TT * DD + i] = __float2half_rn(0.f);
    }
}

// kv partial: part p covers s in [p*SPART, min(SS, (p+1)*SPART))
__global__ void __launch_bounds__(256) kv3_k() {
    int bh = blockIdx.x, part = blockIdx.y;
    int b = bh >> 3, h = bh & 7;
    int sbeg = part * SPART;
    int send = min(SS, sbeg + SPART);
    __shared__ float kf_sh[8][64], v_sh[8][64];
    int tid = threadIdx.x;
    int m = tid & 63, dg = tid >> 6;
    float acc[16];
#pragma unroll
    for (int jj = 0; jj < 16; jj++) acc[jj] = 0.f;
    float ksum = 0.f;
    for (int s0 = sbeg; s0 < send; s0 += 8) {
        __syncthreads();
#pragma unroll
        for (int u = 0; u < 4; u++) {
            int idx = tid + u * 256;
            int which = idx >> 9;
            int rr = (idx >> 6) & 7;
            int cc = idx & 63;
            int s = s0 + rr;
            float val = (s < send)
                ? __half2float(g_qkvh[(size_t)(b*SS + s)*NQKV + (which ? 1024 : 512) + h*64 + cc])
                : 0.f;
            if (which) v_sh[rr][cc] = val; else kf_sh[rr][cc] = val;
        }
        __syncthreads();
#pragma unroll
        for (int r = 0; r < 8; r++) {
            float vr = v_sh[r][m];
#pragma unroll
            for (int jj = 0; jj < 16; jj++) acc[jj] += kf_sh[r][dg*16 + jj] * vr;
        }
        if (tid < 64) {
#pragma unroll
            for (int r = 0; r < 8; r++) ksum += kf_sh[r][tid];
        }
    }
#pragma unroll
    for (int jj = 0; jj < 16; jj++)
        g_kvp[part][((size_t)bh * DHD + dg*16 + jj) * DHD + m] = acc[jj];
    if (tid < 64) g_ksump[part][bh * DHD + tid] = ksum;
}

// attn chunk: block (bh, ch) handles tokens [ch*32, min(SS, ch*32+32))
__global__ void __launch_bounds__(256) attn3_k() {
    int bh = blockIdx.x, ch = blockIdx.y;
    int b = bh >> 3, h = bh & 7;
    int sbeg = ch * 32;
    int send = min(SS, sbeg + 32);
    __shared__ float kvs[DHD * DHD];
    __shared__ float ks[DHD];
    __shared__ float q4[4][64];
    __shared__ float red[4][64];
    __shared__ float part[4][4][64];
    __shared__ float zsh[4];
    int tid = threadIdx.x, wid = tid >> 5, lane = tid & 31;
    int m = tid & 63, dg = tid >> 6;
    for (int i = tid; i < DHD * DHD; i += 256) {
        size_t o = (size_t)bh * DHD * DHD + i;
        kvs[i] = g_kvp[0][o] + g_kvp[1][o] + g_kvp[2][o] + g_kvp[3][o];
    }
    if (tid < 64) {
        int o = bh * DHD + tid;
        ks[tid] = g_ksump[0][o] + g_ksump[1][o] + g_ksump[2][o] + g_ksump[3][o];
    }
    __syncthreads();
    for (int s0 = sbeg; s0 < send; s0 += 4) {
        int r = tid >> 6, c = tid & 63;
        int sr = s0 + r;
        q4[r][c] = (sr < send)
            ? __half2float(g_qkvh[(size_t)(b*SS + sr)*NQKV + h*64 + c]) : 0.f;
        __syncthreads();
        red[r][c] = q4[r][c] * ks[c];
        __syncthreads();
        if (wid < 4) {
            float v = red[wid][lane] + red[wid][lane + 32];
            for (int o = 16; o; o >>= 1) v += __shfl_down_sync(0xffffffffu, v, o);
            if (lane == 0) zsh[wid] = 1.f / (v + 1e-6f);
        }
        float a[4] = {0.f, 0.f, 0.f, 0.f};
#pragma unroll
        for (int jj = 0; jj < 16; jj++) {
            int d = dg*16 + jj;
            float kc = kvs[d * DHD + m];
#pragma unroll
            for (int rr = 0; rr < 4; rr++) a[rr] += q4[rr][d] * kc;
        }
#pragma unroll
        for (int rr = 0; rr < 4; rr++) part[dg][rr][m] = a[rr];
        __syncthreads();
        {
            int rr = tid >> 6, mm = tid & 63;
            int s = s0 + rr;
            if (s < send) {
                float o = (part[0][rr][mm] + part[1][rr][mm] +
                           part[2][rr][mm] + part[3][rr][mm]) * zsh[rr];
                g_attn[((size_t)(b*SS + s))*DD + h*64 + mm] = __float2half_rn(o);
            }
        }
        __syncthreads();
    }
}

// final LN on token 0 + classifier head
__global__ void __launch_bounds__(256) final_k(
    const float* __restrict__ lnf_s, const float* __restrict__ lnf_b,
    const float* __restrict__ ow, const float* __restrict__ ob,
    float* __restrict__ out)
{
    int b = blockIdx.x, tid = threadIdx.x;
    size_t base = (size_t)b * SS * DD;
    float v0 = g_x[base + tid];
    float v1 = g_x[base + tid + 256];
    float s = v0 + v1, ss = v0 * v0 + v1 * v1;
    __shared__ float rs[8], rss[8];
    __shared__ float row[DD];
    for (int o = 16; o; o >>= 1) {
        s  += __shfl_down_sync(0xffffffffu, s, o);
        ss += __shfl_down_sync(0xffffffffu, ss, o);
    }
    int w = tid >> 5;
    if ((tid & 31) == 0) { rs[w] = s; rss[w] = ss; }
    __syncthreads();
    if (tid == 0) {
        float S1 = 0.f, S2 = 0.f;
        for (int i = 0; i < 8; i++) { S1 += rs[i]; S2 += rss[i]; }
        rs[0] = S1 / (float)DD;
        rss[0] = S2 / (float)DD;
    }
    __syncthreads();
    float mean = rs[0];
    float inv = rsqrtf(rss[0] - mean * mean + 1e-5f);
    row[tid]       = (v0 - mean) * inv * lnf_s[tid] + lnf_b[tid];
    row[tid + 256] = (v1 - mean) * inv * lnf_s[tid + 256] + lnf_b[tid + 256];
    __syncthreads();
    for (int c = 0; c < NCLS; c++) {
        float p = row[tid] * ow[tid * NCLS + c] + row[tid + 256] * ow[(tid + 256) * NCLS + c];
        for (int o = 16; o; o >>= 1) p += __shfl_down_sync(0xffffffffu, p, o);
        if ((tid & 31) == 0) rs[tid >> 5] = p;
        __syncthreads();
        if (tid == 0) {
            float t2 = 0.f;
            for (int i = 0; i < 8; i++) t2 += rs[i];
            out[b * NCLS + c] = t2 + ob[c];
        }
        __syncthreads();
    }
}

// ---------------- host driver ----------------
extern "C" void kernel_launch(void* const* d_in, const int* in_sizes, int n_in,
                              void* d_out, int out_size)
{
    const int*   inputs     = (const int*)  d_in[0];
    const float* input_mask = (const float*)d_in[1];
    const float* emb        = (const float*)d_in[2];
    const float* conv_w     = (const float*)d_in[3];
    const float* conv_b     = (const float*)d_in[4];
    const float* pos        = (const float*)d_in[5];
    const float* cls        = (const float*)d_in[6];
    const float* Wq         = (const float*)d_in[7];
    const float* bq         = (const float*)d_in[8];
    const float* Wk         = (const float*)d_in[9];
    const float* bk         = (const float*)d_in[10];
    const float* Wv         = (const float*)d_in[11];
    const float* bv         = (const float*)d_in[12];
    const float* Wo         = (const float*)d_in[13];
    const float* bo         = (const float*)d_in[14];
    const float* ln1_s      = (const float*)d_in[15];
    const float* ln1_b      = (const float*)d_in[16];
    const float* ln2_s      = (const float*)d_in[17];
    const float* ln2_b      = (const float*)d_in[18];
    const float* W1         = (const float*)d_in[19];
    const float* b1         = (const float*)d_in[20];
    const float* W2         = (const float*)d_in[21];
    const float* b2         = (const float*)d_in[22];
    const float* lnf_s      = (const float*)d_in[23];
    const float* lnf_b      = (const float*)d_in[24];
    const float* out_w      = (const float*)d_in[25];
    const float* out_b      = (const float*)d_in[26];
    float* out = (float*)d_out;

    float  *pbqkv;
    __half *pxh, *pattn, *ph, *pWqkv, *pWoh, *pW1h, *pW2h, *pembt;
    cudaGetSymbolAddress((void**)&pxh,   g_xh);
    cudaGetSymbolAddress((void**)&pattn, g_attn);
    cudaGetSymbolAddress((void**)&ph,    g_h);
    cudaGetSymbolAddress((void**)&pWqkv, g_Wqkv);
    cudaGetSymbolAddress((void**)&pbqkv, g_bqkv);
    cudaGetSymbolAddress((void**)&pWoh,  g_Woh);
    cudaGetSymbolAddress((void**)&pW1h,  g_W1h);
    cudaGetSymbolAddress((void**)&pW2h,  g_W2h);
    cudaGetSymbolAddress((void**)&pembt, g_embt);

    cudaFuncSetAttribute(hgemm2_k<1>,   cudaFuncAttributeMaxDynamicSharedMemorySize, DSMEM);
    cudaFuncSetAttribute(hgemm2_k<2>,   cudaFuncAttributeMaxDynamicSharedMemorySize, DSMEM);
    cudaFuncSetAttribute(conv_hgemm2_k, cudaFuncAttributeMaxDynamicSharedMemorySize, CSMEM);
    cudaFuncSetAttribute(gemm_ln_k,     cudaFuncAttributeMaxDynamicSharedMemorySize, LSMEM);

    // prologue — pure converts, no transposes
    pack_convw2_k<<<DD, 256>>>(conv_w);
    half4_k<<<(32000 * DD / 4 + 255) / 256, 256>>>((const float4*)emb, pembt, 32000 * DD / 4);
    pack_qkvc_k<<<(int)(((size_t)NLAY * DD * NQKV + 255) / 256), 256>>>(Wq, Wk, Wv);
    pack_qkvb_k<<<(NLAY * NQKV + 255) / 256, 256>>>(bq, bk, bv);
    half4_k<<<(NLAY * DD * DD / 4 + 255) / 256, 256>>>((const float4*)Wo, pWoh, NLAY * DD * DD / 4);
    half4_k<<<(NLAY * DD * FFD / 4 + 255) / 256, 256>>>((const float4*)W1, pW1h, NLAY * DD * FFD / 4);
    half4_k<<<(NLAY * FFD * DD / 4 + 255) / 256, 256>>>((const float4*)W2, pW2h, NLAY * FFD * DD / 4);
    rope_tab_k<<<(SS * 32 + 255) / 256, 256>>>();
    lengths_k<<<BB, 256>>>(input_mask);
    zero_pad_k<<<((TPAD - TT) * DD + 255) / 256, 256>>>();
    init_cls_k<<<(BB * DD + 255) / 256, 256>>>(cls, pos);
    conv_hgemm2_k<<<dim3(DD / 256, MCONV / 128), 256, CSMEM>>>(inputs, conv_b, pos);

    dim3 gQKV(NQKV / 256, TPAD / 128);  // (6, 65)
    dim3 gF(FFD / 256, TPAD / 128);     // (8, 65)
    int gLN = TPAD / 64;                // 130

    for (int i = 0; i < NLAY; i++) {
        hgemm2_k<2><<<gQKV, 256, DSMEM>>>(pxh, pWqkv + (size_t)i*DD*NQKV,
                                          pbqkv + (size_t)i*NQKV, nullptr, NQKV, DD);
        kv3_k<<<dim3(BB * HH, KVPARTS), 256>>>();
        attn3_k<<<dim3(BB * HH, 9), 256>>>();
        gemm_ln_k<<<gLN, 512, LSMEM>>>(pattn, pWoh + (size_t)i*DD*DD,
                                       bo + (size_t)i*DD,
                                       ln1_s + (size_t)i*DD, ln1_b + (size_t)i*DD, DD);
        hgemm2_k<1><<<gF, 256, DSMEM>>>(pxh, pW1h + (size_t)i*DD*FFD,
                                        b1 + (size_t)i*FFD, ph, FFD, DD);
        gemm_ln_k<<<gLN, 512, LSMEM>>>(ph, pW2h + (size_t)i*FFD*DD,
                                       b2 + (size_t)i*DD,
                                       ln2_s + (size_t)i*DD, ln2_b + (size_t)i*DD, FFD);
    }

    final_k<<<BB, 256>>>(lnf_s, lnf_b, out_w, out_b, out);
}

// round 15
// speedup vs baseline: 3.8389x; 1.0068x over previous
#include <cuda_runtime.h>
#include <cuda_fp16.h>
#include <mma.h>
#include <math.h>
#include <stdint.h>

using namespace nvcuda;

#define BB   32
#define LL   4096
#define PP   16
#define SS   257
#define DD   512
#define HH   8
#define DHD  64
#define NLAY 8
#define FFD  2048
#define NCLS 4
#define TT   (BB*SS)      /* 8224 */
#define TPAD 8320         /* 65*128 */
#define KCONV 8192
#define MCONV 8192
#define NQKV 1536
#define KVPARTS 4
#define SPART 72

// ---------------- scratch (device globals; no allocations) ----------------
__device__ float  g_x[TPAD*DD];
__device__ __half g_xh[TPAD*DD];
__device__ __half g_qkvh[(size_t)TPAD*NQKV];
__device__ __half g_attn[TPAD*DD];
__device__ __half g_h[(size_t)TPAD*FFD];
__device__ float  g_kvp[KVPARTS][BB*HH*DHD*DHD];
__device__ float  g_ksump[KVPARTS][BB*HH*DHD];
__device__ float  g_len[BB];
__device__ float  g_cs[SS*32*2];
// fp16 weights, native [K][N] layout (no transpose) except conv ([N][K])
__device__ __half g_Wc[(size_t)DD*KCONV];        // [o][k] col-major path
__device__ __half g_embt[(size_t)32000*DD];
__device__ __half g_Wqkv[(size_t)NLAY*DD*NQKV];  // [l][k][n]
__device__ float  g_bqkv[NLAY*NQKV];
__device__ __half g_Woh[(size_t)NLAY*DD*DD];
__device__ __half g_W1h[(size_t)NLAY*DD*FFD];
__device__ __half g_W2h[(size_t)NLAY*FFD*DD];

// ---------------- helpers ----------------
__device__ __forceinline__ void cpa16(const __half* dst_smem, const __half* src) {
    uint32_t d = (uint32_t)__cvta_generic_to_shared(dst_smem);
    asm volatile("cp.async.cg.shared.global [%0], [%1], 16;" :: "r"(d), "l"(src) : "memory");
}
#define CP_COMMIT() asm volatile("cp.async.commit_group;" ::: "memory")
#define CP_WAIT1()  asm volatile("cp.async.wait_group 1;" ::: "memory")

// ====== dense fp16 wmma GEMM, tile 128x256, BK=64, 3-stage, B row-major ======
#define ALD   72                        /* A row stride (halves) */
#define BLD   264                       /* B row stride (halves) */
#define DASTG (128*ALD)
#define DBSTG (64*BLD)
#define DSTGB ((DASTG+DBSTG)*2)         /* 52224 bytes per stage */
#define DSMEM (3*DSTGB)                 /* 156672 bytes */

#define HG2_ISSUE(CH, ST, APTR, BPTR, KDIM, NDIM) do {                            \
    __half* As_ = (__half*)(sbuf + (ST)*DSTGB);                                   \
    __half* Bs_ = As_ + DASTG;                                                    \
    int k0_ = (CH) << 6;                                                          \
    _Pragma("unroll") for (int t_ = 0; t_ < 4; t_++) {                            \
        int idx_ = tid + t_*256; int row_ = idx_ >> 3, c_ = (idx_ & 7) * 8;       \
        cpa16(As_ + row_*ALD + c_, (APTR) + (size_t)(m0 + row_)*(KDIM) + k0_ + c_); } \
    _Pragma("unroll") for (int t_ = 0; t_ < 8; t_++) {                            \
        int idx_ = tid + t_*256; int row_ = idx_ >> 5, c_ = (idx_ & 31) * 8;      \
        cpa16(Bs_ + row_*BLD + c_, (BPTR) + (size_t)(k0_ + row_)*(NDIM) + n0 + c_); } \
} while (0)

#define HG2_COMP(ST) do {                                                         \
    const __half* As_ = (const __half*)(sbuf + (ST)*DSTGB);                       \
    const __half* Bs_ = As_ + DASTG;                                              \
    _Pragma("unroll") for (int kk = 0; kk < 4; kk++) {                            \
        wmma::fragment<wmma::matrix_a,16,16,16,__half,wmma::row_major> af[4];     \
        wmma::fragment<wmma::matrix_b,16,16,16,__half,wmma::row_major> bf[4];     \
        _Pragma("unroll") for (int i = 0; i < 4; i++)                             \
            wmma::load_matrix_sync(af[i], As_ + (wm*64 + i*16)*ALD + kk*16, ALD); \
        _Pragma("unroll") for (int j = 0; j < 4; j++)                             \
            wmma::load_matrix_sync(bf[j], Bs_ + (kk*16)*BLD + wn*64 + j*16, BLD); \
        _Pragma("unroll") for (int i = 0; i < 4; i++)                             \
            _Pragma("unroll") for (int j = 0; j < 4; j++)                         \
                wmma::mma_sync(acc[i][j], af[i], bf[j], acc[i][j]);               \
    }                                                                             \
} while (0)

// EPI 1: half out + bias + gelu   2: qkv half out (bias+rope+elu+mask)
template<int EPI>
__global__ void __launch_bounds__(256) hgemm2_k(
    const __half* __restrict__ A, const __half* __restrict__ Bm,
    const float* __restrict__ bias, void* __restrict__ Cv,
    int N, int K)
{
    extern __shared__ char sbuf[];
    int tid = threadIdx.x, wid = tid >> 5, lane = tid & 31;
    int wm = wid >> 2, wn = wid & 3;
    int m0 = blockIdx.y * 128, n0 = blockIdx.x * 256;
    int KT = K >> 6;

    wmma::fragment<wmma::accumulator,16,16,16,float> acc[4][4];
#pragma unroll
    for (int i = 0; i < 4; i++)
#pragma unroll
        for (int j = 0; j < 4; j++) wmma::fill_fragment(acc[i][j], 0.f);

    for (int s = 0; s < 2; s++) { if (s < KT) HG2_ISSUE(s, s, A, Bm, K, N); CP_COMMIT(); }
    for (int c = 0; c < KT; c++) {
        CP_WAIT1();
        __syncthreads();
        if (c + 2 < KT) HG2_ISSUE(c + 2, (c + 2) % 3, A, Bm, K, N);
        CP_COMMIT();
        HG2_COMP(c % 3);
    }
    __syncthreads();

    if (EPI == 2) {
        float* st = (float*)sbuf + wid * (16 * 68);
        int nb = n0 + wn * 64;
        int wtype = nb >> 9;          // 0=q 1=k 2=v
#pragma unroll
        for (int i = 0; i < 4; i++) {
#pragma unroll
            for (int j = 0; j < 4; j++)
                wmma::store_matrix_sync(st + j * 16, acc[i][j], 68, wmma::mem_row_major);
            __syncwarp();
#pragma unroll
            for (int e = 0; e < 32; e++) {
                int idx = e * 32 + lane;
                int r = idx >> 6, c = idx & 63;
                int m = m0 + wm*64 + i*16 + r;
                int n = nb + c;
                float val = st[r*68 + c] + bias[n];
                float outv;
                if (wtype < 2) {
                    int s = m % SS, b = m / SS;
                    if (b > BB - 1) b = BB - 1;
                    int jj = c & 31;
                    float cs = g_cs[(s*32 + jj)*2];
                    float sn = g_cs[(s*32 + jj)*2 + 1];
                    float partner = st[r*68 + (c ^ 32)] + bias[nb + (c ^ 32)];
                    float sgn = (c < 32) ? -1.f : 1.f;
                    float rot = val * cs + sgn * partner * sn;
                    float f = rot > 0.f ? rot + 1.f : expf(rot);
                    if (wtype == 1) f *= ((float)s < g_len[b]) ? 1.f : 0.f;
                    outv = f;
                } else {
                    outv = val;
                }
                g_qkvh[(size_t)m * NQKV + n] = __float2half_rn(outv);
            }
            __syncwarp();
        }
        return;
    }

    float* stg = (float*)sbuf + wid * 16 * 20;
#pragma unroll
    for (int i = 0; i < 4; i++)
#pragma unroll
        for (int j = 0; j < 4; j++) {
            wmma::store_matrix_sync(stg, acc[i][j], 20, wmma::mem_row_major);
            __syncwarp();
#pragma unroll
            for (int e = 0; e < 8; e++) {
                int idx = lane * 8 + e;
                int r = idx >> 4, cc = idx & 15;
                int m = m0 + wm*64 + i*16 + r;
                int n = n0 + wn*64 + j*16 + cc;
                float val = stg[r*20 + cc] + bias[n];
                val = 0.5f * val * (1.0f + erff(val * 0.70710678118654752f));
                ((__half*)Cv)[(size_t)m * N + n] = __float2half_rn(val);
            }
            __syncwarp();
        }
}

// ======= GEMM + residual + LayerNorm fused: tile 64x512, 512 thr, BK=32 =======
#define LALD  40
#define LBLD  520
#define LASTG (64*LALD)
#define LBSTG (32*LBLD)
#define LSTGB ((LASTG+LBSTG)*2)         /* 38400 bytes */
#define LSMEM 138240
#define ELD   520

#define LG_ISSUE(CH, ST, APTR, BPTR, KDIM) do {                                   \
    __half* As_ = (__half*)(sbuf + (ST)*LSTGB);                                   \
    __half* Bs_ = As_ + LASTG;                                                    \
    int k0_ = (CH) << 5;                                                          \
    if (tid < 256) { int row_ = tid >> 2, c_ = (tid & 3) * 8;                     \
        cpa16(As_ + row_*LALD + c_, (APTR) + (size_t)(m0 + row_)*(KDIM) + k0_ + c_); } \
    _Pragma("unroll") for (int t_ = 0; t_ < 4; t_++) {                            \
        int idx_ = tid + t_*512; int row_ = idx_ >> 6, c_ = (idx_ & 63) * 8;      \
        cpa16(Bs_ + row_*LBLD + c_, (BPTR) + (size_t)(k0_ + row_)*DD + c_); }     \
} while (0)

#define LG_COMP(ST) do {                                                          \
    const __half* As_ = (const __half*)(sbuf + (ST)*LSTGB);                       \
    const __half* Bs_ = As_ + LASTG;                                              \
    _Pragma("unroll") for (int kk = 0; kk < 2; kk++) {                            \
        wmma::fragment<wmma::matrix_a,16,16,16,__half,wmma::row_major> af[2];     \
        wmma::fragment<wmma::matrix_b,16,16,16,__half,wmma::row_major> bf[4];     \
        _Pragma("unroll") for (int i = 0; i < 2; i++)                             \
            wmma::load_matrix_sync(af[i], As_ + (wm*32 + i*16)*LALD + kk*16, LALD); \
        _Pragma("unroll") for (int j = 0; j < 4; j++)                             \
            wmma::load_matrix_sync(bf[j], Bs_ + (kk*16)*LBLD + wn*64 + j*16, LBLD); \
        _Pragma("unroll") for (int i = 0; i < 2; i++)                             \
            _Pragma("unroll") for (int j = 0; j < 4; j++)                         \
                wmma::mma_sync(acc[i][j], af[i], bf[j], acc[i][j]);               \
    }                                                                             \
} while (0)

__global__ void __launch_bounds__(512) gemm_ln_k(
    const __half* __restrict__ A, const __half* __restrict__ Bm,
    const float* __restrict__ bias, const float* __restrict__ ln_s,
    const float* __restrict__ ln_b, int K)
{
    extern __shared__ char sbuf[];
    __shared__ float rmean[64], rinv[64];
    int tid = threadIdx.x, wid = tid >> 5;
    int wm = wid >> 3, wn = wid & 7;    // 2 x 8
    int m0 = blockIdx.x * 64;
    int KT = K >> 5;

    wmma::fragment<wmma::accumulator,16,16,16,float> acc[2][4];
#pragma unroll
    for (int i = 0; i < 2; i++)
#pragma unroll
        for (int j = 0; j < 4; j++) wmma::fill_fragment(acc[i][j], 0.f);

    for (int s = 0; s < 2; s++) { if (s < KT) LG_ISSUE(s, s, A, Bm, K); CP_COMMIT(); }
    for (int c = 0; c < KT; c++) {
        CP_WAIT1();
        __syncthreads();
        if (c + 2 < KT) LG_ISSUE(c + 2, (c + 2) % 3, A, Bm, K);
        CP_COMMIT();
        LG_COMP(c % 3);
    }
    __syncthreads();

    float* ebuf = (float*)sbuf;
#pragma unroll
    for (int i = 0; i < 2; i++)
#pragma unroll
        for (int j = 0; j < 4; j++)
            wmma::store_matrix_sync(ebuf + (wm*32 + i*16)*ELD + wn*64 + j*16,
                                    acc[i][j], ELD, wmma::mem_row_major);
    __syncthreads();

    {
        int r = tid >> 3, sub = tid & 7;
        size_t mrow = (size_t)(m0 + r) * DD;
        float s = 0.f, ss = 0.f;
        for (int c = sub; c < DD; c += 8) {
            float v = ebuf[r*ELD + c] + bias[c] + g_x[mrow + c];
            ebuf[r*ELD + c] = v;
            s += v; ss += v * v;
        }
        s  += __shfl_down_sync(0xffffffffu, s, 4, 8);
        ss += __shfl_down_sync(0xffffffffu, ss, 4, 8);
        s  += __shfl_down_sync(0xffffffffu, s, 2, 8);
        ss += __shfl_down_sync(0xffffffffu, ss, 2, 8);
        s  += __shfl_down_sync(0xffffffffu, s, 1, 8);
        ss += __shfl_down_sync(0xffffffffu, ss, 1, 8);
        if (sub == 0) {
            float mean = s / (float)DD;
            float var = ss / (float)DD - mean * mean;
            rmean[r] = mean;
            rinv[r]  = rsqrtf(var + 1e-5f);
        }
    }
    __syncthreads();

#pragma unroll 4
    for (int it = 0; it < 64; it++) {
        int idx = it * 512 + tid;
        int rr = idx >> 9, c = idx & 511;
        float v = ebuf[rr*ELD + c];
        float o = (v - rmean[rr]) * rinv[rr] * ln_s[c] + ln_b[c];
        size_t oo = (size_t)(m0 + rr) * DD + c;
        g_x[oo]  = o;
        g_xh[oo] = __float2half_rn(o);
    }
}

// ------ conv-embedding GEMM (gathered A, B col-major [N][K]) ------
#define CASTG (128*ALD)
#define CBSTG (256*ALD)
#define CSTGB ((CASTG+CBSTG)*2)         /* 55296 */
#define CSMEM (3*CSTGB)                 /* 165888 */

__global__ void __launch_bounds__(256) conv_hgemm2_k(
    const int* __restrict__ tok, const float* __restrict__ conv_b,
    const float* __restrict__ pos)
{
    extern __shared__ char sbuf[];
    __shared__ int toks[16][128];
    int tid = threadIdx.x, wid = tid >> 5, lane = tid & 31;
    int wm = wid >> 2, wn = wid & 3;
    int m0 = blockIdx.y * 128, n0 = blockIdx.x * 256;
    const int KT = KCONV >> 6;   // 128

    if (tid < 128) {
        int r = m0 + tid;
        int b = r >> 8, nn = r & 255;
        int base = b * LL + nn * PP;
#pragma unroll
        for (int p = 0; p < 16; p++) toks[p][tid] = tok[base + p];
    }
    __syncthreads();

    wmma::fragment<wmma::accumulator,16,16,16,float> acc[4][4];
#pragma unroll
    for (int i = 0; i < 4; i++)
#pragma unroll
        for (int j = 0; j < 4; j++) wmma::fill_fragment(acc[i][j], 0.f);

#define CV2_ISSUE(CH, ST) do {                                                    \
    __half* As_ = (__half*)(sbuf + (ST)*CSTGB);                                   \
    __half* Bs_ = As_ + CASTG;                                                    \
    int k0_ = (CH) << 6; int p_ = k0_ >> 9, i0_ = k0_ & 511;                      \
    _Pragma("unroll") for (int t_ = 0; t_ < 4; t_++) {                            \
        int idx_ = tid + t_*256; int row_ = idx_ >> 3, c_ = (idx_ & 7) * 8;       \
        int tk_ = toks[p_][row_];                                                 \
        cpa16(As_ + row_*ALD + c_, g_embt + (size_t)tk_*DD + i0_ + c_); }         \
    _Pragma("unroll") for (int t_ = 0; t_ < 8; t_++) {                            \
        int idx_ = tid + t_*256; int row_ = idx_ >> 3, c_ = (idx_ & 7) * 8;       \
        cpa16(Bs_ + row_*ALD + c_, g_Wc + (size_t)(n0 + row_)*KCONV + k0_ + c_); } \
} while (0)

#define CVC_COMP(ST) do {                                                         \
    const __half* As_ = (const __half*)(sbuf + (ST)*CSTGB);                       \
    const __half* Bs_ = As_ + CASTG;                                              \
    _Pragma("unroll") for (int kk = 0; kk < 4; kk++) {                            \
        wmma::fragment<wmma::matrix_a,16,16,16,__half,wmma::row_major> af[4];     \
        wmma::fragment<wmma::matrix_b,16,16,16,__half,wmma::col_major> bf[4];     \
        _Pragma("unroll") for (int i = 0; i < 4; i++)                             \
            wmma::load_matrix_sync(af[i], As_ + (wm*64 + i*16)*ALD + kk*16, ALD); \
        _Pragma("unroll") for (int j = 0; j < 4; j++)                             \
            wmma::load_matrix_sync(bf[j], Bs_ + (wn*64 + j*16)*ALD + kk*16, ALD); \
        _Pragma("unroll") for (int i = 0; i < 4; i++)                             \
            _Pragma("unroll") for (int j = 0; j < 4; j++)                         \
                wmma::mma_sync(acc[i][j], af[i], bf[j], acc[i][j]);               \
    }                                                                             \
} while (0)

    for (int s = 0; s < 2; s++) { CV2_ISSUE(s, s); CP_COMMIT(); }
    for (int c = 0; c < KT; c++) {
        CP_WAIT1();
        __syncthreads();
        if (c + 2 < KT) CV2_ISSUE(c + 2, (c + 2) % 3);
        CP_COMMIT();
        CVC_COMP(c % 3);
    }
    __syncthreads();

    float* stg = (float*)sbuf + wid * 16 * 20;
#pragma unroll
    for (int i = 0; i < 4; i++)
#pragma unroll
        for (int j = 0; j < 4; j++) {
            wmma::store_matrix_sync(stg, acc[i][j], 20, wmma::mem_row_major);
            __syncwarp();
#pragma unroll
            for (int e = 0; e < 8; e++) {
                int idx = lane * 8 + e;
                int r = idx >> 4, cc = idx & 15;
                int mrow = m0 + wm*64 + i*16 + r;
                int b = mrow >> 8, nn = mrow & 255;
                int s = nn + 1;
                int n = n0 + wn*64 + j*16 + cc;
                float val = stg[r*20 + cc] + conv_b[n] + pos[(size_t)s*DD + n];
                size_t o = ((size_t)(b*SS + s))*DD + n;
                g_x[o]  = val;
                g_xh[o] = __float2half_rn(val);
            }
            __syncwarp();
        }
}

// ---------------- prologue pack kernels ----------------
__global__ void half4_k(const float4* __restrict__ src, __half* __restrict__ dst, int n4) {
    int i = blockIdx.x * 256 + threadIdx.x;
    if (i >= n4) return;
    float4 v = src[i];
    __half2 a = __floats2half2_rn(v.x, v.y);
    __half2 b = __floats2half2_rn(v.z, v.w);
    __half2* d = (__half2*)(dst + (size_t)i * 4);
    d[0] = a; d[1] = b;
}

__global__ void pack_qkvc_k(const float* __restrict__ Wq, const float* __restrict__ Wk,
                            const float* __restrict__ Wv) {
    size_t idx = (size_t)blockIdx.x * 256 + threadIdx.x;
    if (idx >= (size_t)NLAY * DD * NQKV) return;
    int l = (int)(idx / (DD * NQKV));
    int rem = (int)(idx % (DD * NQKV));
    int k = rem / NQKV, n = rem % NQKV;
    int w = n >> 9, nn = n & 511;
    const float* W = (w == 0) ? Wq : (w == 1) ? Wk : Wv;
    g_Wqkv[idx] = __float2half_rn(W[((size_t)l * DD + k) * DD + nn]);
}

__global__ void pack_qkvb_k(const float* __restrict__ bq, const float* __restrict__ bk,
                            const float* __restrict__ bv) {
    int idx = blockIdx.x * 256 + threadIdx.x;
    if (idx >= NLAY * NQKV) return;
    int i = idx / NQKV, n = idx % NQKV;
    int w = n >> 9, nn = n & 511;
    const float* Bv = (w == 0) ? bq : (w == 1) ? bk : bv;
    g_bqkv[idx] = Bv[i * DD + nn];
}

__global__ void __launch_bounds__(256) pack_convw2_k(const float* __restrict__ cw) {
    __shared__ float row[KCONV];
    int o = blockIdx.x;
    int tid = threadIdx.x;
    for (int i = tid; i < KCONV; i += 256) row[i] = cw[(size_t)o * KCONV + i];
    __syncthreads();
    for (int k = tid; k < KCONV; k += 256) {
        int i = k & 511, p = k >> 9;
        g_Wc[(size_t)o * KCONV + k] = __float2half_rn(row[i * PP + p]);
    }
}

__global__ void rope_tab_k() {
    int idx = blockIdx.x * 256 + threadIdx.x;
    if (idx >= SS * 32) return;
    int s = idx >> 5, j = idx & 31;
    float ang = (float)s * exp2f(-(float)j * (13.287712379549449f / 32.f));
    g_cs[idx * 2]     = cosf(ang);
    g_cs[idx * 2 + 1] = sinf(ang);
}

// ---------------- small kernels ----------------
__global__ void lengths_k(const float* __restrict__ mask) {
    __shared__ float sh[256];
    int b = blockIdx.x;
    float s = 0.f;
    for (int i = threadIdx.x; i < LL; i += 256) s += mask[(size_t)b * LL + i];
    sh[threadIdx.x] = s;
    __syncthreads();
    for (int st = 128; st > 0; st >>= 1) {
        if (threadIdx.x < st) sh[threadIdx.x] += sh[threadIdx.x + st];
        __syncthreads();
    }
    if (threadIdx.x == 0) g_len[b] = ceilf((sh[0] + 1.0f) / (float)PP);
}

__global__ void init_cls_k(const float* __restrict__ cls, const float* __restrict__ pos) {
    int idx = blockIdx.x * blockDim.x + threadIdx.x;
    if (idx >= BB * DD) return;
    int b = idx >> 9, d = idx & 511;
    float v = cls[d] + pos[d];
    size_t o = (size_t)b * SS * DD + d;
    g_x[o] = v; g_xh[o] = __float2half_rn(v);
}

__global__ void zero_pad_k() {
    int i = blockIdx.x * blockDim.x + threadIdx.x;
    int n = (TPAD - TT) * DD;
    if (i < n) {
        g_x[(size_t)TT * DD + i] = 0.f;
        g_xh[(size_t)TT * DD + i] = __float2half_rn(0.f);
        g_attn[(size_t)TT * DD + i] = __float2half_rn(0.f);
    }
}

// kv partial: part p covers s in [p*SPART, min(SS, (p+1)*SPART))
__global__ void __launch_bounds__(256) kv3_k() {
    int bh = blockIdx.x, part = blockIdx.y;
    int b = bh >> 3, h = bh & 7;
    int sbeg = part * SPART;
    int send = min(SS, sbeg + SPART);
    __shared__ float kf_sh[8][64], v_sh[8][64];
    int tid = threadIdx.x;
    int m = tid & 63, dg = tid >> 6;
    float acc[16];
#pragma unroll
    for (int jj = 0; jj < 16; jj++) acc[jj] = 0.f;
    float ksum = 0.f;
    for (int s0 = sbeg; s0 < send; s0 += 8) {
        __syncthreads();
#pragma unroll
        for (int u = 0; u < 4; u++) {
            int idx = tid + u * 256;
            int which = idx >> 9;
            int rr = (idx >> 6) & 7;
            int cc = idx & 63;
            int s = s0 + rr;
            float val = (s < send)
                ? __half2float(g_qkvh[(size_t)(b*SS + s)*NQKV + (which ? 1024 : 512) + h*64 + cc])
                : 0.f;
            if (which) v_sh[rr][cc] = val; else kf_sh[rr][cc] = val;
        }
        __syncthreads();
#pragma unroll
        for (int r = 0; r < 8; r++) {
            float vr = v_sh[r][m];
#pragma unroll
            for (int jj = 0; jj < 16; jj++) acc[jj] += kf_sh[r][dg*16 + jj] * vr;
        }
        if (tid < 64) {
#pragma unroll
            for (int r = 0; r < 8; r++) ksum += kf_sh[r][tid];
        }
    }
#pragma unroll
    for (int jj = 0; jj < 16; jj++)
        g_kvp[part][((size_t)bh * DHD + dg*16 + jj) * DHD + m] = acc[jj];
    if (tid < 64) g_ksump[part][bh * DHD + tid] = ksum;
}

// attn chunk: block (bh, ch) handles tokens [ch*32, min(SS, ch*32+32))
__global__ void __launch_bounds__(256) attn3_k() {
    int bh = blockIdx.x, ch = blockIdx.y;
    int b = bh >> 3, h = bh & 7;
    int sbeg = ch * 32;
    int send = min(SS, sbeg + 32);
    __shared__ float kvs[DHD * DHD];
    __shared__ float ks[DHD];
    __shared__ float q4[4][64];
    __shared__ float red[4][64];
    __shared__ float part[4][4][64];
    __shared__ float zsh[4];
    int tid = threadIdx.x, wid = tid >> 5, lane = tid & 31;
    int m = tid & 63, dg = tid >> 6;
    for (int i = tid; i < DHD * DHD; i += 256) {
        size_t o = (size_t)bh * DHD * DHD + i;
        kvs[i] = g_kvp[0][o] + g_kvp[1][o] + g_kvp[2][o] + g_kvp[3][o];
    }
    if (tid < 64) {
        int o = bh * DHD + tid;
        ks[tid] = g_ksump[0][o] + g_ksump[1][o] + g_ksump[2][o] + g_ksump[3][o];
    }
    __syncthreads();
    for (int s0 = sbeg; s0 < send; s0 += 4) {
        int r = tid >> 6, c = tid & 63;
        int sr = s0 + r;
        q4[r][c] = (sr < send)
            ? __half2float(g_qkvh[(size_t)(b*SS + sr)*NQKV + h*64 + c]) : 0.f;
        __syncthreads();
        red[r][c] = q4[r][c] * ks[c];
        __syncthreads();
        if (wid < 4) {
            float v = red[wid][lane] + red[wid][lane + 32];
            for (int o = 16; o; o >>= 1) v += __shfl_down_sync(0xffffffffu, v, o);
            if (lane == 0) zsh[wid] = 1.f / (v + 1e-6f);
        }
        float a[4] = {0.f, 0.f, 0.f, 0.f};
#pragma unroll
        for (int jj = 0; jj < 16; jj++) {
            int d = dg*16 + jj;
            float kc = kvs[d * DHD + m];
#pragma unroll
            for (int rr = 0; rr < 4; rr++) a[rr] += q4[rr][d] * kc;
        }
#pragma unroll
        for (int rr = 0; rr < 4; rr++) part[dg][rr][m] = a[rr];
        __syncthreads();
        {
            int rr = tid >> 6, mm = tid & 63;
            int s = s0 + rr;
            if (s < send) {
                float o = (part[0][rr][mm] + part[1][rr][mm] +
                           part[2][rr][mm] + part[3][rr][mm]) * zsh[rr];
                g_attn[((size_t)(b*SS + s))*DD + h*64 + mm] = __float2half_rn(o);
            }
        }
        __syncthreads();
    }
}

// final LN on token 0 + classifier head
__global__ void __launch_bounds__(256) final_k(
    const float* __restrict__ lnf_s, const float* __restrict__ lnf_b,
    const float* __restrict__ ow, const float* __restrict__ ob,
    float* __restrict__ out)
{
    int b = blockIdx.x, tid = threadIdx.x;
    size_t base = (size_t)b * SS * DD;
    float v0 = g_x[base + tid];
    float v1 = g_x[base + tid + 256];
    float s = v0 + v1, ss = v0 * v0 + v1 * v1;
    __shared__ float rs[8], rss[8];
    __shared__ float row[DD];
    for (int o = 16; o; o >>= 1) {
        s  += __shfl_down_sync(0xffffffffu, s, o);
        ss += __shfl_down_sync(0xffffffffu, ss, o);
    }
    int w = tid >> 5;
    if ((tid & 31) == 0) { rs[w] = s; rss[w] = ss; }
    __syncthreads();
    if (tid == 0) {
        float S1 = 0.f, S2 = 0.f;
        for (int i = 0; i < 8; i++) { S1 += rs[i]; S2 += rss[i]; }
        rs[0] = S1 / (float)DD;
        rss[0] = S2 / (float)DD;
    }
    __syncthreads();
    float mean = rs[0];
    float inv = rsqrtf(rss[0] - mean * mean + 1e-5f);
    row[tid]       = (v0 - mean) * inv * lnf_s[tid] + lnf_b[tid];
    row[tid + 256] = (v1 - mean) * inv * lnf_s[tid + 256] + lnf_b[tid + 256];
    __syncthreads();
    for (int c = 0; c < NCLS; c++) {
        float p = row[tid] * ow[tid * NCLS + c] + row[tid + 256] * ow[(tid + 256) * NCLS + c];
        for (int o = 16; o; o >>= 1) p += __shfl_down_sync(0xffffffffu, p, o);
        if ((tid & 31) == 0) rs[tid >> 5] = p;
        __syncthreads();
        if (tid == 0) {
            float t2 = 0.f;
            for (int i = 0; i < 8; i++) t2 += rs[i];
            out[b * NCLS + c] = t2 + ob[c];
        }
        __syncthreads();
    }
}

// ---------------- host driver ----------------
extern "C" void kernel_launch(void* const* d_in, const int* in_sizes, int n_in,
                              void* d_out, int out_size)
{
    const int*   inputs     = (const int*)  d_in[0];
    const float* input_mask = (const float*)d_in[1];
    const float* emb        = (const float*)d_in[2];
    const float* conv_w     = (const float*)d_in[3];
    const float* conv_b     = (const float*)d_in[4];
    const float* pos        = (const float*)d_in[5];
    const float* cls        = (const float*)d_in[6];
    const float* Wq         = (const float*)d_in[7];
    const float* bq         = (const float*)d_in[8];
    const float* Wk         = (const float*)d_in[9];
    const float* bk         = (const float*)d_in[10];
    const float* Wv         = (const float*)d_in[11];
    const float* bv         = (const float*)d_in[12];
    const float* Wo         = (const float*)d_in[13];
    const float* bo         = (const float*)d_in[14];
    const float* ln1_s      = (const float*)d_in[15];
    const float* ln1_b      = (const float*)d_in[16];
    const float* ln2_s      = (const float*)d_in[17];
    const float* ln2_b      = (const float*)d_in[18];
    const float* W1         = (const float*)d_in[19];
    const float* b1         = (const float*)d_in[20];
    const float* W2         = (const float*)d_in[21];
    const float* b2         = (const float*)d_in[22];
    const float* lnf_s      = (const float*)d_in[23];
    const float* lnf_b      = (const float*)d_in[24];
    const float* out_w      = (const float*)d_in[25];
    const float* out_b      = (const float*)d_in[26];
    float* out = (float*)d_out;

    float  *pbqkv;
    __half *pxh, *pattn, *ph, *pWqkv, *pWoh, *pW1h, *pW2h, *pembt;
    cudaGetSymbolAddress((void**)&pxh,   g_xh);
    cudaGetSymbolAddress((void**)&pattn, g_attn);
    cudaGetSymbolAddress((void**)&ph,    g_h);
    cudaGetSymbolAddress((void**)&pWqkv, g_Wqkv);
    cudaGetSymbolAddress((void**)&pbqkv, g_bqkv);
    cudaGetSymbolAddress((void**)&pWoh,  g_Woh);
    cudaGetSymbolAddress((void**)&pW1h,  g_W1h);
    cudaGetSymbolAddress((void**)&pW2h,  g_W2h);
    cudaGetSymbolAddress((void**)&pembt, g_embt);

    cudaFuncSetAttribute(hgemm2_k<1>,   cudaFuncAttributeMaxDynamicSharedMemorySize, DSMEM);
    cudaFuncSetAttribute(hgemm2_k<2>,   cudaFuncAttributeMaxDynamicSharedMemorySize, DSMEM);
    cudaFuncSetAttribute(conv_hgemm2_k, cudaFuncAttributeMaxDynamicSharedMemorySize, CSMEM);
    cudaFuncSetAttribute(gemm_ln_k,     cudaFuncAttributeMaxDynamicSharedMemorySize, LSMEM);

    // fork a side stream for the layer-weight converts (graph-captured fork/join)
    cudaStream_t s2;
    cudaStreamCreateWithFlags(&s2, cudaStreamNonBlocking);
    cudaEvent_t evFork, evJoin;
    cudaEventCreateWithFlags(&evFork, cudaEventDisableTiming);
    cudaEventCreateWithFlags(&evJoin, cudaEventDisableTiming);

    cudaEventRecord(evFork, 0);
    cudaStreamWaitEvent(s2, evFork, 0);

    // main stream: conv path (pack conv W -> convert emb -> conv GEMM)
    pack_convw2_k<<<DD, 256>>>(conv_w);
    half4_k<<<(32000 * DD / 4 + 255) / 256, 256>>>((const float4*)emb, pembt, 32000 * DD / 4);
    init_cls_k<<<(BB * DD + 255) / 256, 256>>>(cls, pos);
    conv_hgemm2_k<<<dim3(DD / 256, MCONV / 128), 256, CSMEM>>>(inputs, conv_b, pos);

    // side stream: everything the layer loop needs but conv doesn't
    pack_qkvc_k<<<(int)(((size_t)NLAY * DD * NQKV + 255) / 256), 256, 0, s2>>>(Wq, Wk, Wv);
    pack_qkvb_k<<<(NLAY * NQKV + 255) / 256, 256, 0, s2>>>(bq, bk, bv);
    half4_k<<<(NLAY * DD * DD / 4 + 255) / 256, 256, 0, s2>>>((const float4*)Wo, pWoh, NLAY * DD * DD / 4);
    half4_k<<<(NLAY * DD * FFD / 4 + 255) / 256, 256, 0, s2>>>((const float4*)W1, pW1h, NLAY * DD * FFD / 4);
    half4_k<<<(NLAY * FFD * DD / 4 + 255) / 256, 256, 0, s2>>>((const float4*)W2, pW2h, NLAY * FFD * DD / 4);
    rope_tab_k<<<(SS * 32 + 255) / 256, 256, 0, s2>>>();
    lengths_k<<<BB, 256, 0, s2>>>(input_mask);
    zero_pad_k<<<((TPAD - TT) * DD + 255) / 256, 256, 0, s2>>>();

    cudaEventRecord(evJoin, s2);
    cudaStreamWaitEvent(0, evJoin, 0);

    dim3 gQKV(NQKV / 256, TPAD / 128);  // (6, 65)
    dim3 gF(FFD / 256, TPAD / 128);     // (8, 65)
    int gLN = TPAD / 64;                // 130

    for (int i = 0; i < NLAY; i++) {
        hgemm2_k<2><<<gQKV, 256, DSMEM>>>(pxh, pWqkv + (size_t)i*DD*NQKV,
                                          pbqkv + (size_t)i*NQKV, nullptr, NQKV, DD);
        kv3_k<<<dim3(BB * HH, KVPARTS), 256>>>();
        attn3_k<<<dim3(BB * HH, 9), 256>>>();
        gemm_ln_k<<<gLN, 512, LSMEM>>>(pattn, pWoh + (size_t)i*DD*DD,
                                       bo + (size_t)i*DD,
                                       ln1_s + (size_t)i*DD, ln1_b + (size_t)i*DD, DD);
        hgemm2_k<1><<<gF, 256, DSMEM>>>(pxh, pW1h + (size_t)i*DD*FFD,
                                        b1 + (size_t)i*FFD, ph, FFD, DD);
        gemm_ln_k<<<gLN, 512, LSMEM>>>(ph, pW2h + (size_t)i*FFD*DD,
                                       b2 + (size_t)i*DD,
                                       ln2_s + (size_t)i*DD, ln2_b + (size_t)i*DD, FFD);
    }

    final_k<<<BB, 256>>>(lnf_s, lnf_b, out_w, out_b, out);
}